// round 2
// baseline (speedup 1.0000x reference)
#include <cuda_runtime.h>

// ---------------- problem constants ----------------
namespace {
constexpr int Bn = 32;    // batch
constexpr int S  = 512;   // sequence
constexpr int H  = 768;   // hidden
constexpr int NN = 32;    // neighbors
constexpr int T  = 32;    // tokens per neighbor
constexpr int NE = 256;   // q/k embed
constexpr int AE = 128;   // attn embed
constexpr int RL = 8;     // region length (E1: 1..9, E2: 20..28)
constexpr float SCALE = 0.0625f;   // 1/sqrt(256)
constexpr float NEG   = 0.01f;     // leaky slope
}

// ---------------- scratch (device globals; no allocation) ----------------
__device__ float g_x    [Bn * S * H];          // updated x
__device__ float g_q    [Bn * S * NE];
__device__ float g_k    [Bn * S * NE];
__device__ float g_v    [Bn * S * H];
__device__ float g_probs[Bn * S * S];          // attention probs
__device__ float g_kn   [Bn * NN * T * NE];    // neighbor keys (reused per branch)
__device__ float g_msg1 [Bn * NN * RL * H];
__device__ float g_msg2 [Bn * NN * RL * H];
__device__ float g_qe1  [Bn * RL * NE];
__device__ float g_qe2  [Bn * RL * NE];
__device__ float g_att1 [Bn * NN];
__device__ float g_att2 [Bn * NN];
__device__ float g_u    [2 * H + 1];           // u1[0:H], u2[H:2H], cbase at [2H]

// ---------------- generic tiled SGEMM: C = alpha*(A @ opB) (+ bias) ----------------
// BM=BN=128, BK=8, 256 threads, 8x8 microtile. Requires M%128==0, N%128==0, K%8==0.
template<bool TRANSB, bool HASBIAS>
__global__ __launch_bounds__(256) void sgemm_k(
    const float* __restrict__ A, const float* __restrict__ Bm,
    const float* __restrict__ bias, float* __restrict__ C,
    int M, int N, int K, float alpha,
    long long sA, long long sB, long long sC)
{
    __shared__ float As[8][128];
    __shared__ float Bs[8][128];

    const int bz = blockIdx.z;
    A  += (long long)bz * sA;
    Bm += (long long)bz * sB;
    C  += (long long)bz * sC;

    const int m0 = blockIdx.y * 128;
    const int n0 = blockIdx.x * 128;
    const int tid = threadIdx.x;
    const int ty = tid >> 4, tx = tid & 15;

    float acc[8][8];
#pragma unroll
    for (int i = 0; i < 8; i++)
#pragma unroll
        for (int j = 0; j < 8; j++) acc[i][j] = 0.f;

    for (int k0 = 0; k0 < K; k0 += 8) {
        // A tile: 128 rows x 8 k, stored transposed As[k][m]
        {
            int row = tid >> 1, kq = (tid & 1) * 4;
            float4 av = *(const float4*)&A[(long long)(m0 + row) * K + k0 + kq];
            As[kq + 0][row] = av.x; As[kq + 1][row] = av.y;
            As[kq + 2][row] = av.z; As[kq + 3][row] = av.w;
        }
        if (!TRANSB) {
            int kk = tid >> 5, n4 = (tid & 31) * 4;
            float4 bv = *(const float4*)&Bm[(long long)(k0 + kk) * N + n0 + n4];
            *(float4*)&Bs[kk][n4] = bv;
        } else {
            int nn = tid >> 1, kq = (tid & 1) * 4;
            float4 bv = *(const float4*)&Bm[(long long)(n0 + nn) * K + k0 + kq];
            Bs[kq + 0][nn] = bv.x; Bs[kq + 1][nn] = bv.y;
            Bs[kq + 2][nn] = bv.z; Bs[kq + 3][nn] = bv.w;
        }
        __syncthreads();

#pragma unroll
        for (int kk = 0; kk < 8; kk++) {
            float a[8], b[8];
            *(float4*)&a[0] = *(const float4*)&As[kk][ty * 4];
            *(float4*)&a[4] = *(const float4*)&As[kk][64 + ty * 4];
            *(float4*)&b[0] = *(const float4*)&Bs[kk][tx * 4];
            *(float4*)&b[4] = *(const float4*)&Bs[kk][64 + tx * 4];
#pragma unroll
            for (int i = 0; i < 8; i++)
#pragma unroll
                for (int j = 0; j < 8; j++) acc[i][j] += a[i] * b[j];
        }
        __syncthreads();
    }

#pragma unroll
    for (int ri = 0; ri < 2; ri++)
#pragma unroll
        for (int i = 0; i < 4; i++) {
            int m = m0 + ri * 64 + ty * 4 + i;
#pragma unroll
            for (int cj = 0; cj < 2; cj++) {
                int n = n0 + cj * 64 + tx * 4;
                float4 cv;
                cv.x = acc[ri * 4 + i][cj * 4 + 0] * alpha;
                cv.y = acc[ri * 4 + i][cj * 4 + 1] * alpha;
                cv.z = acc[ri * 4 + i][cj * 4 + 2] * alpha;
                cv.w = acc[ri * 4 + i][cj * 4 + 3] * alpha;
                if (HASBIAS) {
                    cv.x += bias[n + 0]; cv.y += bias[n + 1];
                    cv.z += bias[n + 2]; cv.w += bias[n + 3];
                }
                *(float4*)&C[(long long)m * N + n] = cv;
            }
        }
}

// ---------------- u = Wa @ Wattn halves; cbase = ba.(w1+w2) + battn ----------------
__global__ void u_kernel(const float* __restrict__ Wa, const float* __restrict__ Wattn,
                         const float* __restrict__ ba, const float* __restrict__ battn)
{
    if (blockIdx.x < 6) {
        int g = blockIdx.x * 256 + threadIdx.x;   // [0, 1536)
        int j = g / H, h = g - j * H;
        float acc = 0.f;
#pragma unroll 8
        for (int a = 0; a < AE; a++) acc += Wa[h * AE + a] * Wattn[j * AE + a];
        g_u[g] = acc;
    } else {
        __shared__ float red[256];
        int tid = threadIdx.x;
        float v = 0.f;
        if (tid < AE) v = ba[tid] * (Wattn[tid] + Wattn[AE + tid]);
        red[tid] = v; __syncthreads();
        for (int s2 = 128; s2 > 0; s2 >>= 1) {
            if (tid < s2) red[tid] += red[tid + s2];
            __syncthreads();
        }
        if (tid == 0) g_u[2 * H] = red[0] + battn[0];
    }
}

// ---------------- q_e = e_fea @ Wq + bq  (256 blocks = B*RL, 256 threads = NE) ----
__global__ __launch_bounds__(256) void qe_kernel(
    const float* __restrict__ xs, const float* __restrict__ Wq,
    const float* __restrict__ bq, float* __restrict__ qe, int E0)
{
    __shared__ float xr[H];
    int b = blockIdx.x >> 3, l = blockIdx.x & 7;
    int tid = threadIdx.x;
    const float* row = xs + ((long long)b * S + E0 + l) * H;
    for (int i = tid; i < H; i += 256) xr[i] = row[i];
    __syncthreads();
    float acc = bq[tid];
#pragma unroll 8
    for (int h = 0; h < H; h++) acc += xr[h] * Wq[h * NE + tid];
    qe[(long long)(b * RL + l) * NE + tid] = acc;
}

// ---------------- per-(b,n): scores -> softmax over T -> message ----------------
__global__ __launch_bounds__(256) void neigh_kernel(
    const float* __restrict__ qe, const float* __restrict__ emb,
    float* __restrict__ msg)
{
    __shared__ float qs[RL * NE];
    __shared__ float ks[T * (NE + 1)];
    __shared__ float aw[RL * T];
    int b = blockIdx.x / NN, n = blockIdx.x % NN;
    int tid = threadIdx.x;

    const float* qb = qe + (long long)b * RL * NE;
    for (int i = tid; i < RL * NE; i += 256) qs[i] = qb[i];
    const float* kb = g_kn + (long long)(b * NN + n) * T * NE;
    for (int i = tid; i < T * NE; i += 256) {
        int r = i / NE, c = i - r * NE;
        ks[r * (NE + 1) + c] = kb[i];
    }
    __syncthreads();

    // one thread per (l, t) score; warp w handles row l=w
    int l = tid >> 5, tt = tid & 31;
    float s = 0.f;
    const float* qrow = qs + l * NE;
    const float* krow = ks + tt * (NE + 1);
#pragma unroll 8
    for (int e = 0; e < NE; e++) s += qrow[e] * krow[e];
    s *= SCALE;
    float m = s;
#pragma unroll
    for (int o = 16; o > 0; o >>= 1) m = fmaxf(m, __shfl_xor_sync(0xffffffffu, m, o));
    float ex = __expf(s - m), sum = ex;
#pragma unroll
    for (int o = 16; o > 0; o >>= 1) sum += __shfl_xor_sync(0xffffffffu, sum, o);
    aw[l * T + tt] = ex / sum;
    __syncthreads();

    const float* eb = emb + (long long)(b * NN + n) * T * H;
    float* mb = msg + (long long)(b * NN + n) * RL * H;
    for (int idx = tid; idx < RL * H; idx += 256) {
        int l2 = idx / H, h = idx - l2 * H;
        float acc = 0.f;
#pragma unroll 8
        for (int t2 = 0; t2 < T; t2++) acc += aw[l2 * T + t2] * eb[(long long)t2 * H + h];
        mb[idx] = acc;
    }
}

// ---------------- gate attention per b (grid Bn) ----------------
__global__ __launch_bounds__(256) void region_attn_kernel(
    const float* __restrict__ xs, const float* __restrict__ msg,
    const float* __restrict__ dist, const float* __restrict__ wb,
    const float* __restrict__ bb, float* __restrict__ att, int E0)
{
    __shared__ float red[256];
    __shared__ float sc[NN];
    int b = blockIdx.x, tid = threadIdx.x;

    float p = 0.f;
    const float* xb = xs + ((long long)b * S + E0) * H;
    for (int i = tid; i < RL * H; i += 256) p += xb[i] * g_u[i % H];
    red[tid] = p; __syncthreads();
    for (int s2 = 128; s2 > 0; s2 >>= 1) {
        if (tid < s2) red[tid] += red[tid + s2];
        __syncthreads();
    }
    float feasdot = red[0] / (float)RL;
    __syncthreads();

    for (int n = 0; n < NN; n++) {
        const float* mb = msg + (long long)(b * NN + n) * RL * H;
        float p2 = 0.f;
        for (int i = tid; i < RL * H; i += 256) p2 += mb[i] * g_u[H + i % H];
        red[tid] = p2; __syncthreads();
        for (int s2 = 128; s2 > 0; s2 >>= 1) {
            if (tid < s2) red[tid] += red[tid + s2];
            __syncthreads();
        }
        if (tid == 0) {
            float pre = feasdot + red[0] / (float)RL + g_u[2 * H];
            float z = pre >= 0.f ? pre : NEG * pre;
            sc[n] = z + dist[b * NN + n] * wb[0] + bb[0];
        }
        __syncthreads();
    }

    if (tid < 32) {
        float v = sc[tid];
        float m = v;
#pragma unroll
        for (int o = 16; o > 0; o >>= 1) m = fmaxf(m, __shfl_xor_sync(0xffffffffu, m, o));
        float e = __expf(v - m), s = e;
#pragma unroll
        for (int o = 16; o > 0; o >>= 1) s += __shfl_xor_sync(0xffffffffu, s, o);
        att[b * NN + tid] = e / s;
    }
}

// ---------------- x = xs (+ region message aggregation) ----------------
__global__ void build_x_kernel(const float* __restrict__ xs)
{
    long long idx = (long long)blockIdx.x * 256 + threadIdx.x;
    float v = xs[idx];
    int h = (int)(idx % H);
    int s = (int)((idx / H) % S);
    int b = (int)(idx / ((long long)H * S));
    if (s >= 1 && s < 9) {
        int l = s - 1;
#pragma unroll 4
        for (int n = 0; n < NN; n++)
            v += g_att1[b * NN + n] * g_msg1[(((long long)(b * NN + n)) * RL + l) * H + h];
    } else if (s >= 20 && s < 28) {
        int l = s - 20;
#pragma unroll 4
        for (int n = 0; n < NN; n++)
            v += g_att2[b * NN + n] * g_msg2[(((long long)(b * NN + n)) * RL + l) * H + h];
    }
    g_x[idx] = v;
}

// ---------------- row softmax over 512 cols of g_probs ----------------
__global__ __launch_bounds__(256) void softmax_rows_kernel()
{
    __shared__ float red[256];
    long long row = blockIdx.x;
    float* r = g_probs + row * S;
    int tid = threadIdx.x;
    float a = r[tid], b2 = r[tid + 256];
    float m = fmaxf(a, b2);
    red[tid] = m; __syncthreads();
    for (int s2 = 128; s2 > 0; s2 >>= 1) {
        if (tid < s2) red[tid] = fmaxf(red[tid], red[tid + s2]);
        __syncthreads();
    }
    float M = red[0]; __syncthreads();
    float ea = __expf(a - M), eb = __expf(b2 - M);
    red[tid] = ea + eb; __syncthreads();
    for (int s2 = 128; s2 > 0; s2 >>= 1) {
        if (tid < s2) red[tid] += red[tid + s2];
        __syncthreads();
    }
    float inv = 1.f / red[0];
    r[tid] = ea * inv; r[tid + 256] = eb * inv;
}

// ---------------- launch ----------------
extern "C" void kernel_launch(void* const* d_in, const int* in_sizes, int n_in,
                              void* d_out, int out_size)
{
    const float* xs    = (const float*)d_in[0];
    const float* n1emb = (const float*)d_in[1];
    const float* n2emb = (const float*)d_in[2];
    const float* dist1 = (const float*)d_in[3];
    const float* dist2 = (const float*)d_in[4];
    const float* Wq    = (const float*)d_in[5];
    const float* bq    = (const float*)d_in[6];
    const float* Wk    = (const float*)d_in[7];
    const float* bk    = (const float*)d_in[8];
    const float* Wv    = (const float*)d_in[9];
    const float* bv    = (const float*)d_in[10];
    const float* Wa    = (const float*)d_in[11];
    const float* ba    = (const float*)d_in[12];
    const float* Wattn = (const float*)d_in[13];
    const float* battn = (const float*)d_in[14];
    const float* wb    = (const float*)d_in[15];
    const float* bb    = (const float*)d_in[16];
    float* out = (float*)d_out;

    float *px, *pq, *pk, *pv, *pp, *pkn, *pm1, *pm2, *pqe1, *pqe2, *pa1, *pa2;
    cudaGetSymbolAddress((void**)&px,   g_x);
    cudaGetSymbolAddress((void**)&pq,   g_q);
    cudaGetSymbolAddress((void**)&pk,   g_k);
    cudaGetSymbolAddress((void**)&pv,   g_v);
    cudaGetSymbolAddress((void**)&pp,   g_probs);
    cudaGetSymbolAddress((void**)&pkn,  g_kn);
    cudaGetSymbolAddress((void**)&pm1,  g_msg1);
    cudaGetSymbolAddress((void**)&pm2,  g_msg2);
    cudaGetSymbolAddress((void**)&pqe1, g_qe1);
    cudaGetSymbolAddress((void**)&pqe2, g_qe2);
    cudaGetSymbolAddress((void**)&pa1,  g_att1);
    cudaGetSymbolAddress((void**)&pa2,  g_att2);

    // gate projection vectors
    u_kernel<<<7, 256>>>(Wa, Wattn, ba, battn);

    // per-branch neighbor queries
    qe_kernel<<<Bn * RL, 256>>>(xs, Wq, bq, pqe1, 1);
    qe_kernel<<<Bn * RL, 256>>>(xs, Wq, bq, pqe2, 20);

    // branch 1: kn GEMM then fused attn+message
    dim3 gkn(NE / 128, (Bn * NN * T) / 128, 1);
    sgemm_k<false, true><<<gkn, 256>>>(n1emb, Wk, bk, pkn, Bn * NN * T, NE, H, 1.f, 0, 0, 0);
    neigh_kernel<<<Bn * NN, 256>>>(pqe1, n1emb, pm1);

    // branch 2 (reuses g_kn)
    sgemm_k<false, true><<<gkn, 256>>>(n2emb, Wk, bk, pkn, Bn * NN * T, NE, H, 1.f, 0, 0, 0);
    neigh_kernel<<<Bn * NN, 256>>>(pqe2, n2emb, pm2);

    // gate attention weights
    region_attn_kernel<<<Bn, 256>>>(xs, pm1, dist1, wb, bb, pa1, 1);
    region_attn_kernel<<<Bn, 256>>>(xs, pm2, dist2, wb, bb, pa2, 20);

    // x = xs + gated messages
    build_x_kernel<<<(Bn * S * H) / 256, 256>>>(xs);

    // final attention projections
    sgemm_k<false, true><<<dim3(NE / 128, (Bn * S) / 128, 1), 256>>>(
        px, Wq, bq, pq, Bn * S, NE, H, 1.f, 0, 0, 0);
    sgemm_k<false, true><<<dim3(NE / 128, (Bn * S) / 128, 1), 256>>>(
        px, Wk, bk, pk, Bn * S, NE, H, 1.f, 0, 0, 0);
    sgemm_k<false, true><<<dim3(H / 128, (Bn * S) / 128, 1), 256>>>(
        px, Wv, bv, pv, Bn * S, H, H, 1.f, 0, 0, 0);

    // scores = scale * q @ k^T  (batched, transB)
    sgemm_k<true, false><<<dim3(S / 128, S / 128, Bn), 256>>>(
        pq, pk, nullptr, pp, S, S, NE, SCALE,
        (long long)S * NE, (long long)S * NE, (long long)S * S);

    softmax_rows_kernel<<<Bn * S, 256>>>();

    // out = probs @ v (batched)
    sgemm_k<false, false><<<dim3(H / 128, S / 128, Bn), 256>>>(
        pp, pv, nullptr, out, S, H, S, 1.f,
        (long long)S * S, (long long)S * H, (long long)S * H);
}

// round 4
// speedup vs baseline: 1.7758x; 1.7758x over previous
#include <cuda_runtime.h>
#include <cuda_bf16.h>
#include <cstdint>

// ---------------- problem constants ----------------
namespace {
constexpr int Bn = 32;    // batch
constexpr int S  = 512;   // sequence
constexpr int H  = 768;   // hidden
constexpr int NN = 32;    // neighbors
constexpr int T  = 32;    // tokens per neighbor
constexpr int NE = 256;   // q/k embed
constexpr int AE = 128;   // attn embed
constexpr int RL = 8;     // region length
constexpr float SCALE = 0.0625f;
constexpr float NEG   = 0.01f;
}

// ---------------- scratch (device globals; no allocation) ----------------
__device__ float g_x    [Bn * S * H];
__device__ float g_q    [Bn * S * NE];
__device__ float g_probs[Bn * S * S];
__device__ float g_kn   [Bn * NN * T * NE];
__device__ float g_msg1 [Bn * NN * RL * H];
__device__ float g_msg2 [Bn * NN * RL * H];
__device__ float g_qe1  [Bn * RL * NE];
__device__ float g_qe2  [Bn * RL * NE];
__device__ float g_att1 [Bn * NN];
__device__ float g_att2 [Bn * NN];
__device__ float g_u    [2 * H + 1];

__device__ __nv_bfloat16 g_WqTh[NE * H], g_WqTl[NE * H];
__device__ __nv_bfloat16 g_WkTh[NE * H], g_WkTl[NE * H];
__device__ __nv_bfloat16 g_WvTh[H * H],  g_WvTl[H * H];
__device__ __nv_bfloat16 g_kh[Bn * S * NE], g_kl[Bn * S * NE];
__device__ __nv_bfloat16 g_vTh[Bn * H * S], g_vTl[Bn * H * S];

// ---------------- helpers ----------------
__device__ __forceinline__ uint32_t smem_u32(const void* p) {
    uint32_t a;
    asm("{ .reg .u64 t; cvta.to.shared.u64 t, %1; cvt.u32.u64 %0, t; }" : "=r"(a) : "l"(p));
    return a;
}
__device__ __forceinline__ uint32_t bpack(__nv_bfloat16 a, __nv_bfloat16 b) {
    __nv_bfloat162 t = __halves2bfloat162(a, b);
    return *reinterpret_cast<uint32_t*>(&t);
}
__device__ __forceinline__ uint32_t fpack(float a, float b) {
    __nv_bfloat162 t = __floats2bfloat162_rn(a, b);
    return *reinterpret_cast<uint32_t*>(&t);
}
__device__ __forceinline__ void ldsm4(uint32_t& r0, uint32_t& r1, uint32_t& r2,
                                      uint32_t& r3, uint32_t a) {
    asm volatile("ldmatrix.sync.aligned.m8n8.x4.shared.b16 {%0,%1,%2,%3}, [%4];"
                 : "=r"(r0), "=r"(r1), "=r"(r2), "=r"(r3) : "r"(a));
}
__device__ __forceinline__ void mma16816(float* d, const uint32_t* a, const uint32_t* b) {
    asm volatile(
        "mma.sync.aligned.m16n8k16.row.col.f32.bf16.bf16.f32 "
        "{%0,%1,%2,%3}, {%4,%5,%6,%7}, {%8,%9}, {%0,%1,%2,%3};"
        : "+f"(d[0]), "+f"(d[1]), "+f"(d[2]), "+f"(d[3])
        : "r"(a[0]), "r"(a[1]), "r"(a[2]), "r"(a[3]), "r"(b[0]), "r"(b[1]));
}

// ================= bf16x3 HMMA GEMM =================
// D[m,n] = sum_k A[m,k]*B[n,k] (+bias), A fp32 (inline hi/lo split), B bf16 hi/lo
// K-major. Block tile 128x128, BK=32, 8 warps (2x4), warp tile 64x32.
// EPI: 0 = fp32 out (alpha*acc + bias?), 1 = bf16 hi/lo out (+bias),
//      2 = bf16 hi/lo TRANSPOSED out (+bias): Ch[b*NT*512 + n*512 + t], m = b*512+t
constexpr int ROWB = 80;           // padded bytes per 32-element bf16 row
constexpr int MTILE = 128 * ROWB;  // 10240 per matrix
constexpr int BUFB  = 4 * MTILE;   // Ah, Al, Bh, Bl
constexpr int HG_SMEM = 2 * BUFB;  // 81920 (double buffered)

template<int EPI>
__global__ __launch_bounds__(256, 1) void hgemm(
    const float* __restrict__ A,
    const __nv_bfloat16* __restrict__ Bhp, const __nv_bfloat16* __restrict__ Blp,
    const float* __restrict__ bias, float* __restrict__ Cf,
    __nv_bfloat16* __restrict__ Ch, __nv_bfloat16* __restrict__ Cl,
    int lda, int ldb, int ldc, int K, float alpha,
    long long sA, long long sB, long long sC, int NT)
{
    extern __shared__ char smem[];
    const uint32_t sb = smem_u32(smem);
    const int tid = threadIdx.x, w = tid >> 5, lane = tid & 31;
    const int m0 = blockIdx.y * 128, n0 = blockIdx.x * 128, bz = blockIdx.z;
    A   += (long long)bz * sA;
    Bhp += (long long)bz * sB;
    Blp += (long long)bz * sB;
    if (EPI == 0) Cf += (long long)bz * sC;

    const int wm = (w >> 2) * 64, wn = (w & 3) * 32;
    float acc[4][4][4];
#pragma unroll
    for (int a = 0; a < 4; a++)
#pragma unroll
        for (int b = 0; b < 4; b++)
#pragma unroll
            for (int c = 0; c < 4; c++) acc[a][b][c] = 0.f;

    float aS[16];
    uint4 bhS[2], blS[2];

    auto LDG = [&](int c) {
        const int k0 = c << 5;
#pragma unroll
        for (int it = 0; it < 4; ++it) {
            int i = (it << 8) + tid, row = i >> 3, kq = (i & 7) << 2;
            *(float4*)&aS[it * 4] =
                *(const float4*)(A + (long long)(m0 + row) * lda + k0 + kq);
        }
#pragma unroll
        for (int it = 0; it < 2; ++it) {
            int i = (it << 8) + tid, row = i >> 2, kb = (i & 3) << 3;
            long long g = (long long)(n0 + row) * ldb + k0 + kb;
            bhS[it] = *(const uint4*)(Bhp + g);
            blS[it] = *(const uint4*)(Blp + g);
        }
    };
    auto STS = [&](int c) {
        char* base = smem + (c & 1) * BUFB;
#pragma unroll
        for (int it = 0; it < 4; ++it) {
            int i = (it << 8) + tid, row = i >> 3, kq = (i & 7) << 2;
            float x0 = aS[it * 4], x1 = aS[it * 4 + 1];
            float x2 = aS[it * 4 + 2], x3 = aS[it * 4 + 3];
            __nv_bfloat16 h0 = __float2bfloat16(x0), h1 = __float2bfloat16(x1);
            __nv_bfloat16 h2 = __float2bfloat16(x2), h3 = __float2bfloat16(x3);
            uint2 hv; hv.x = bpack(h0, h1); hv.y = bpack(h2, h3);
            uint2 lv;
            lv.x = fpack(x0 - __bfloat162float(h0), x1 - __bfloat162float(h1));
            lv.y = fpack(x2 - __bfloat162float(h2), x3 - __bfloat162float(h3));
            int off = row * ROWB + (kq << 1);
            *(uint2*)(base + off) = hv;
            *(uint2*)(base + MTILE + off) = lv;
        }
#pragma unroll
        for (int it = 0; it < 2; ++it) {
            int i = (it << 8) + tid, row = i >> 2, kb = (i & 3) << 3;
            int off = row * ROWB + (kb << 1);
            *(uint4*)(base + 2 * MTILE + off) = bhS[it];
            *(uint4*)(base + 3 * MTILE + off) = blS[it];
        }
    };

    // lane-constant ldmatrix address selectors
    const int q = lane >> 3, r = lane & 7;
    const int aRow = ((q & 1) << 3) + r;   // +8 rows for matrices 1,3
    const int aCol = (q >> 1) << 4;        // +16 B (k+8) for matrices 2,3
    const int bRow = ((q >> 1) << 3) + r;  // +8 rows (next n-tile) for matrices 2,3
    const int bCol = (q & 1) << 4;         // +16 B (k+8) for matrices 1,3

    const int nch = K >> 5;
    for (int c = 0; c < nch; c++) {
        if (c == 0) { LDG(0); STS(0); __syncthreads(); }
        if (c + 1 < nch) LDG(c + 1);

        const uint32_t Ah = sb + (c & 1) * BUFB;
        const uint32_t Al = Ah + MTILE, Bh = Ah + 2 * MTILE, Bl = Ah + 3 * MTILE;
#pragma unroll
        for (int s = 0; s < 2; s++) {
            const int kOff = s * 32;
            uint32_t ah[4][4], al[4][4];
#pragma unroll
            for (int mt = 0; mt < 4; mt++) {
                uint32_t off = (uint32_t)(wm + mt * 16 + aRow) * ROWB + kOff + aCol;
                ldsm4(ah[mt][0], ah[mt][1], ah[mt][2], ah[mt][3], Ah + off);
                ldsm4(al[mt][0], al[mt][1], al[mt][2], al[mt][3], Al + off);
            }
            uint32_t bh[4][2], bl[4][2];
#pragma unroll
            for (int np = 0; np < 2; np++) {
                uint32_t off = (uint32_t)(wn + np * 16 + bRow) * ROWB + kOff + bCol;
                ldsm4(bh[2 * np][0], bh[2 * np][1], bh[2 * np + 1][0], bh[2 * np + 1][1],
                      Bh + off);
                ldsm4(bl[2 * np][0], bl[2 * np][1], bl[2 * np + 1][0], bl[2 * np + 1][1],
                      Bl + off);
            }
#pragma unroll
            for (int mt = 0; mt < 4; mt++)
#pragma unroll
                for (int nt = 0; nt < 4; nt++) {
                    mma16816(acc[mt][nt], ah[mt], bh[nt]);
                    mma16816(acc[mt][nt], ah[mt], bl[nt]);
                    mma16816(acc[mt][nt], al[mt], bh[nt]);
                }
        }
        if (c + 1 < nch) STS(c + 1);
        __syncthreads();
    }

    // epilogue: lane holds (row gid/gid+8, cols tig*2,+1) per mma tile
    const int gid = lane >> 2, tig = lane & 3;
#pragma unroll
    for (int mt = 0; mt < 4; mt++)
#pragma unroll
        for (int half = 0; half < 2; half++) {
            const long long m = m0 + wm + mt * 16 + gid + half * 8;
#pragma unroll
            for (int nt = 0; nt < 4; nt++) {
                float v0 = acc[mt][nt][half * 2 + 0];
                float v1 = acc[mt][nt][half * 2 + 1];
                const int n = n0 + wn + nt * 8 + tig * 2;
                if (EPI == 0) {
                    v0 *= alpha; v1 *= alpha;
                    if (bias) { v0 += bias[n]; v1 += bias[n + 1]; }
                    *(float2*)&Cf[m * ldc + n] = make_float2(v0, v1);
                } else if (EPI == 1) {
                    v0 += bias[n]; v1 += bias[n + 1];
                    __nv_bfloat16 h0 = __float2bfloat16(v0), h1 = __float2bfloat16(v1);
                    *(uint32_t*)&Ch[m * ldc + n] = bpack(h0, h1);
                    *(uint32_t*)&Cl[m * ldc + n] =
                        fpack(v0 - __bfloat162float(h0), v1 - __bfloat162float(h1));
                } else {
                    v0 += bias[n]; v1 += bias[n + 1];
                    const long long b = m >> 9, t = m & 511;
                    __nv_bfloat16 h0 = __float2bfloat16(v0), h1 = __float2bfloat16(v1);
                    Ch[(b * NT + n) * 512 + t] = h0;
                    Cl[(b * NT + n) * 512 + t] = __float2bfloat16(v0 - __bfloat162float(h0));
                    Ch[(b * NT + n + 1) * 512 + t] = h1;
                    Cl[(b * NT + n + 1) * 512 + t] = __float2bfloat16(v1 - __bfloat162float(h1));
                }
            }
        }
}

// ---------------- transpose + split weights: W[K,N] -> out[N,K] bf16 hi/lo ----
__global__ void tsplit_kernel(const float* __restrict__ W,
                              __nv_bfloat16* __restrict__ oh,
                              __nv_bfloat16* __restrict__ ol, int K, int N)
{
    int idx = blockIdx.x * 256 + threadIdx.x;
    if (idx >= K * N) return;
    int n = idx / K, k = idx - n * K;
    float x = W[(long long)k * N + n];
    __nv_bfloat16 h = __float2bfloat16(x);
    oh[idx] = h;
    ol[idx] = __float2bfloat16(x - __bfloat162float(h));
}

// ---------------- u = Wa @ Wattn halves; cbase ----------------
__global__ void u_kernel(const float* __restrict__ Wa, const float* __restrict__ Wattn,
                         const float* __restrict__ ba, const float* __restrict__ battn)
{
    if (blockIdx.x < 6) {
        int g = blockIdx.x * 256 + threadIdx.x;
        int j = g / H, h = g - j * H;
        float acc = 0.f;
#pragma unroll 8
        for (int a = 0; a < AE; a++) acc += Wa[h * AE + a] * Wattn[j * AE + a];
        g_u[g] = acc;
    } else {
        __shared__ float red[256];
        int tid = threadIdx.x;
        float v = 0.f;
        if (tid < AE) v = ba[tid] * (Wattn[tid] + Wattn[AE + tid]);
        red[tid] = v; __syncthreads();
        for (int s2 = 128; s2 > 0; s2 >>= 1) {
            if (tid < s2) red[tid] += red[tid + s2];
            __syncthreads();
        }
        if (tid == 0) g_u[2 * H] = red[0] + battn[0];
    }
}

// ---------------- q_e = e_fea @ Wq + bq ----------------
__global__ __launch_bounds__(256) void qe_kernel(
    const float* __restrict__ xs, const float* __restrict__ Wq,
    const float* __restrict__ bq, float* __restrict__ qe, int E0)
{
    __shared__ float xr[H];
    int b = blockIdx.x >> 3, l = blockIdx.x & 7;
    int tid = threadIdx.x;
    const float* row = xs + ((long long)b * S + E0 + l) * H;
    for (int i = tid; i < H; i += 256) xr[i] = row[i];
    __syncthreads();
    float acc = bq[tid];
#pragma unroll 8
    for (int h = 0; h < H; h++) acc += xr[h] * Wq[h * NE + tid];
    qe[(long long)(b * RL + l) * NE + tid] = acc;
}

// ---------------- per-(b,n): scores -> softmax over T -> message ----------------
__global__ __launch_bounds__(256) void neigh_kernel(
    const float* __restrict__ qe, const float* __restrict__ emb,
    float* __restrict__ msg)
{
    __shared__ float qs[RL * NE];
    __shared__ float ks[T * (NE + 1)];
    __shared__ float aw[RL * T];
    int b = blockIdx.x / NN, n = blockIdx.x % NN;
    int tid = threadIdx.x;

    const float* qb = qe + (long long)b * RL * NE;
    for (int i = tid; i < RL * NE; i += 256) qs[i] = qb[i];
    const float* kb = g_kn + (long long)(b * NN + n) * T * NE;
    for (int i = tid; i < T * NE; i += 256) {
        int r = i / NE, c = i - r * NE;
        ks[r * (NE + 1) + c] = kb[i];
    }
    __syncthreads();

    int l = tid >> 5, tt = tid & 31;
    float s = 0.f;
    const float* qrow = qs + l * NE;
    const float* krow = ks + tt * (NE + 1);
#pragma unroll 8
    for (int e = 0; e < NE; e++) s += qrow[e] * krow[e];
    s *= SCALE;
    float m = s;
#pragma unroll
    for (int o = 16; o > 0; o >>= 1) m = fmaxf(m, __shfl_xor_sync(0xffffffffu, m, o));
    float ex = __expf(s - m), sum = ex;
#pragma unroll
    for (int o = 16; o > 0; o >>= 1) sum += __shfl_xor_sync(0xffffffffu, sum, o);
    aw[l * T + tt] = ex / sum;
    __syncthreads();

    const float* eb = emb + (long long)(b * NN + n) * T * H;
    float* mb = msg + (long long)(b * NN + n) * RL * H;
    for (int idx = tid; idx < RL * H; idx += 256) {
        int l2 = idx / H, h = idx - l2 * H;
        float acc = 0.f;
#pragma unroll 8
        for (int t2 = 0; t2 < T; t2++) acc += aw[l2 * T + t2] * eb[(long long)t2 * H + h];
        mb[idx] = acc;
    }
}

// ---------------- gate attention per b ----------------
__global__ __launch_bounds__(256) void region_attn_kernel(
    const float* __restrict__ xs, const float* __restrict__ msg,
    const float* __restrict__ dist, const float* __restrict__ wb,
    const float* __restrict__ bb, float* __restrict__ att, int E0)
{
    __shared__ float red[256];
    __shared__ float sc[NN];
    int b = blockIdx.x, tid = threadIdx.x;

    float p = 0.f;
    const float* xb = xs + ((long long)b * S + E0) * H;
    for (int i = tid; i < RL * H; i += 256) p += xb[i] * g_u[i % H];
    red[tid] = p; __syncthreads();
    for (int s2 = 128; s2 > 0; s2 >>= 1) {
        if (tid < s2) red[tid] += red[tid + s2];
        __syncthreads();
    }
    float feasdot = red[0] / (float)RL;
    __syncthreads();

    for (int n = 0; n < NN; n++) {
        const float* mb = msg + (long long)(b * NN + n) * RL * H;
        float p2 = 0.f;
        for (int i = tid; i < RL * H; i += 256) p2 += mb[i] * g_u[H + i % H];
        red[tid] = p2; __syncthreads();
        for (int s2 = 128; s2 > 0; s2 >>= 1) {
            if (tid < s2) red[tid] += red[tid + s2];
            __syncthreads();
        }
        if (tid == 0) {
            float pre = feasdot + red[0] / (float)RL + g_u[2 * H];
            float z = pre >= 0.f ? pre : NEG * pre;
            sc[n] = z + dist[b * NN + n] * wb[0] + bb[0];
        }
        __syncthreads();
    }

    if (tid < 32) {
        float v = sc[tid];
        float m = v;
#pragma unroll
        for (int o = 16; o > 0; o >>= 1) m = fmaxf(m, __shfl_xor_sync(0xffffffffu, m, o));
        float e = __expf(v - m), s = e;
#pragma unroll
        for (int o = 16; o > 0; o >>= 1) s += __shfl_xor_sync(0xffffffffu, s, o);
        att[b * NN + tid] = e / s;
    }
}

// ---------------- x = xs (+ region message aggregation) ----------------
__global__ void build_x_kernel(const float* __restrict__ xs)
{
    long long idx = (long long)blockIdx.x * 256 + threadIdx.x;
    float v = xs[idx];
    int h = (int)(idx % H);
    int s = (int)((idx / H) % S);
    int b = (int)(idx / ((long long)H * S));
    if (s >= 1 && s < 9) {
        int l = s - 1;
#pragma unroll 4
        for (int n = 0; n < NN; n++)
            v += g_att1[b * NN + n] * g_msg1[(((long long)(b * NN + n)) * RL + l) * H + h];
    } else if (s >= 20 && s < 28) {
        int l = s - 20;
#pragma unroll 4
        for (int n = 0; n < NN; n++)
            v += g_att2[b * NN + n] * g_msg2[(((long long)(b * NN + n)) * RL + l) * H + h];
    }
    g_x[idx] = v;
}

// ---------------- row softmax over 512 cols of g_probs ----------------
__global__ __launch_bounds__(256) void softmax_rows_kernel()
{
    __shared__ float red[256];
    long long row = blockIdx.x;
    float* r = g_probs + row * S;
    int tid = threadIdx.x;
    float a = r[tid], b2 = r[tid + 256];
    float m = fmaxf(a, b2);
    red[tid] = m; __syncthreads();
    for (int s2 = 128; s2 > 0; s2 >>= 1) {
        if (tid < s2) red[tid] = fmaxf(red[tid], red[tid + s2]);
        __syncthreads();
    }
    float M = red[0]; __syncthreads();
    float ea = __expf(a - M), eb = __expf(b2 - M);
    red[tid] = ea + eb; __syncthreads();
    for (int s2 = 128; s2 > 0; s2 >>= 1) {
        if (tid < s2) red[tid] += red[tid + s2];
        __syncthreads();
    }
    float inv = 1.f / red[0];
    r[tid] = ea * inv; r[tid + 256] = eb * inv;
}

// ---------------- launch ----------------
extern "C" void kernel_launch(void* const* d_in, const int* in_sizes, int n_in,
                              void* d_out, int out_size)
{
    const float* xs    = (const float*)d_in[0];
    const float* n1emb = (const float*)d_in[1];
    const float* n2emb = (const float*)d_in[2];
    const float* dist1 = (const float*)d_in[3];
    const float* dist2 = (const float*)d_in[4];
    const float* Wq    = (const float*)d_in[5];
    const float* bq    = (const float*)d_in[6];
    const float* Wk    = (const float*)d_in[7];
    const float* bk    = (const float*)d_in[8];
    const float* Wv    = (const float*)d_in[9];
    const float* bv    = (const float*)d_in[10];
    const float* Wa    = (const float*)d_in[11];
    const float* ba    = (const float*)d_in[12];
    const float* Wattn = (const float*)d_in[13];
    const float* battn = (const float*)d_in[14];
    const float* wb    = (const float*)d_in[15];
    const float* bb    = (const float*)d_in[16];
    float* out = (float*)d_out;

    float *px, *pq, *pp, *pkn, *pm1, *pm2, *pqe1, *pqe2, *pa1, *pa2;
    __nv_bfloat16 *wqth, *wqtl, *wkth, *wktl, *wvth, *wvtl, *pkh, *pkl, *pvh, *pvl;
    cudaGetSymbolAddress((void**)&px,   g_x);
    cudaGetSymbolAddress((void**)&pq,   g_q);
    cudaGetSymbolAddress((void**)&pp,   g_probs);
    cudaGetSymbolAddress((void**)&pkn,  g_kn);
    cudaGetSymbolAddress((void**)&pm1,  g_msg1);
    cudaGetSymbolAddress((void**)&pm2,  g_msg2);
    cudaGetSymbolAddress((void**)&pqe1, g_qe1);
    cudaGetSymbolAddress((void**)&pqe2, g_qe2);
    cudaGetSymbolAddress((void**)&pa1,  g_att1);
    cudaGetSymbolAddress((void**)&pa2,  g_att2);
    cudaGetSymbolAddress((void**)&wqth, g_WqTh);
    cudaGetSymbolAddress((void**)&wqtl, g_WqTl);
    cudaGetSymbolAddress((void**)&wkth, g_WkTh);
    cudaGetSymbolAddress((void**)&wktl, g_WkTl);
    cudaGetSymbolAddress((void**)&wvth, g_WvTh);
    cudaGetSymbolAddress((void**)&wvtl, g_WvTl);
    cudaGetSymbolAddress((void**)&pkh,  g_kh);
    cudaGetSymbolAddress((void**)&pkl,  g_kl);
    cudaGetSymbolAddress((void**)&pvh,  g_vTh);
    cudaGetSymbolAddress((void**)&pvl,  g_vTl);

    cudaFuncSetAttribute(hgemm<0>, cudaFuncAttributeMaxDynamicSharedMemorySize, HG_SMEM);
    cudaFuncSetAttribute(hgemm<1>, cudaFuncAttributeMaxDynamicSharedMemorySize, HG_SMEM);
    cudaFuncSetAttribute(hgemm<2>, cudaFuncAttributeMaxDynamicSharedMemorySize, HG_SMEM);

    // weight transpose + split
    tsplit_kernel<<<(H * NE + 255) / 256, 256>>>(Wq, wqth, wqtl, H, NE);
    tsplit_kernel<<<(H * NE + 255) / 256, 256>>>(Wk, wkth, wktl, H, NE);
    tsplit_kernel<<<(H * H  + 255) / 256, 256>>>(Wv, wvth, wvtl, H, H);

    // gate projection vectors + neighbor queries
    u_kernel<<<7, 256>>>(Wa, Wattn, ba, battn);
    qe_kernel<<<Bn * RL, 256>>>(xs, Wq, bq, pqe1, 1);
    qe_kernel<<<Bn * RL, 256>>>(xs, Wq, bq, pqe2, 20);

    // branch 1: kn = emb1 @ Wk^T + bk, then fused attn+message
    hgemm<0><<<dim3(NE / 128, (Bn * NN * T) / 128, 1), 256, HG_SMEM>>>(
        n1emb, wkth, wktl, bk, pkn, nullptr, nullptr,
        H, H, NE, H, 1.f, 0, 0, 0, 0);
    neigh_kernel<<<Bn * NN, 256>>>(pqe1, n1emb, pm1);

    // branch 2 (reuses g_kn)
    hgemm<0><<<dim3(NE / 128, (Bn * NN * T) / 128, 1), 256, HG_SMEM>>>(
        n2emb, wkth, wktl, bk, pkn, nullptr, nullptr,
        H, H, NE, H, 1.f, 0, 0, 0, 0);
    neigh_kernel<<<Bn * NN, 256>>>(pqe2, n2emb, pm2);

    // gate attention + x update
    region_attn_kernel<<<Bn, 256>>>(xs, pm1, dist1, wb, bb, pa1, 1);
    region_attn_kernel<<<Bn, 256>>>(xs, pm2, dist2, wb, bb, pa2, 20);
    build_x_kernel<<<(Bn * S * H) / 256, 256>>>(xs);

    // q = x @ Wq^T + bq (fp32, A-operand of QK)
    hgemm<0><<<dim3(NE / 128, (Bn * S) / 128, 1), 256, HG_SMEM>>>(
        px, wqth, wqtl, bq, pq, nullptr, nullptr,
        H, H, NE, H, 1.f, 0, 0, 0, 0);
    // k = x @ Wk^T + bk (bf16 hi/lo, B-operand of QK)
    hgemm<1><<<dim3(NE / 128, (Bn * S) / 128, 1), 256, HG_SMEM>>>(
        px, wkth, wktl, bk, nullptr, pkh, pkl,
        H, H, NE, H, 1.f, 0, 0, 0, 0);
    // v = x @ Wv^T + bv (bf16 hi/lo TRANSPOSED per batch, B-operand of PV)
    hgemm<2><<<dim3(H / 128, (Bn * S) / 128, 1), 256, HG_SMEM>>>(
        px, wvth, wvtl, bv, nullptr, pvh, pvl,
        H, H, 0, H, 1.f, 0, 0, 0, H);

    // scores = SCALE * q @ k^T (batched)
    hgemm<0><<<dim3(S / 128, S / 128, Bn), 256, HG_SMEM>>>(
        pq, pkh, pkl, nullptr, pp, nullptr, nullptr,
        NE, NE, S, NE, SCALE,
        (long long)S * NE, (long long)S * NE, (long long)S * S, 0);

    softmax_rows_kernel<<<Bn * S, 256>>>();

    // out = probs @ v (batched; B = v^T hi/lo)
    hgemm<0><<<dim3(H / 128, S / 128, Bn), 256, HG_SMEM>>>(
        pp, pvh, pvl, nullptr, out, nullptr, nullptr,
        S, S, H, S, 1.f,
        (long long)S * S, (long long)H * S, (long long)S * H, 0);
}

// round 5
// speedup vs baseline: 2.5594x; 1.4412x over previous
#include <cuda_runtime.h>
#include <cuda_bf16.h>
#include <cstdint>

// ---------------- problem constants ----------------
namespace {
constexpr int Bn = 32;    // batch
constexpr int S  = 512;   // sequence
constexpr int H  = 768;   // hidden
constexpr int NN = 32;    // neighbors
constexpr int T  = 32;    // tokens per neighbor
constexpr int NE = 256;   // q/k embed
constexpr int AE = 128;   // attn embed
constexpr int RL = 8;     // region length
constexpr float SCALE = 0.0625f;
constexpr float NEG   = 0.01f;
}

// ---------------- scratch (device globals; no allocation) ----------------
__device__ float g_x    [Bn * S * H];
__device__ float g_q    [Bn * S * NE];
__device__ float g_probs[Bn * S * S];
__device__ float g_kn   [Bn * NN * T * NE];
__device__ float g_msg1 [Bn * NN * RL * H];
__device__ float g_msg2 [Bn * NN * RL * H];
__device__ float g_qe   [2 * Bn * RL * NE];
__device__ float g_att1 [Bn * NN];
__device__ float g_att2 [Bn * NN];
__device__ float g_u    [2 * H + 1];
__device__ float g_md   [2 * Bn * NN];
__device__ float g_feas [2 * Bn];

__device__ __nv_bfloat16 g_WqTh[NE * H], g_WqTl[NE * H];
__device__ __nv_bfloat16 g_WkTh[NE * H], g_WkTl[NE * H];
__device__ __nv_bfloat16 g_WvTh[H * H],  g_WvTl[H * H];
__device__ __nv_bfloat16 g_kh[Bn * S * NE], g_kl[Bn * S * NE];
__device__ __nv_bfloat16 g_vTh[Bn * H * S], g_vTl[Bn * H * S];

// ---------------- helpers ----------------
__device__ __forceinline__ uint32_t smem_u32(const void* p) {
    uint32_t a;
    asm("{ .reg .u64 t; cvta.to.shared.u64 t, %1; cvt.u32.u64 %0, t; }" : "=r"(a) : "l"(p));
    return a;
}
__device__ __forceinline__ uint32_t bpack(__nv_bfloat16 a, __nv_bfloat16 b) {
    __nv_bfloat162 t = __halves2bfloat162(a, b);
    return *reinterpret_cast<uint32_t*>(&t);
}
__device__ __forceinline__ uint32_t fpack(float a, float b) {
    __nv_bfloat162 t = __floats2bfloat162_rn(a, b);
    return *reinterpret_cast<uint32_t*>(&t);
}
__device__ __forceinline__ void ldsm4(uint32_t& r0, uint32_t& r1, uint32_t& r2,
                                      uint32_t& r3, uint32_t a) {
    asm volatile("ldmatrix.sync.aligned.m8n8.x4.shared.b16 {%0,%1,%2,%3}, [%4];"
                 : "=r"(r0), "=r"(r1), "=r"(r2), "=r"(r3) : "r"(a));
}
__device__ __forceinline__ void mma16816(float* d, const uint32_t* a, const uint32_t* b) {
    asm volatile(
        "mma.sync.aligned.m16n8k16.row.col.f32.bf16.bf16.f32 "
        "{%0,%1,%2,%3}, {%4,%5,%6,%7}, {%8,%9}, {%0,%1,%2,%3};"
        : "+f"(d[0]), "+f"(d[1]), "+f"(d[2]), "+f"(d[3])
        : "r"(a[0]), "r"(a[1]), "r"(a[2]), "r"(a[3]), "r"(b[0]), "r"(b[1]));
}

// ================= bf16x3 HMMA GEMM =================
// D[m,n] = sum_k A[m,k]*B[n,k] (+bias), A fp32 (inline hi/lo split), B bf16 hi/lo
// K-major. Block tile 128x128, BK=32, 8 warps (2x4), warp tile 64x32.
// EPI: 0 = fp32 out, 1 = bf16 hi/lo out (+bias), 2 = bf16 hi/lo transposed out.
// GATHER: A row m maps to xs row (b*S + E0(branch) + l), m = branch*256 + b*8 + l.
constexpr int ROWB = 80;
constexpr int MTILE = 128 * ROWB;
constexpr int BUFB  = 4 * MTILE;
constexpr int HG_SMEM = 2 * BUFB;  // 81920

template<int EPI, bool GATHER>
__global__ __launch_bounds__(256, 1) void hgemm(
    const float* __restrict__ A,
    const __nv_bfloat16* __restrict__ Bhp, const __nv_bfloat16* __restrict__ Blp,
    const float* __restrict__ bias, float* __restrict__ Cf,
    __nv_bfloat16* __restrict__ Ch, __nv_bfloat16* __restrict__ Cl,
    int lda, int ldb, int ldc, int K, float alpha,
    long long sA, long long sB, long long sC, int NT)
{
    extern __shared__ char smem[];
    const uint32_t sb = smem_u32(smem);
    const int tid = threadIdx.x, w = tid >> 5, lane = tid & 31;
    const int m0 = blockIdx.y * 128, n0 = blockIdx.x * 128, bz = blockIdx.z;
    A   += (long long)bz * sA;
    Bhp += (long long)bz * sB;
    Blp += (long long)bz * sB;
    if (EPI == 0) Cf += (long long)bz * sC;

    const int wm = (w >> 2) * 64, wn = (w & 3) * 32;
    float acc[4][4][4];
#pragma unroll
    for (int a = 0; a < 4; a++)
#pragma unroll
        for (int b = 0; b < 4; b++)
#pragma unroll
            for (int c = 0; c < 4; c++) acc[a][b][c] = 0.f;

    float aS[16];
    uint4 bhS[2], blS[2];

    auto arow = [&](int m) -> long long {
        if (!GATHER) return m;
        int br = m >> 8, b_ = (m >> 3) & 31, ll = m & 7;
        return (long long)b_ * S + (br ? 20 : 1) + ll;
    };

    auto LDG = [&](int c) {
        const int k0 = c << 5;
#pragma unroll
        for (int it = 0; it < 4; ++it) {
            int i = (it << 8) + tid, row = i >> 3, kq = (i & 7) << 2;
            *(float4*)&aS[it * 4] =
                *(const float4*)(A + arow(m0 + row) * lda + k0 + kq);
        }
#pragma unroll
        for (int it = 0; it < 2; ++it) {
            int i = (it << 8) + tid, row = i >> 2, kb = (i & 3) << 3;
            long long g = (long long)(n0 + row) * ldb + k0 + kb;
            bhS[it] = *(const uint4*)(Bhp + g);
            blS[it] = *(const uint4*)(Blp + g);
        }
    };
    auto STS = [&](int c) {
        char* base = smem + (c & 1) * BUFB;
#pragma unroll
        for (int it = 0; it < 4; ++it) {
            int i = (it << 8) + tid, row = i >> 3, kq = (i & 7) << 2;
            float x0 = aS[it * 4], x1 = aS[it * 4 + 1];
            float x2 = aS[it * 4 + 2], x3 = aS[it * 4 + 3];
            __nv_bfloat16 h0 = __float2bfloat16(x0), h1 = __float2bfloat16(x1);
            __nv_bfloat16 h2 = __float2bfloat16(x2), h3 = __float2bfloat16(x3);
            uint2 hv; hv.x = bpack(h0, h1); hv.y = bpack(h2, h3);
            uint2 lv;
            lv.x = fpack(x0 - __bfloat162float(h0), x1 - __bfloat162float(h1));
            lv.y = fpack(x2 - __bfloat162float(h2), x3 - __bfloat162float(h3));
            int off = row * ROWB + (kq << 1);
            *(uint2*)(base + off) = hv;
            *(uint2*)(base + MTILE + off) = lv;
        }
#pragma unroll
        for (int it = 0; it < 2; ++it) {
            int i = (it << 8) + tid, row = i >> 2, kb = (i & 3) << 3;
            int off = row * ROWB + (kb << 1);
            *(uint4*)(base + 2 * MTILE + off) = bhS[it];
            *(uint4*)(base + 3 * MTILE + off) = blS[it];
        }
    };

    const int q = lane >> 3, r = lane & 7;
    const int aRow = ((q & 1) << 3) + r;
    const int aCol = (q >> 1) << 4;
    const int bRow = ((q >> 1) << 3) + r;
    const int bCol = (q & 1) << 4;

    const int nch = K >> 5;
    for (int c = 0; c < nch; c++) {
        if (c == 0) { LDG(0); STS(0); __syncthreads(); }
        if (c + 1 < nch) LDG(c + 1);

        const uint32_t Ah = sb + (c & 1) * BUFB;
        const uint32_t Al = Ah + MTILE, Bh = Ah + 2 * MTILE, Bl = Ah + 3 * MTILE;
#pragma unroll
        for (int s = 0; s < 2; s++) {
            const int kOff = s * 32;
            uint32_t ah[4][4], al[4][4];
#pragma unroll
            for (int mt = 0; mt < 4; mt++) {
                uint32_t off = (uint32_t)(wm + mt * 16 + aRow) * ROWB + kOff + aCol;
                ldsm4(ah[mt][0], ah[mt][1], ah[mt][2], ah[mt][3], Ah + off);
                ldsm4(al[mt][0], al[mt][1], al[mt][2], al[mt][3], Al + off);
            }
            uint32_t bh[4][2], bl[4][2];
#pragma unroll
            for (int np = 0; np < 2; np++) {
                uint32_t off = (uint32_t)(wn + np * 16 + bRow) * ROWB + kOff + bCol;
                ldsm4(bh[2 * np][0], bh[2 * np][1], bh[2 * np + 1][0], bh[2 * np + 1][1],
                      Bh + off);
                ldsm4(bl[2 * np][0], bl[2 * np][1], bl[2 * np + 1][0], bl[2 * np + 1][1],
                      Bl + off);
            }
#pragma unroll
            for (int mt = 0; mt < 4; mt++)
#pragma unroll
                for (int nt = 0; nt < 4; nt++) {
                    mma16816(acc[mt][nt], ah[mt], bh[nt]);
                    mma16816(acc[mt][nt], ah[mt], bl[nt]);
                    mma16816(acc[mt][nt], al[mt], bh[nt]);
                }
        }
        if (c + 1 < nch) STS(c + 1);
        __syncthreads();
    }

    const int gid = lane >> 2, tig = lane & 3;
#pragma unroll
    for (int mt = 0; mt < 4; mt++)
#pragma unroll
        for (int half = 0; half < 2; half++) {
            const long long m = m0 + wm + mt * 16 + gid + half * 8;
#pragma unroll
            for (int nt = 0; nt < 4; nt++) {
                float v0 = acc[mt][nt][half * 2 + 0];
                float v1 = acc[mt][nt][half * 2 + 1];
                const int n = n0 + wn + nt * 8 + tig * 2;
                if (EPI == 0) {
                    v0 *= alpha; v1 *= alpha;
                    if (bias) { v0 += bias[n]; v1 += bias[n + 1]; }
                    *(float2*)&Cf[m * ldc + n] = make_float2(v0, v1);
                } else if (EPI == 1) {
                    v0 += bias[n]; v1 += bias[n + 1];
                    __nv_bfloat16 h0 = __float2bfloat16(v0), h1 = __float2bfloat16(v1);
                    *(uint32_t*)&Ch[m * ldc + n] = bpack(h0, h1);
                    *(uint32_t*)&Cl[m * ldc + n] =
                        fpack(v0 - __bfloat162float(h0), v1 - __bfloat162float(h1));
                } else {
                    v0 += bias[n]; v1 += bias[n + 1];
                    const long long b = m >> 9, t = m & 511;
                    __nv_bfloat16 h0 = __float2bfloat16(v0), h1 = __float2bfloat16(v1);
                    Ch[(b * NT + n) * 512 + t] = h0;
                    Cl[(b * NT + n) * 512 + t] = __float2bfloat16(v0 - __bfloat162float(h0));
                    Ch[(b * NT + n + 1) * 512 + t] = h1;
                    Cl[(b * NT + n + 1) * 512 + t] = __float2bfloat16(v1 - __bfloat162float(h1));
                }
            }
        }
}

// ---------------- transpose + split all three weights in one launch ----------
__global__ void tsplit_all(const float* __restrict__ Wq, const float* __restrict__ Wk,
                           const float* __restrict__ Wv)
{
    int idx = blockIdx.x * 256 + threadIdx.x;   // [0, 983040)
    const float* W; __nv_bfloat16 *oh, *ol; int Nn, local;
    if (idx < NE * H)                 { W = Wq; oh = g_WqTh; ol = g_WqTl; Nn = NE; local = idx; }
    else if (idx < 2 * NE * H)        { W = Wk; oh = g_WkTh; ol = g_WkTl; Nn = NE; local = idx - NE * H; }
    else                              { W = Wv; oh = g_WvTh; ol = g_WvTl; Nn = H;  local = idx - 2 * NE * H; }
    int n = local / H, k = local - n * H;
    float x = W[(long long)k * Nn + n];
    __nv_bfloat16 h = __float2bfloat16(x);
    oh[local] = h;
    ol[local] = __float2bfloat16(x - __bfloat162float(h));
}

// ---------------- u = Wa @ Wattn halves (8 threads/output); cbase ------------
__global__ void u_kernel(const float* __restrict__ Wa, const float* __restrict__ Wattn,
                         const float* __restrict__ ba, const float* __restrict__ battn)
{
    if (blockIdx.x < 48) {
        int gt = blockIdx.x * 256 + threadIdx.x;
        int g = gt >> 3, sub = gt & 7;
        int j = g / H, h = g - j * H;
        float acc = 0.f;
#pragma unroll 4
        for (int a = sub; a < AE; a += 8) acc += Wa[h * AE + a] * Wattn[j * AE + a];
        acc += __shfl_down_sync(0xffffffffu, acc, 4, 8);
        acc += __shfl_down_sync(0xffffffffu, acc, 2, 8);
        acc += __shfl_down_sync(0xffffffffu, acc, 1, 8);
        if (sub == 0) g_u[g] = acc;
    } else {
        __shared__ float red[256];
        int tid = threadIdx.x;
        float v = 0.f;
        if (tid < AE) v = ba[tid] * (Wattn[tid] + Wattn[AE + tid]);
        red[tid] = v; __syncthreads();
        for (int s2 = 128; s2 > 0; s2 >>= 1) {
            if (tid < s2) red[tid] += red[tid + s2];
            __syncthreads();
        }
        if (tid == 0) g_u[2 * H] = red[0] + battn[0];
    }
}

// ---------------- per-(b,n): scores -> softmax over T -> message -------------
__global__ __launch_bounds__(256) void neigh_kernel(
    const float* __restrict__ qe, const float* __restrict__ emb,
    float* __restrict__ msg)
{
    __shared__ float qs[RL * NE];
    __shared__ float ks[T * (NE + 1)];
    __shared__ float aw[RL * T];
    int b = blockIdx.x / NN, n = blockIdx.x % NN;
    int tid = threadIdx.x;

    const float4* qb4 = (const float4*)(qe + (long long)b * RL * NE);
    for (int i = tid; i < RL * NE / 4; i += 256)
        *(float4*)&qs[i * 4] = qb4[i];
    const float4* kb4 = (const float4*)(g_kn + (long long)(b * NN + n) * T * NE);
    for (int i = tid; i < T * NE / 4; i += 256) {
        float4 v = kb4[i];
        int r = i / (NE / 4), c = (i - r * (NE / 4)) * 4;
        float* d = &ks[r * (NE + 1) + c];
        d[0] = v.x; d[1] = v.y; d[2] = v.z; d[3] = v.w;
    }
    __syncthreads();

    int l = tid >> 5, tt = tid & 31;
    float s = 0.f;
    const float* qrow = qs + l * NE;
    const float* krow = ks + tt * (NE + 1);
#pragma unroll 8
    for (int e = 0; e < NE; e++) s += qrow[e] * krow[e];
    s *= SCALE;
    float m = s;
#pragma unroll
    for (int o = 16; o > 0; o >>= 1) m = fmaxf(m, __shfl_xor_sync(0xffffffffu, m, o));
    float ex = __expf(s - m), sum = ex;
#pragma unroll
    for (int o = 16; o > 0; o >>= 1) sum += __shfl_xor_sync(0xffffffffu, sum, o);
    aw[l * T + tt] = ex / sum;
    __syncthreads();

    const float4* eb4 = (const float4*)(emb + (long long)(b * NN + n) * T * H);
    float4* mb4 = (float4*)(msg + (long long)(b * NN + n) * RL * H);
#pragma unroll
    for (int it = 0; it < RL * H / 4 / 256; it++) {
        int idx = it * 256 + tid;
        int l2 = idx / (H / 4), h4 = idx - l2 * (H / 4);
        float4 acc = make_float4(0.f, 0.f, 0.f, 0.f);
        const float* awr = aw + l2 * T;
#pragma unroll 8
        for (int t2 = 0; t2 < T; t2++) {
            float wgt = awr[t2];
            float4 e = eb4[t2 * (H / 4) + h4];
            acc.x += wgt * e.x; acc.y += wgt * e.y;
            acc.z += wgt * e.z; acc.w += wgt * e.w;
        }
        mb4[idx] = acc;
    }
}

// ---------------- region gate: per-(branch,b,j) dot products -----------------
__global__ __launch_bounds__(128) void rscore_kernel(
    const float* __restrict__ xs, const float* __restrict__ msg1,
    const float* __restrict__ msg2)
{
    __shared__ float wred[4];
    int id = blockIdx.x;                  // 2 * Bn * 33
    int br = id / (Bn * 33);
    int rem = id - br * (Bn * 33);
    int b = rem / 33, j = rem - b * 33;
    int tid = threadIdx.x;

    const float* src;
    const float* uvec;
    if (j < NN) {
        src = (br ? msg2 : msg1) + (long long)(b * NN + j) * RL * H;
        uvec = g_u + H;
    } else {
        src = xs + ((long long)b * S + (br ? 20 : 1)) * H;
        uvec = g_u;
    }
    const float4* s4 = (const float4*)src;
    float p = 0.f;
#pragma unroll
    for (int it = 0; it < RL * H / 4 / 128; it++) {
        int i = it * 128 + tid;
        float4 v = s4[i];
        const float* up = uvec + (i % (H / 4)) * 4;
        p += v.x * up[0] + v.y * up[1] + v.z * up[2] + v.w * up[3];
    }
#pragma unroll
    for (int o = 16; o > 0; o >>= 1) p += __shfl_xor_sync(0xffffffffu, p, o);
    if ((tid & 31) == 0) wred[tid >> 5] = p;
    __syncthreads();
    if (tid == 0) {
        float tot = (wred[0] + wred[1] + wred[2] + wred[3]) * (1.f / RL);
        if (j < NN) g_md[(br * Bn + b) * NN + j] = tot;
        else        g_feas[br * Bn + b] = tot;
    }
}

// ---------------- region gate softmax: one warp per (branch,b) ---------------
__global__ void rsoftmax_kernel(const float* __restrict__ dist1,
                                const float* __restrict__ dist2,
                                const float* __restrict__ wb,
                                const float* __restrict__ bb)
{
    int br = blockIdx.x >> 5, b = blockIdx.x & 31;
    int lane = threadIdx.x;
    float pre = g_feas[br * Bn + b] + g_md[(br * Bn + b) * NN + lane] + g_u[2 * H];
    float z = pre >= 0.f ? pre : NEG * pre;
    const float* dist = br ? dist2 : dist1;
    float v = z + dist[b * NN + lane] * wb[0] + bb[0];
    float m = v;
#pragma unroll
    for (int o = 16; o > 0; o >>= 1) m = fmaxf(m, __shfl_xor_sync(0xffffffffu, m, o));
    float e = __expf(v - m), s = e;
#pragma unroll
    for (int o = 16; o > 0; o >>= 1) s += __shfl_xor_sync(0xffffffffu, s, o);
    (br ? g_att2 : g_att1)[b * NN + lane] = e / s;
}

// ---------------- x = xs (+ region message aggregation), float4 --------------
__global__ void build_x_kernel(const float* __restrict__ xs)
{
    int idx = blockIdx.x * 256 + threadIdx.x;   // over Bn*S*H/4
    float4 v = ((const float4*)xs)[idx];
    int h4 = idx % (H / 4);
    int s = (idx / (H / 4)) % S;
    int b = idx / (S * H / 4);
    if (s >= 1 && s < 9) {
        int l = s - 1;
        const float4* m4 = (const float4*)g_msg1;
#pragma unroll 4
        for (int n = 0; n < NN; n++) {
            float a = g_att1[b * NN + n];
            float4 m = m4[((b * NN + n) * RL + l) * (H / 4) + h4];
            v.x += a * m.x; v.y += a * m.y; v.z += a * m.z; v.w += a * m.w;
        }
    } else if (s >= 20 && s < 28) {
        int l = s - 20;
        const float4* m4 = (const float4*)g_msg2;
#pragma unroll 4
        for (int n = 0; n < NN; n++) {
            float a = g_att2[b * NN + n];
            float4 m = m4[((b * NN + n) * RL + l) * (H / 4) + h4];
            v.x += a * m.x; v.y += a * m.y; v.z += a * m.z; v.w += a * m.w;
        }
    }
    ((float4*)g_x)[idx] = v;
}

// ---------------- row softmax, one warp per 512-col row ----------------------
__global__ __launch_bounds__(256) void softmax_rows_kernel()
{
    int warp = threadIdx.x >> 5, lane = threadIdx.x & 31;
    long long row = (long long)blockIdx.x * 8 + warp;
    float4* r4 = (float4*)(g_probs + row * S);
    float4 x[4];
    float m = -3.4e38f;
#pragma unroll
    for (int k = 0; k < 4; k++) {
        x[k] = r4[lane + 32 * k];
        m = fmaxf(m, fmaxf(fmaxf(x[k].x, x[k].y), fmaxf(x[k].z, x[k].w)));
    }
#pragma unroll
    for (int o = 16; o > 0; o >>= 1) m = fmaxf(m, __shfl_xor_sync(0xffffffffu, m, o));
    float s = 0.f;
#pragma unroll
    for (int k = 0; k < 4; k++) {
        x[k].x = __expf(x[k].x - m); x[k].y = __expf(x[k].y - m);
        x[k].z = __expf(x[k].z - m); x[k].w = __expf(x[k].w - m);
        s += x[k].x + x[k].y + x[k].z + x[k].w;
    }
#pragma unroll
    for (int o = 16; o > 0; o >>= 1) s += __shfl_xor_sync(0xffffffffu, s, o);
    float inv = 1.f / s;
#pragma unroll
    for (int k = 0; k < 4; k++) {
        x[k].x *= inv; x[k].y *= inv; x[k].z *= inv; x[k].w *= inv;
        r4[lane + 32 * k] = x[k];
    }
}

// ---------------- launch ----------------
extern "C" void kernel_launch(void* const* d_in, const int* in_sizes, int n_in,
                              void* d_out, int out_size)
{
    const float* xs    = (const float*)d_in[0];
    const float* n1emb = (const float*)d_in[1];
    const float* n2emb = (const float*)d_in[2];
    const float* dist1 = (const float*)d_in[3];
    const float* dist2 = (const float*)d_in[4];
    const float* Wq    = (const float*)d_in[5];
    const float* bq    = (const float*)d_in[6];
    const float* Wk    = (const float*)d_in[7];
    const float* bk    = (const float*)d_in[8];
    const float* Wv    = (const float*)d_in[9];
    const float* bv    = (const float*)d_in[10];
    const float* Wa    = (const float*)d_in[11];
    const float* ba    = (const float*)d_in[12];
    const float* Wattn = (const float*)d_in[13];
    const float* battn = (const float*)d_in[14];
    const float* wb    = (const float*)d_in[15];
    const float* bb    = (const float*)d_in[16];
    float* out = (float*)d_out;

    float *px, *pq, *pp, *pkn, *pm1, *pm2, *pqe;
    __nv_bfloat16 *wqth, *wqtl, *wkth, *wktl, *wvth, *wvtl, *pkh, *pkl, *pvh, *pvl;
    cudaGetSymbolAddress((void**)&px,   g_x);
    cudaGetSymbolAddress((void**)&pq,   g_q);
    cudaGetSymbolAddress((void**)&pp,   g_probs);
    cudaGetSymbolAddress((void**)&pkn,  g_kn);
    cudaGetSymbolAddress((void**)&pm1,  g_msg1);
    cudaGetSymbolAddress((void**)&pm2,  g_msg2);
    cudaGetSymbolAddress((void**)&pqe,  g_qe);
    cudaGetSymbolAddress((void**)&wqth, g_WqTh);
    cudaGetSymbolAddress((void**)&wqtl, g_WqTl);
    cudaGetSymbolAddress((void**)&wkth, g_WkTh);
    cudaGetSymbolAddress((void**)&wktl, g_WkTl);
    cudaGetSymbolAddress((void**)&wvth, g_WvTh);
    cudaGetSymbolAddress((void**)&wvtl, g_WvTl);
    cudaGetSymbolAddress((void**)&pkh,  g_kh);
    cudaGetSymbolAddress((void**)&pkl,  g_kl);
    cudaGetSymbolAddress((void**)&pvh,  g_vTh);
    cudaGetSymbolAddress((void**)&pvl,  g_vTl);

    cudaFuncSetAttribute(hgemm<0, false>, cudaFuncAttributeMaxDynamicSharedMemorySize, HG_SMEM);
    cudaFuncSetAttribute(hgemm<1, false>, cudaFuncAttributeMaxDynamicSharedMemorySize, HG_SMEM);
    cudaFuncSetAttribute(hgemm<2, false>, cudaFuncAttributeMaxDynamicSharedMemorySize, HG_SMEM);
    cudaFuncSetAttribute(hgemm<0, true>,  cudaFuncAttributeMaxDynamicSharedMemorySize, HG_SMEM);

    // weight transpose + split (single launch) + gate vectors
    tsplit_all<<<3840, 256>>>(Wq, Wk, Wv);
    u_kernel<<<49, 256>>>(Wa, Wattn, ba, battn);

    // neighbor queries for both branches: one gather GEMM (M=512)
    hgemm<0, true><<<dim3(NE / 128, 4, 1), 256, HG_SMEM>>>(
        xs, wqth, wqtl, bq, pqe, nullptr, nullptr,
        H, H, NE, H, 1.f, 0, 0, 0, 0);

    // branch 1: kn = emb1 @ Wk^T + bk, then fused attn+message
    hgemm<0, false><<<dim3(NE / 128, (Bn * NN * T) / 128, 1), 256, HG_SMEM>>>(
        n1emb, wkth, wktl, bk, pkn, nullptr, nullptr,
        H, H, NE, H, 1.f, 0, 0, 0, 0);
    neigh_kernel<<<Bn * NN, 256>>>(pqe, n1emb, pm1);

    // branch 2 (reuses g_kn)
    hgemm<0, false><<<dim3(NE / 128, (Bn * NN * T) / 128, 1), 256, HG_SMEM>>>(
        n2emb, wkth, wktl, bk, pkn, nullptr, nullptr,
        H, H, NE, H, 1.f, 0, 0, 0, 0);
    neigh_kernel<<<Bn * NN, 256>>>(pqe + 256 * NE, n2emb, pm2);

    // gate attention + x update
    rscore_kernel<<<2 * Bn * 33, 128>>>(xs, pm1, pm2);
    rsoftmax_kernel<<<2 * Bn, 32>>>(dist1, dist2, wb, bb);
    build_x_kernel<<<(Bn * S * H / 4) / 256, 256>>>(xs);

    // q = x @ Wq^T + bq (fp32, A-operand of QK)
    hgemm<0, false><<<dim3(NE / 128, (Bn * S) / 128, 1), 256, HG_SMEM>>>(
        px, wqth, wqtl, bq, pq, nullptr, nullptr,
        H, H, NE, H, 1.f, 0, 0, 0, 0);
    // k = x @ Wk^T + bk (bf16 hi/lo, B-operand of QK)
    hgemm<1, false><<<dim3(NE / 128, (Bn * S) / 128, 1), 256, HG_SMEM>>>(
        px, wkth, wktl, bk, nullptr, pkh, pkl,
        H, H, NE, H, 1.f, 0, 0, 0, 0);
    // v = x @ Wv^T + bv (bf16 hi/lo TRANSPOSED per batch, B-operand of PV)
    hgemm<2, false><<<dim3(H / 128, (Bn * S) / 128, 1), 256, HG_SMEM>>>(
        px, wvth, wvtl, bv, nullptr, pvh, pvl,
        H, H, 0, H, 1.f, 0, 0, 0, H);

    // scores = SCALE * q @ k^T (batched)
    hgemm<0, false><<<dim3(S / 128, S / 128, Bn), 256, HG_SMEM>>>(
        pq, pkh, pkl, nullptr, pp, nullptr, nullptr,
        NE, NE, S, NE, SCALE,
        (long long)S * NE, (long long)S * NE, (long long)S * S, 0);

    softmax_rows_kernel<<<Bn * S / 8, 256>>>();

    // out = probs @ v (batched; B = v^T hi/lo)
    hgemm<0, false><<<dim3(H / 128, S / 128, Bn), 256, HG_SMEM>>>(
        pp, pvh, pvl, nullptr, out, nullptr, nullptr,
        S, S, H, S, 1.f,
        (long long)S * S, (long long)H * S, (long long)S * H, 0);
}

// round 6
// speedup vs baseline: 2.6160x; 1.0221x over previous
#include <cuda_runtime.h>
#include <cuda_bf16.h>
#include <cstdint>

// ---------------- problem constants ----------------
namespace {
constexpr int Bn = 32;    // batch
constexpr int S  = 512;   // sequence
constexpr int H  = 768;   // hidden
constexpr int NN = 32;    // neighbors
constexpr int T  = 32;    // tokens per neighbor
constexpr int NE = 256;   // q/k embed
constexpr int AE = 128;   // attn embed
constexpr int RL = 8;     // region length
constexpr float SCALE = 0.0625f;
constexpr float NEG   = 0.01f;
constexpr int EMB_ELTS = Bn * NN * T * H;   // 25165824
}

// ---------------- scratch (device globals; no allocation) ----------------
__device__ float g_probs[Bn * S * S];
__device__ float g_kn   [2 * Bn * NN * T * NE];
__device__ float g_msg1 [Bn * NN * RL * H];
__device__ float g_msg2 [Bn * NN * RL * H];
__device__ float g_qe   [2 * Bn * RL * NE];
__device__ float g_att1 [Bn * NN];
__device__ float g_att2 [Bn * NN];
__device__ float g_u    [2 * H + 1];
__device__ float g_md   [2 * Bn * NN];
__device__ float g_feas [2 * Bn];
__device__ float g_bias [1280];

__device__ __nv_bfloat16 g_Wh [1280 * H], g_Wl [1280 * H];     // stacked WqT|WkT|WvT
__device__ __nv_bfloat16 g_eh [2 * EMB_ELTS], g_el [2 * EMB_ELTS];
__device__ __nv_bfloat16 g_xh [Bn * S * H], g_xl [Bn * S * H];
__device__ __nv_bfloat16 g_qkh[Bn * S * 512], g_qkl[Bn * S * 512]; // q cols 0-255, k 256-511
__device__ __nv_bfloat16 g_vTh[Bn * H * S], g_vTl[Bn * H * S];
__device__ __nv_bfloat16 g_ph [Bn * S * S], g_pl [Bn * S * S];
__device__ __nv_bfloat16 g_qAh[512 * H],   g_qAl[512 * H];

// ---------------- helpers ----------------
__device__ __forceinline__ uint32_t smem_u32(const void* p) {
    uint32_t a;
    asm("{ .reg .u64 t; cvta.to.shared.u64 t, %1; cvt.u32.u64 %0, t; }" : "=r"(a) : "l"(p));
    return a;
}
__device__ __forceinline__ uint32_t bpack(__nv_bfloat16 a, __nv_bfloat16 b) {
    __nv_bfloat162 t = __halves2bfloat162(a, b);
    return *reinterpret_cast<uint32_t*>(&t);
}
__device__ __forceinline__ uint32_t fpack(float a, float b) {
    __nv_bfloat162 t = __floats2bfloat162_rn(a, b);
    return *reinterpret_cast<uint32_t*>(&t);
}
__device__ __forceinline__ void split4(float4 v, uint2& hv, uint2& lv) {
    __nv_bfloat16 h0 = __float2bfloat16(v.x), h1 = __float2bfloat16(v.y);
    __nv_bfloat16 h2 = __float2bfloat16(v.z), h3 = __float2bfloat16(v.w);
    hv.x = bpack(h0, h1); hv.y = bpack(h2, h3);
    lv.x = fpack(v.x - __bfloat162float(h0), v.y - __bfloat162float(h1));
    lv.y = fpack(v.z - __bfloat162float(h2), v.w - __bfloat162float(h3));
}
__device__ __forceinline__ void ldsm4(uint32_t& r0, uint32_t& r1, uint32_t& r2,
                                      uint32_t& r3, uint32_t a) {
    asm volatile("ldmatrix.sync.aligned.m8n8.x4.shared.b16 {%0,%1,%2,%3}, [%4];"
                 : "=r"(r0), "=r"(r1), "=r"(r2), "=r"(r3) : "r"(a));
}
__device__ __forceinline__ void mma16816(float* d, const uint32_t* a, const uint32_t* b) {
    asm volatile(
        "mma.sync.aligned.m16n8k16.row.col.f32.bf16.bf16.f32 "
        "{%0,%1,%2,%3}, {%4,%5,%6,%7}, {%8,%9}, {%0,%1,%2,%3};"
        : "+f"(d[0]), "+f"(d[1]), "+f"(d[2]), "+f"(d[3])
        : "r"(a[0]), "r"(a[1]), "r"(a[2]), "r"(a[3]), "r"(b[0]), "r"(b[1]));
}

// ================= all-bf16 cp.async-pipelined bf16x3 GEMM =================
// D[m,n] = sum_k A[m,k]*B[n,k] (+bias), all operands bf16 hi/lo in global, K-major.
// Block tile 128x128, BK=32, 8 warps (2x4), warp tile 64x32, 4-stage cp.async.
// EPI: 0 = fp32 out (alpha*acc + bias?), 3 = fused qkv routing:
//      n<512 -> bf16 pairs into Ch/Cl (ld 512); n>=512 -> transposed pairs into Dh/Dl.
constexpr int ROWB  = 80;
constexpr int MTILE = 128 * ROWB;     // 10240
constexpr int STAGEB = 4 * MTILE;     // 40960
constexpr int BG_SMEM = 4 * STAGEB;   // 163840

template<int EPI>
__global__ __launch_bounds__(256, 1) void bgemm(
    const __nv_bfloat16* __restrict__ Ahp, const __nv_bfloat16* __restrict__ Alp,
    const __nv_bfloat16* __restrict__ Bhp, const __nv_bfloat16* __restrict__ Blp,
    const float* __restrict__ bias, float* __restrict__ Cf,
    __nv_bfloat16* __restrict__ Ch, __nv_bfloat16* __restrict__ Cl,
    __nv_bfloat16* __restrict__ Dh, __nv_bfloat16* __restrict__ Dl,
    int lda, int ldb, int ldc, int K, float alpha,
    long long sA, long long sB, long long sC)
{
    extern __shared__ char smem[];
    const uint32_t sb = smem_u32(smem);
    const int tid = threadIdx.x, w = tid >> 5, lane = tid & 31;
    const int m0 = blockIdx.y * 128, n0 = blockIdx.x * 128, bz = blockIdx.z;
    Ahp += bz * sA; Alp += bz * sA;
    Bhp += bz * sB; Blp += bz * sB;
    if (EPI == 0) Cf += bz * sC;

    const int wm = (w >> 2) * 64, wn = (w & 3) * 32;
    float acc[4][4][4];
#pragma unroll
    for (int a = 0; a < 4; a++)
#pragma unroll
        for (int b = 0; b < 4; b++)
#pragma unroll
            for (int c = 0; c < 4; c++) acc[a][b][c] = 0.f;

    auto issue = [&](int c) {
        const int k0 = c << 5;
        const uint32_t dstb = sb + (c & 3) * STAGEB;
#pragma unroll
        for (int mat = 0; mat < 4; mat++) {
            const __nv_bfloat16* g = (mat == 0) ? Ahp : (mat == 1) ? Alp
                                   : (mat == 2) ? Bhp : Blp;
            const int rb = (mat < 2) ? m0 : n0;
            const int ld = (mat < 2) ? lda : ldb;
#pragma unroll
            for (int it = 0; it < 2; it++) {
                int i2 = (it << 8) + tid, row = i2 >> 2, c16 = i2 & 3;
                const __nv_bfloat16* src = g + (long long)(rb + row) * ld + k0 + (c16 << 3);
                uint32_t dst = dstb + mat * MTILE + row * ROWB + (c16 << 4);
                asm volatile("cp.async.cg.shared.global [%0], [%1], 16;"
                             :: "r"(dst), "l"(src));
            }
        }
        asm volatile("cp.async.commit_group;");
    };

    const int q = lane >> 3, r = lane & 7;
    const int aRow = ((q & 1) << 3) + r;
    const int aCol = (q >> 1) << 4;
    const int bRow = ((q >> 1) << 3) + r;
    const int bCol = (q & 1) << 4;

    auto compute = [&](int c) {
        const uint32_t Ah = sb + (c & 3) * STAGEB;
        const uint32_t Al = Ah + MTILE, Bh = Ah + 2 * MTILE, Bl = Ah + 3 * MTILE;
#pragma unroll
        for (int s = 0; s < 2; s++) {
            const int kOff = s * 32;
            uint32_t ah[4][4], al[4][4];
#pragma unroll
            for (int mt = 0; mt < 4; mt++) {
                uint32_t off = (uint32_t)(wm + mt * 16 + aRow) * ROWB + kOff + aCol;
                ldsm4(ah[mt][0], ah[mt][1], ah[mt][2], ah[mt][3], Ah + off);
                ldsm4(al[mt][0], al[mt][1], al[mt][2], al[mt][3], Al + off);
            }
            uint32_t bh[4][2], bl[4][2];
#pragma unroll
            for (int np = 0; np < 2; np++) {
                uint32_t off = (uint32_t)(wn + np * 16 + bRow) * ROWB + kOff + bCol;
                ldsm4(bh[2 * np][0], bh[2 * np][1], bh[2 * np + 1][0], bh[2 * np + 1][1],
                      Bh + off);
                ldsm4(bl[2 * np][0], bl[2 * np][1], bl[2 * np + 1][0], bl[2 * np + 1][1],
                      Bl + off);
            }
#pragma unroll
            for (int mt = 0; mt < 4; mt++)
#pragma unroll
                for (int nt = 0; nt < 4; nt++) {
                    mma16816(acc[mt][nt], ah[mt], bh[nt]);
                    mma16816(acc[mt][nt], ah[mt], bl[nt]);
                    mma16816(acc[mt][nt], al[mt], bh[nt]);
                }
        }
    };

    const int nch = K >> 5;
#pragma unroll
    for (int s = 0; s < 3; s++) {
        if (s < nch) issue(s);
        else asm volatile("cp.async.commit_group;");
    }
    for (int c = 0; c < nch; c++) {
        asm volatile("cp.async.wait_group 2;");
        __syncthreads();
        compute(c);
        if (c + 3 < nch) issue(c + 3);
        else asm volatile("cp.async.commit_group;");
    }

    // epilogue
    const int gid = lane >> 2, tig = lane & 3;
#pragma unroll
    for (int mt = 0; mt < 4; mt++)
#pragma unroll
        for (int half = 0; half < 2; half++) {
            const long long m = m0 + wm + mt * 16 + gid + half * 8;
#pragma unroll
            for (int nt = 0; nt < 4; nt++) {
                float v0 = acc[mt][nt][half * 2 + 0];
                float v1 = acc[mt][nt][half * 2 + 1];
                const int n = n0 + wn + nt * 8 + tig * 2;
                if (EPI == 0) {
                    v0 *= alpha; v1 *= alpha;
                    if (bias) { v0 += bias[n]; v1 += bias[n + 1]; }
                    *(float2*)&Cf[m * ldc + n] = make_float2(v0, v1);
                } else {  // EPI == 3
                    v0 += bias[n]; v1 += bias[n + 1];
                    if (n0 < 512) {
                        __nv_bfloat16 h0 = __float2bfloat16(v0), h1 = __float2bfloat16(v1);
                        *(uint32_t*)&Ch[m * 512 + n] = bpack(h0, h1);
                        *(uint32_t*)&Cl[m * 512 + n] =
                            fpack(v0 - __bfloat162float(h0), v1 - __bfloat162float(h1));
                    } else {
                        const int nv = n - 512;
                        const long long b = m >> 9, t = m & 511;
                        __nv_bfloat16 h0 = __float2bfloat16(v0), h1 = __float2bfloat16(v1);
                        Dh[(b * 768 + nv) * 512 + t] = h0;
                        Dl[(b * 768 + nv) * 512 + t] = __float2bfloat16(v0 - __bfloat162float(h0));
                        Dh[(b * 768 + nv + 1) * 512 + t] = h1;
                        Dl[(b * 768 + nv + 1) * 512 + t] = __float2bfloat16(v1 - __bfloat162float(h1));
                    }
                }
            }
        }
}

// ---------------- stacked weight transpose+split + bias stack ---------------
__global__ void tsplit_all(const float* __restrict__ Wq, const float* __restrict__ Wk,
                           const float* __restrict__ Wv, const float* __restrict__ bq,
                           const float* __restrict__ bk, const float* __restrict__ bv)
{
    int idx = blockIdx.x * 256 + threadIdx.x;
    if (idx < 1280 * H) {
        int n = idx / H, k = idx - n * H;
        float x = (n < 256) ? Wq[(long long)k * NE + n]
                : (n < 512) ? Wk[(long long)k * NE + (n - 256)]
                            : Wv[(long long)k * H + (n - 512)];
        __nv_bfloat16 h = __float2bfloat16(x);
        g_Wh[idx] = h;
        g_Wl[idx] = __float2bfloat16(x - __bfloat162float(h));
    } else if (idx < 1280 * H + 1280) {
        int j = idx - 1280 * H;
        g_bias[j] = (j < 256) ? bq[j] : (j < 512) ? bk[j - 256] : bv[j - 512];
    }
}

// ---------------- split both neighbor embeddings to bf16 pairs ---------------
__global__ void semb_kernel(const float* __restrict__ e1, const float* __restrict__ e2)
{
    long long idx = (long long)blockIdx.x * 256 + threadIdx.x;   // float4 units
    const long long half = EMB_ELTS / 4;
    const float4* src = (idx < half) ? (const float4*)e1 : (const float4*)e2;
    long long local = (idx < half) ? idx : idx - half;
    float4 v = src[local];
    uint2 hv, lv; split4(v, hv, lv);
    ((uint2*)g_eh)[idx] = hv;
    ((uint2*)g_el)[idx] = lv;
}

// ---------------- gather + split region rows for qe GEMM --------------------
__global__ void sgat_kernel(const float* __restrict__ xs)
{
    int idx = blockIdx.x * 256 + threadIdx.x;   // 512*192
    int m = idx / (H / 4), r4 = idx - m * (H / 4);
    int br = m >> 8, b = (m >> 3) & 31, l = m & 7;
    float4 v = ((const float4*)(xs + ((long long)b * S + (br ? 20 : 1) + l) * H))[r4];
    uint2 hv, lv; split4(v, hv, lv);
    ((uint2*)g_qAh)[idx] = hv;
    ((uint2*)g_qAl)[idx] = lv;
}

// ---------------- u = Wa @ Wattn halves (8 threads/output); cbase ------------
__global__ void u_kernel(const float* __restrict__ Wa, const float* __restrict__ Wattn,
                         const float* __restrict__ ba, const float* __restrict__ battn)
{
    if (blockIdx.x < 48) {
        int gt = blockIdx.x * 256 + threadIdx.x;
        int g = gt >> 3, sub = gt & 7;
        int j = g / H, h = g - j * H;
        float acc = 0.f;
#pragma unroll 4
        for (int a = sub; a < AE; a += 8) acc += Wa[h * AE + a] * Wattn[j * AE + a];
        acc += __shfl_down_sync(0xffffffffu, acc, 4, 8);
        acc += __shfl_down_sync(0xffffffffu, acc, 2, 8);
        acc += __shfl_down_sync(0xffffffffu, acc, 1, 8);
        if (sub == 0) g_u[g] = acc;
    } else {
        __shared__ float red[256];
        int tid = threadIdx.x;
        float v = 0.f;
        if (tid < AE) v = ba[tid] * (Wattn[tid] + Wattn[AE + tid]);
        red[tid] = v; __syncthreads();
        for (int s2 = 128; s2 > 0; s2 >>= 1) {
            if (tid < s2) red[tid] += red[tid + s2];
            __syncthreads();
        }
        if (tid == 0) g_u[2 * H] = red[0] + battn[0];
    }
}

// ---------------- per-(b,n): scores -> softmax over T -> message -------------
__global__ __launch_bounds__(256) void neigh_kernel(
    const float* __restrict__ qe, const float* __restrict__ kn,
    const float* __restrict__ emb, float* __restrict__ msg)
{
    __shared__ float qs[RL * NE];
    __shared__ float ks[T * (NE + 1)];
    __shared__ float aw[RL * T];
    int b = blockIdx.x / NN, n = blockIdx.x % NN;
    int tid = threadIdx.x;

    const float4* qb4 = (const float4*)(qe + (long long)b * RL * NE);
    for (int i = tid; i < RL * NE / 4; i += 256)
        *(float4*)&qs[i * 4] = qb4[i];
    const float4* kb4 = (const float4*)(kn + (long long)(b * NN + n) * T * NE);
    for (int i = tid; i < T * NE / 4; i += 256) {
        float4 v = kb4[i];
        int r = i / (NE / 4), c = (i - r * (NE / 4)) * 4;
        float* d = &ks[r * (NE + 1) + c];
        d[0] = v.x; d[1] = v.y; d[2] = v.z; d[3] = v.w;
    }
    __syncthreads();

    int l = tid >> 5, tt = tid & 31;
    float s = 0.f;
    const float* qrow = qs + l * NE;
    const float* krow = ks + tt * (NE + 1);
#pragma unroll 8
    for (int e = 0; e < NE; e++) s += qrow[e] * krow[e];
    s *= SCALE;
    float m = s;
#pragma unroll
    for (int o = 16; o > 0; o >>= 1) m = fmaxf(m, __shfl_xor_sync(0xffffffffu, m, o));
    float ex = __expf(s - m), sum = ex;
#pragma unroll
    for (int o = 16; o > 0; o >>= 1) sum += __shfl_xor_sync(0xffffffffu, sum, o);
    aw[l * T + tt] = ex / sum;
    __syncthreads();

    const float4* eb4 = (const float4*)(emb + (long long)(b * NN + n) * T * H);
    float4* mb4 = (float4*)(msg + (long long)(b * NN + n) * RL * H);
#pragma unroll
    for (int it = 0; it < RL * H / 4 / 256; it++) {
        int idx = it * 256 + tid;
        int l2 = idx / (H / 4), h4 = idx - l2 * (H / 4);
        float4 acc = make_float4(0.f, 0.f, 0.f, 0.f);
        const float* awr = aw + l2 * T;
#pragma unroll 8
        for (int t2 = 0; t2 < T; t2++) {
            float wgt = awr[t2];
            float4 e = eb4[t2 * (H / 4) + h4];
            acc.x += wgt * e.x; acc.y += wgt * e.y;
            acc.z += wgt * e.z; acc.w += wgt * e.w;
        }
        mb4[idx] = acc;
    }
}

// ---------------- region gate: per-(branch,b,j) dot products -----------------
__global__ __launch_bounds__(128) void rscore_kernel(
    const float* __restrict__ xs, const float* __restrict__ msg1,
    const float* __restrict__ msg2)
{
    __shared__ float wred[4];
    int id = blockIdx.x;                  // 2 * Bn * 33
    int br = id / (Bn * 33);
    int rem = id - br * (Bn * 33);
    int b = rem / 33, j = rem - b * 33;
    int tid = threadIdx.x;

    const float* src;
    const float* uvec;
    if (j < NN) {
        src = (br ? msg2 : msg1) + (long long)(b * NN + j) * RL * H;
        uvec = g_u + H;
    } else {
        src = xs + ((long long)b * S + (br ? 20 : 1)) * H;
        uvec = g_u;
    }
    const float4* s4 = (const float4*)src;
    float p = 0.f;
#pragma unroll
    for (int it = 0; it < RL * H / 4 / 128; it++) {
        int i = it * 128 + tid;
        float4 v = s4[i];
        const float* up = uvec + (i % (H / 4)) * 4;
        p += v.x * up[0] + v.y * up[1] + v.z * up[2] + v.w * up[3];
    }
#pragma unroll
    for (int o = 16; o > 0; o >>= 1) p += __shfl_xor_sync(0xffffffffu, p, o);
    if ((tid & 31) == 0) wred[tid >> 5] = p;
    __syncthreads();
    if (tid == 0) {
        float tot = (wred[0] + wred[1] + wred[2] + wred[3]) * (1.f / RL);
        if (j < NN) g_md[(br * Bn + b) * NN + j] = tot;
        else        g_feas[br * Bn + b] = tot;
    }
}

// ---------------- region gate softmax: one warp per (branch,b) ---------------
__global__ void rsoftmax_kernel(const float* __restrict__ dist1,
                                const float* __restrict__ dist2,
                                const float* __restrict__ wb,
                                const float* __restrict__ bb)
{
    int br = blockIdx.x >> 5, b = blockIdx.x & 31;
    int lane = threadIdx.x;
    float pre = g_feas[br * Bn + b] + g_md[(br * Bn + b) * NN + lane] + g_u[2 * H];
    float z = pre >= 0.f ? pre : NEG * pre;
    const float* dist = br ? dist2 : dist1;
    float v = z + dist[b * NN + lane] * wb[0] + bb[0];
    float m = v;
#pragma unroll
    for (int o = 16; o > 0; o >>= 1) m = fmaxf(m, __shfl_xor_sync(0xffffffffu, m, o));
    float e = __expf(v - m), s = e;
#pragma unroll
    for (int o = 16; o > 0; o >>= 1) s += __shfl_xor_sync(0xffffffffu, s, o);
    (br ? g_att2 : g_att1)[b * NN + lane] = e / s;
}

// ---------------- x = xs (+ gated messages) -> bf16 hi/lo pairs --------------
__global__ void build_x_kernel(const float* __restrict__ xs)
{
    int idx = blockIdx.x * 256 + threadIdx.x;   // over Bn*S*H/4
    float4 v = ((const float4*)xs)[idx];
    int h4 = idx % (H / 4);
    int s = (idx / (H / 4)) % S;
    int b = idx / (S * H / 4);
    if (s >= 1 && s < 9) {
        int l = s - 1;
        const float4* m4 = (const float4*)g_msg1;
#pragma unroll 4
        for (int n = 0; n < NN; n++) {
            float a = g_att1[b * NN + n];
            float4 m = m4[((b * NN + n) * RL + l) * (H / 4) + h4];
            v.x += a * m.x; v.y += a * m.y; v.z += a * m.z; v.w += a * m.w;
        }
    } else if (s >= 20 && s < 28) {
        int l = s - 20;
        const float4* m4 = (const float4*)g_msg2;
#pragma unroll 4
        for (int n = 0; n < NN; n++) {
            float a = g_att2[b * NN + n];
            float4 m = m4[((b * NN + n) * RL + l) * (H / 4) + h4];
            v.x += a * m.x; v.y += a * m.y; v.z += a * m.z; v.w += a * m.w;
        }
    }
    uint2 hv, lv; split4(v, hv, lv);
    ((uint2*)g_xh)[idx] = hv;
    ((uint2*)g_xl)[idx] = lv;
}

// ---------------- row softmax (warp/row) -> bf16 hi/lo pairs -----------------
__global__ __launch_bounds__(256) void softmax_rows_kernel()
{
    int warp = threadIdx.x >> 5, lane = threadIdx.x & 31;
    long long row = (long long)blockIdx.x * 8 + warp;
    const float4* r4 = (const float4*)(g_probs + row * S);
    float4 x[4];
    float m = -3.4e38f;
#pragma unroll
    for (int k = 0; k < 4; k++) {
        x[k] = r4[lane + 32 * k];
        m = fmaxf(m, fmaxf(fmaxf(x[k].x, x[k].y), fmaxf(x[k].z, x[k].w)));
    }
#pragma unroll
    for (int o = 16; o > 0; o >>= 1) m = fmaxf(m, __shfl_xor_sync(0xffffffffu, m, o));
    float s = 0.f;
#pragma unroll
    for (int k = 0; k < 4; k++) {
        x[k].x = __expf(x[k].x - m); x[k].y = __expf(x[k].y - m);
        x[k].z = __expf(x[k].z - m); x[k].w = __expf(x[k].w - m);
        s += x[k].x + x[k].y + x[k].z + x[k].w;
    }
#pragma unroll
    for (int o = 16; o > 0; o >>= 1) s += __shfl_xor_sync(0xffffffffu, s, o);
    float inv = 1.f / s;
    uint2* ph4 = (uint2*)(g_ph + row * S);
    uint2* pl4 = (uint2*)(g_pl + row * S);
#pragma unroll
    for (int k = 0; k < 4; k++) {
        x[k].x *= inv; x[k].y *= inv; x[k].z *= inv; x[k].w *= inv;
        uint2 hv, lv; split4(x[k], hv, lv);
        ph4[lane + 32 * k] = hv;
        pl4[lane + 32 * k] = lv;
    }
}

// ---------------- launch ----------------
extern "C" void kernel_launch(void* const* d_in, const int* in_sizes, int n_in,
                              void* d_out, int out_size)
{
    const float* xs    = (const float*)d_in[0];
    const float* n1emb = (const float*)d_in[1];
    const float* n2emb = (const float*)d_in[2];
    const float* dist1 = (const float*)d_in[3];
    const float* dist2 = (const float*)d_in[4];
    const float* Wq    = (const float*)d_in[5];
    const float* bq    = (const float*)d_in[6];
    const float* Wk    = (const float*)d_in[7];
    const float* bk    = (const float*)d_in[8];
    const float* Wv    = (const float*)d_in[9];
    const float* bv    = (const float*)d_in[10];
    const float* Wa    = (const float*)d_in[11];
    const float* ba    = (const float*)d_in[12];
    const float* Wattn = (const float*)d_in[13];
    const float* battn = (const float*)d_in[14];
    const float* wb    = (const float*)d_in[15];
    const float* bb    = (const float*)d_in[16];
    float* out = (float*)d_out;

    float *pp, *pkn, *pm1, *pm2, *pqe, *pbias;
    __nv_bfloat16 *pwh, *pwl, *peh, *pel, *pxh, *pxl, *pqkh, *pqkl,
                  *pvh, *pvl, *pph, *ppl, *pah, *pal;
    cudaGetSymbolAddress((void**)&pp,   g_probs);
    cudaGetSymbolAddress((void**)&pkn,  g_kn);
    cudaGetSymbolAddress((void**)&pm1,  g_msg1);
    cudaGetSymbolAddress((void**)&pm2,  g_msg2);
    cudaGetSymbolAddress((void**)&pqe,  g_qe);
    cudaGetSymbolAddress((void**)&pbias,g_bias);
    cudaGetSymbolAddress((void**)&pwh,  g_Wh);
    cudaGetSymbolAddress((void**)&pwl,  g_Wl);
    cudaGetSymbolAddress((void**)&peh,  g_eh);
    cudaGetSymbolAddress((void**)&pel,  g_el);
    cudaGetSymbolAddress((void**)&pxh,  g_xh);
    cudaGetSymbolAddress((void**)&pxl,  g_xl);
    cudaGetSymbolAddress((void**)&pqkh, g_qkh);
    cudaGetSymbolAddress((void**)&pqkl, g_qkl);
    cudaGetSymbolAddress((void**)&pvh,  g_vTh);
    cudaGetSymbolAddress((void**)&pvl,  g_vTl);
    cudaGetSymbolAddress((void**)&pph,  g_ph);
    cudaGetSymbolAddress((void**)&ppl,  g_pl);
    cudaGetSymbolAddress((void**)&pah,  g_qAh);
    cudaGetSymbolAddress((void**)&pal,  g_qAl);

    cudaFuncSetAttribute(bgemm<0>, cudaFuncAttributeMaxDynamicSharedMemorySize, BG_SMEM);
    cudaFuncSetAttribute(bgemm<3>, cudaFuncAttributeMaxDynamicSharedMemorySize, BG_SMEM);

    // prep: weights/bias stack, gate vectors, emb splits, qe gather-split
    tsplit_all<<<(1280 * H + 1280 + 255) / 256, 256>>>(Wq, Wk, Wv, bq, bk, bv);
    u_kernel<<<49, 256>>>(Wa, Wattn, ba, battn);
    semb_kernel<<<(2 * EMB_ELTS / 4) / 256, 256>>>(n1emb, n2emb);
    sgat_kernel<<<512 * (H / 4) / 256, 256>>>(xs);

    // qe = gathered regions @ Wq^T + bq (fp32)
    bgemm<0><<<dim3(2, 4, 1), 256, BG_SMEM>>>(
        pah, pal, pwh, pwl, pbias, pqe, nullptr, nullptr, nullptr, nullptr,
        H, H, NE, H, 1.f, 0, 0, 0);

    // kn (both branches) = emb @ Wk^T + bk (fp32)
    bgemm<0><<<dim3(2, 256, 2), 256, BG_SMEM>>>(
        peh, pel, pwh + 256 * H, pwl + 256 * H, pbias + 256, pkn,
        nullptr, nullptr, nullptr, nullptr,
        H, H, NE, H, 1.f, (long long)EMB_ELTS, 0, (long long)Bn * NN * T * NE);

    // neighbor attention + messages
    neigh_kernel<<<Bn * NN, 256>>>(pqe, pkn, n1emb, pm1);
    neigh_kernel<<<Bn * NN, 256>>>(pqe + 256 * NE, pkn + Bn * NN * T * NE, n2emb, pm2);

    // gate attention + x pairs
    rscore_kernel<<<2 * Bn * 33, 128>>>(xs, pm1, pm2);
    rsoftmax_kernel<<<2 * Bn, 32>>>(dist1, dist2, wb, bb);
    build_x_kernel<<<(Bn * S * H / 4) / 256, 256>>>(xs);

    // fused q/k/v projections: N = 1280 (q 0-255, k 256-511, v 512-1279)
    bgemm<3><<<dim3(10, 128, 1), 256, BG_SMEM>>>(
        pxh, pxl, pwh, pwl, pbias, nullptr, pqkh, pqkl, pvh, pvl,
        H, H, 512, H, 1.f, 0, 0, 0);

    // scores = SCALE * q @ k^T (batched; A = qk cols 0-255, B = qk cols 256-511)
    bgemm<0><<<dim3(4, 4, 32), 256, BG_SMEM>>>(
        pqkh, pqkl, pqkh + 256, pqkl + 256, nullptr, pp,
        nullptr, nullptr, nullptr, nullptr,
        512, 512, S, NE, SCALE,
        (long long)S * 512, (long long)S * 512, (long long)S * S);

    softmax_rows_kernel<<<Bn * S / 8, 256>>>();

    // out = probs @ v (batched; A = prob pairs, B = vT pairs)
    bgemm<0><<<dim3(6, 4, 32), 256, BG_SMEM>>>(
        pph, ppl, pvh, pvl, nullptr, out, nullptr, nullptr, nullptr, nullptr,
        512, 512, H, S, 1.f,
        (long long)S * S, (long long)H * S, (long long)S * H);
}

// round 7
// speedup vs baseline: 3.0109x; 1.1509x over previous
#include <cuda_runtime.h>
#include <cuda_bf16.h>
#include <cstdint>

// ---------------- problem constants ----------------
namespace {
constexpr int Bn = 32;
constexpr int S  = 512;
constexpr int H  = 768;
constexpr int NN = 32;
constexpr int T  = 32;
constexpr int NE = 256;
constexpr int AE = 128;
constexpr int RL = 8;
constexpr float SCALE = 0.0625f;
constexpr float NEG   = 0.01f;
}

// ---------------- scratch ----------------
__device__ float g_probs[Bn * S * S];
__device__ float g_msg1 [Bn * NN * RL * H];
__device__ float g_msg2 [Bn * NN * RL * H];
__device__ float g_qe   [2 * Bn * RL * NE];
__device__ float g_z    [2 * Bn * RL * H];
__device__ float g_c    [2 * Bn * RL];
__device__ float g_att1 [Bn * NN];
__device__ float g_att2 [Bn * NN];
__device__ float g_u    [2 * H + 1];
__device__ float g_md   [2 * Bn * NN];
__device__ float g_feas [2 * Bn];
__device__ float g_bias [1280];

__device__ __nv_bfloat16 g_Wh  [1280 * H], g_Wl  [1280 * H];  // stacked WqT|WkT|WvT
__device__ __nv_bfloat16 g_WkNh[H * NE],   g_WkNl[H * NE];    // Wk original layout
__device__ __nv_bfloat16 g_qeh [512 * NE], g_qel [512 * NE];
__device__ __nv_bfloat16 g_xh  [Bn * S * H], g_xl [Bn * S * H];
__device__ __nv_bfloat16 g_qkh [Bn * S * 512], g_qkl[Bn * S * 512];
__device__ __nv_bfloat16 g_vTh [Bn * H * S], g_vTl[Bn * H * S];
__device__ __nv_bfloat16 g_ph  [Bn * S * S], g_pl [Bn * S * S];
__device__ __nv_bfloat16 g_qAh [512 * H],   g_qAl [512 * H];

// ---------------- helpers ----------------
__device__ __forceinline__ uint32_t smem_u32(const void* p) {
    uint32_t a;
    asm("{ .reg .u64 t; cvta.to.shared.u64 t, %1; cvt.u32.u64 %0, t; }" : "=r"(a) : "l"(p));
    return a;
}
__device__ __forceinline__ uint32_t bpack(__nv_bfloat16 a, __nv_bfloat16 b) {
    __nv_bfloat162 t = __halves2bfloat162(a, b);
    return *reinterpret_cast<uint32_t*>(&t);
}
__device__ __forceinline__ uint32_t fpack(float a, float b) {
    __nv_bfloat162 t = __floats2bfloat162_rn(a, b);
    return *reinterpret_cast<uint32_t*>(&t);
}
__device__ __forceinline__ void split4(float4 v, uint2& hv, uint2& lv) {
    __nv_bfloat16 h0 = __float2bfloat16(v.x), h1 = __float2bfloat16(v.y);
    __nv_bfloat16 h2 = __float2bfloat16(v.z), h3 = __float2bfloat16(v.w);
    hv.x = bpack(h0, h1); hv.y = bpack(h2, h3);
    lv.x = fpack(v.x - __bfloat162float(h0), v.y - __bfloat162float(h1));
    lv.y = fpack(v.z - __bfloat162float(h2), v.w - __bfloat162float(h3));
}
__device__ __forceinline__ void ldsm4(uint32_t& r0, uint32_t& r1, uint32_t& r2,
                                      uint32_t& r3, uint32_t a) {
    asm volatile("ldmatrix.sync.aligned.m8n8.x4.shared.b16 {%0,%1,%2,%3}, [%4];"
                 : "=r"(r0), "=r"(r1), "=r"(r2), "=r"(r3) : "r"(a));
}
__device__ __forceinline__ void mma16816(float* d, const uint32_t* a, const uint32_t* b) {
    asm volatile(
        "mma.sync.aligned.m16n8k16.row.col.f32.bf16.bf16.f32 "
        "{%0,%1,%2,%3}, {%4,%5,%6,%7}, {%8,%9}, {%0,%1,%2,%3};"
        : "+f"(d[0]), "+f"(d[1]), "+f"(d[2]), "+f"(d[3])
        : "r"(a[0]), "r"(a[1]), "r"(a[2]), "r"(a[3]), "r"(b[0]), "r"(b[1]));
}

// ================= all-bf16 cp.async bf16x3 GEMM, CTA 128x256 =================
// 8 warps (2x4), warp tile 64x64, BK=32, 3-stage pipeline.
// EPI: 0 = fp32 out (alpha*acc + bias?)
//      3 = qkv routing: n<512 -> bf16 pairs Ch/Cl (ld 512); n>=512 -> transposed Dh/Dl
//      4 = fp32 out + bf16 pairs (same ldc)
constexpr int ROWB = 80;
constexpr int ASZ  = 128 * ROWB;     // 10240
constexpr int BSZ  = 256 * ROWB;     // 20480
constexpr int STG  = 2 * ASZ + 2 * BSZ;   // 61440
constexpr int BG_SMEM = 3 * STG;     // 184320

template<int EPI>
__global__ __launch_bounds__(256, 1) void bgemm(
    const __nv_bfloat16* __restrict__ Ahp, const __nv_bfloat16* __restrict__ Alp,
    const __nv_bfloat16* __restrict__ Bhp, const __nv_bfloat16* __restrict__ Blp,
    const float* __restrict__ bias, float* __restrict__ Cf,
    __nv_bfloat16* __restrict__ Ch, __nv_bfloat16* __restrict__ Cl,
    __nv_bfloat16* __restrict__ Dh, __nv_bfloat16* __restrict__ Dl,
    int lda, int ldb, int ldc, int K, float alpha,
    long long sA, long long sB, long long sC)
{
    extern __shared__ char smem[];
    const uint32_t sb = smem_u32(smem);
    const int tid = threadIdx.x, w = tid >> 5, lane = tid & 31;
    const int m0 = blockIdx.y * 128, n0 = blockIdx.x * 256, bz = blockIdx.z;
    Ahp += bz * sA; Alp += bz * sA;
    Bhp += bz * sB; Blp += bz * sB;
    if (EPI == 0) Cf += bz * sC;

    const int wm = (w >> 2) * 64, wn = (w & 3) * 64;
    float acc[4][8][4];
#pragma unroll
    for (int a = 0; a < 4; a++)
#pragma unroll
        for (int b = 0; b < 8; b++)
#pragma unroll
            for (int c = 0; c < 4; c++) acc[a][b][c] = 0.f;

    const int nch = K >> 5;

    auto issue = [&](int c) {
        if (c < nch) {
            const int k0 = c << 5;
            const uint32_t dstb = sb + (c % 3) * STG;
#pragma unroll
            for (int mat = 0; mat < 2; mat++) {
                const __nv_bfloat16* g = mat ? Alp : Ahp;
                const uint32_t db = dstb + mat * ASZ;
#pragma unroll
                for (int it = 0; it < 2; it++) {
                    int i = (it << 8) + tid, row = i >> 2, c16 = i & 3;
                    const __nv_bfloat16* src = g + (long long)(m0 + row) * lda + k0 + (c16 << 3);
                    asm volatile("cp.async.cg.shared.global [%0], [%1], 16;"
                                 :: "r"(db + row * ROWB + (c16 << 4)), "l"(src));
                }
            }
#pragma unroll
            for (int mat = 0; mat < 2; mat++) {
                const __nv_bfloat16* g = mat ? Blp : Bhp;
                const uint32_t db = dstb + 2 * ASZ + mat * BSZ;
#pragma unroll
                for (int it = 0; it < 4; it++) {
                    int i = (it << 8) + tid, row = i >> 2, c16 = i & 3;
                    const __nv_bfloat16* src = g + (long long)(n0 + row) * ldb + k0 + (c16 << 3);
                    asm volatile("cp.async.cg.shared.global [%0], [%1], 16;"
                                 :: "r"(db + row * ROWB + (c16 << 4)), "l"(src));
                }
            }
        }
        asm volatile("cp.async.commit_group;");
    };

    const int q = lane >> 3, r = lane & 7;
    const int aRow = ((q & 1) << 3) + r;
    const int aCol = (q >> 1) << 4;
    const int bRow = ((q >> 1) << 3) + r;
    const int bCol = (q & 1) << 4;

    auto compute = [&](int c) {
        const uint32_t Ah = sb + (c % 3) * STG;
        const uint32_t Al = Ah + ASZ, Bh = Ah + 2 * ASZ, Bl = Bh + BSZ;
#pragma unroll
        for (int s = 0; s < 2; s++) {
            const int kOff = s * 32;
            uint32_t ah[4][4], al[4][4];
#pragma unroll
            for (int mt = 0; mt < 4; mt++) {
                uint32_t off = (uint32_t)(wm + mt * 16 + aRow) * ROWB + kOff + aCol;
                ldsm4(ah[mt][0], ah[mt][1], ah[mt][2], ah[mt][3], Ah + off);
                ldsm4(al[mt][0], al[mt][1], al[mt][2], al[mt][3], Al + off);
            }
#pragma unroll
            for (int half = 0; half < 2; half++) {
                uint32_t bh[4][2], bl[4][2];
#pragma unroll
                for (int np = 0; np < 2; np++) {
                    uint32_t off = (uint32_t)(wn + half * 32 + np * 16 + bRow) * ROWB
                                   + kOff + bCol;
                    ldsm4(bh[2 * np][0], bh[2 * np][1],
                          bh[2 * np + 1][0], bh[2 * np + 1][1], Bh + off);
                    ldsm4(bl[2 * np][0], bl[2 * np][1],
                          bl[2 * np + 1][0], bl[2 * np + 1][1], Bl + off);
                }
#pragma unroll
                for (int mt = 0; mt < 4; mt++)
#pragma unroll
                    for (int nt = 0; nt < 4; nt++) {
                        mma16816(acc[mt][half * 4 + nt], ah[mt], bh[nt]);
                        mma16816(acc[mt][half * 4 + nt], ah[mt], bl[nt]);
                        mma16816(acc[mt][half * 4 + nt], al[mt], bh[nt]);
                    }
            }
        }
    };

    issue(0); issue(1);
    for (int c = 0; c < nch; c++) {
        asm volatile("cp.async.wait_group 1;");
        __syncthreads();
        issue(c + 2);
        compute(c);
        __syncthreads();
    }

    const int gid = lane >> 2, tig = lane & 3;
#pragma unroll
    for (int mt = 0; mt < 4; mt++)
#pragma unroll
        for (int half = 0; half < 2; half++) {
            const long long m = m0 + wm + mt * 16 + gid + half * 8;
#pragma unroll
            for (int nt = 0; nt < 8; nt++) {
                float v0 = acc[mt][nt][half * 2 + 0];
                float v1 = acc[mt][nt][half * 2 + 1];
                const int n = n0 + wn + nt * 8 + tig * 2;
                if (EPI == 0) {
                    v0 *= alpha; v1 *= alpha;
                    if (bias) { v0 += bias[n]; v1 += bias[n + 1]; }
                    *(float2*)&Cf[m * ldc + n] = make_float2(v0, v1);
                } else if (EPI == 3) {
                    v0 += bias[n]; v1 += bias[n + 1];
                    if (n < 512) {
                        __nv_bfloat16 h0 = __float2bfloat16(v0), h1 = __float2bfloat16(v1);
                        *(uint32_t*)&Ch[m * 512 + n] = bpack(h0, h1);
                        *(uint32_t*)&Cl[m * 512 + n] =
                            fpack(v0 - __bfloat162float(h0), v1 - __bfloat162float(h1));
                    } else {
                        const int nv = n - 512;
                        const long long b = m >> 9, t = m & 511;
                        __nv_bfloat16 h0 = __float2bfloat16(v0), h1 = __float2bfloat16(v1);
                        Dh[(b * 768 + nv) * 512 + t] = h0;
                        Dl[(b * 768 + nv) * 512 + t] = __float2bfloat16(v0 - __bfloat162float(h0));
                        Dh[(b * 768 + nv + 1) * 512 + t] = h1;
                        Dl[(b * 768 + nv + 1) * 512 + t] = __float2bfloat16(v1 - __bfloat162float(h1));
                    }
                } else {  // EPI == 4: fp32 + pairs
                    v0 += bias[n]; v1 += bias[n + 1];
                    *(float2*)&Cf[m * ldc + n] = make_float2(v0, v1);
                    __nv_bfloat16 h0 = __float2bfloat16(v0), h1 = __float2bfloat16(v1);
                    *(uint32_t*)&Ch[m * ldc + n] = bpack(h0, h1);
                    *(uint32_t*)&Cl[m * ldc + n] =
                        fpack(v0 - __bfloat162float(h0), v1 - __bfloat162float(h1));
                }
            }
        }
}

// ---------------- weights: stacked WT pairs + WkN pairs + bias ---------------
__global__ void tsplit_all(const float* __restrict__ Wq, const float* __restrict__ Wk,
                           const float* __restrict__ Wv, const float* __restrict__ bq,
                           const float* __restrict__ bk, const float* __restrict__ bv)
{
    int idx = blockIdx.x * 256 + threadIdx.x;
    if (idx < 1280 * H) {
        int n = idx / H, k = idx - n * H;
        float x = (n < 256) ? Wq[(long long)k * NE + n]
                : (n < 512) ? Wk[(long long)k * NE + (n - 256)]
                            : Wv[(long long)k * H + (n - 512)];
        __nv_bfloat16 h = __float2bfloat16(x);
        g_Wh[idx] = h;
        g_Wl[idx] = __float2bfloat16(x - __bfloat162float(h));
    } else if (idx < 1280 * H + H * NE) {
        int local = idx - 1280 * H;
        float x = Wk[local];
        __nv_bfloat16 h = __float2bfloat16(x);
        g_WkNh[local] = h;
        g_WkNl[local] = __float2bfloat16(x - __bfloat162float(h));
    } else if (idx < 1280 * H + H * NE + 1280) {
        int j = idx - 1280 * H - H * NE;
        g_bias[j] = (j < 256) ? bq[j] : (j < 512) ? bk[j - 256] : bv[j - 512];
    }
}

// ---------------- gather + split region rows for qe GEMM --------------------
__global__ void sgat_kernel(const float* __restrict__ xs)
{
    int idx = blockIdx.x * 256 + threadIdx.x;
    int m = idx / (H / 4), r4 = idx - m * (H / 4);
    int br = m >> 8, b = (m >> 3) & 31, l = m & 7;
    float4 v = ((const float4*)(xs + ((long long)b * S + (br ? 20 : 1) + l) * H))[r4];
    uint2 hv, lv; split4(v, hv, lv);
    ((uint2*)g_qAh)[idx] = hv;
    ((uint2*)g_qAl)[idx] = lv;
}

// ---------------- c[row] = qe[row]·bk  (one warp per row) --------------------
__global__ void c_kernel()
{
    int row = blockIdx.x * 8 + (threadIdx.x >> 5);
    int lane = threadIdx.x & 31;
    float p = 0.f;
#pragma unroll
    for (int i = 0; i < 8; i++) {
        int e = lane + i * 32;
        p += g_qe[row * NE + e] * g_bias[256 + e];
    }
#pragma unroll
    for (int o = 16; o > 0; o >>= 1) p += __shfl_xor_sync(0xffffffffu, p, o);
    if (lane == 0) g_c[row] = p;
}

// ---------------- u = Wa @ Wattn halves; cbase -------------------------------
__global__ void u_kernel(const float* __restrict__ Wa, const float* __restrict__ Wattn,
                         const float* __restrict__ ba, const float* __restrict__ battn)
{
    if (blockIdx.x < 48) {
        int gt = blockIdx.x * 256 + threadIdx.x;
        int g = gt >> 3, sub = gt & 7;
        int j = g / H, h = g - j * H;
        float acc = 0.f;
#pragma unroll 4
        for (int a = sub; a < AE; a += 8) acc += Wa[h * AE + a] * Wattn[j * AE + a];
        acc += __shfl_down_sync(0xffffffffu, acc, 4, 8);
        acc += __shfl_down_sync(0xffffffffu, acc, 2, 8);
        acc += __shfl_down_sync(0xffffffffu, acc, 1, 8);
        if (sub == 0) g_u[g] = acc;
    } else {
        __shared__ float red[256];
        int tid = threadIdx.x;
        float v = 0.f;
        if (tid < AE) v = ba[tid] * (Wattn[tid] + Wattn[AE + tid]);
        red[tid] = v; __syncthreads();
        for (int s2 = 128; s2 > 0; s2 >>= 1) {
            if (tid < s2) red[tid] += red[tid + s2];
            __syncthreads();
        }
        if (tid == 0) g_u[2 * H] = red[0] + battn[0];
    }
}

// ---------------- per-(br,b,n): scores from z -> softmax -> message ----------
__global__ __launch_bounds__(256) void neigh_kernel(
    const float* __restrict__ e1, const float* __restrict__ e2)
{
    __shared__ float zs[RL * H];        // 24KB
    __shared__ float es[T * 193];       // 24.1KB (chunk Hc=192, stride 193)
    __shared__ float aw[RL * T];
    __shared__ float cs[RL];
    int br = blockIdx.x >> 10;
    int b = (blockIdx.x >> 5) & 31, n = blockIdx.x & 31;
    int tid = threadIdx.x;
    const float* emb = (br ? e2 : e1) + (long long)(b * NN + n) * T * H;
    const float4* eb4 = (const float4*)emb;

    // load z rows + consts
    const float4* z4 = (const float4*)(g_z + (long long)(br * 256 + b * 8) * H);
#pragma unroll
    for (int it = 0; it < 6; it++) {
        int i = it * 256 + tid;
        *(float4*)&zs[i * 4] = z4[i];
    }
    if (tid < 8) cs[tid] = g_c[br * 256 + b * 8 + tid];
    __syncthreads();

    // scores: thread (l = tid>>5, t = tid&31), dot over H in 4 chunks of 192
    int l = tid >> 5, tt = tid & 31;
    float sacc = 0.f;
#pragma unroll
    for (int ch = 0; ch < 4; ch++) {
        for (int i = tid; i < T * 48; i += 256) {
            int t2 = i / 48, h4 = i - t2 * 48;
            float4 v = eb4[t2 * (H / 4) + ch * 48 + h4];
            float* d = &es[t2 * 193 + h4 * 4];
            d[0] = v.x; d[1] = v.y; d[2] = v.z; d[3] = v.w;
        }
        __syncthreads();
        const float* er = es + tt * 193;
        const float* zr = zs + l * H + ch * 192;
#pragma unroll 8
        for (int h = 0; h < 192; h++) sacc += er[h] * zr[h];
        __syncthreads();
    }
    float s = (sacc + cs[l]) * SCALE;
    float m = s;
#pragma unroll
    for (int o = 16; o > 0; o >>= 1) m = fmaxf(m, __shfl_xor_sync(0xffffffffu, m, o));
    float ex = __expf(s - m), sum = ex;
#pragma unroll
    for (int o = 16; o > 0; o >>= 1) sum += __shfl_xor_sync(0xffffffffu, sum, o);
    aw[l * T + tt] = ex / sum;
    __syncthreads();

    // messages
    float* msg = (br ? g_msg2 : g_msg1) + (long long)(b * NN + n) * RL * H;
    float4* mb4 = (float4*)msg;
#pragma unroll
    for (int it = 0; it < RL * H / 4 / 256; it++) {
        int idx = it * 256 + tid;
        int l2 = idx / (H / 4), h4 = idx - l2 * (H / 4);
        float4 acc = make_float4(0.f, 0.f, 0.f, 0.f);
        const float* awr = aw + l2 * T;
#pragma unroll 8
        for (int t2 = 0; t2 < T; t2++) {
            float wgt = awr[t2];
            float4 e = eb4[t2 * (H / 4) + h4];
            acc.x += wgt * e.x; acc.y += wgt * e.y;
            acc.z += wgt * e.z; acc.w += wgt * e.w;
        }
        mb4[idx] = acc;
    }
}

// ---------------- region gate dots ------------------------------------------
__global__ __launch_bounds__(128) void rscore_kernel(
    const float* __restrict__ xs, const float* __restrict__ msg1,
    const float* __restrict__ msg2)
{
    __shared__ float wred[4];
    int id = blockIdx.x;
    int br = id / (Bn * 33);
    int rem = id - br * (Bn * 33);
    int b = rem / 33, j = rem - b * 33;
    int tid = threadIdx.x;

    const float* src;
    const float* uvec;
    if (j < NN) {
        src = (br ? msg2 : msg1) + (long long)(b * NN + j) * RL * H;
        uvec = g_u + H;
    } else {
        src = xs + ((long long)b * S + (br ? 20 : 1)) * H;
        uvec = g_u;
    }
    const float4* s4 = (const float4*)src;
    float p = 0.f;
#pragma unroll
    for (int it = 0; it < RL * H / 4 / 128; it++) {
        int i = it * 128 + tid;
        float4 v = s4[i];
        const float* up = uvec + (i % (H / 4)) * 4;
        p += v.x * up[0] + v.y * up[1] + v.z * up[2] + v.w * up[3];
    }
#pragma unroll
    for (int o = 16; o > 0; o >>= 1) p += __shfl_xor_sync(0xffffffffu, p, o);
    if ((tid & 31) == 0) wred[tid >> 5] = p;
    __syncthreads();
    if (tid == 0) {
        float tot = (wred[0] + wred[1] + wred[2] + wred[3]) * (1.f / RL);
        if (j < NN) g_md[(br * Bn + b) * NN + j] = tot;
        else        g_feas[br * Bn + b] = tot;
    }
}

__global__ void rsoftmax_kernel(const float* __restrict__ dist1,
                                const float* __restrict__ dist2,
                                const float* __restrict__ wb,
                                const float* __restrict__ bb)
{
    int br = blockIdx.x >> 5, b = blockIdx.x & 31;
    int lane = threadIdx.x;
    float pre = g_feas[br * Bn + b] + g_md[(br * Bn + b) * NN + lane] + g_u[2 * H];
    float z = pre >= 0.f ? pre : NEG * pre;
    const float* dist = br ? dist2 : dist1;
    float v = z + dist[b * NN + lane] * wb[0] + bb[0];
    float m = v;
#pragma unroll
    for (int o = 16; o > 0; o >>= 1) m = fmaxf(m, __shfl_xor_sync(0xffffffffu, m, o));
    float e = __expf(v - m), s = e;
#pragma unroll
    for (int o = 16; o > 0; o >>= 1) s += __shfl_xor_sync(0xffffffffu, s, o);
    (br ? g_att2 : g_att1)[b * NN + lane] = e / s;
}

// ---------------- x = xs (+ gated messages) -> bf16 pairs --------------------
__global__ void build_x_kernel(const float* __restrict__ xs)
{
    int idx = blockIdx.x * 256 + threadIdx.x;
    float4 v = ((const float4*)xs)[idx];
    int h4 = idx % (H / 4);
    int s = (idx / (H / 4)) % S;
    int b = idx / (S * H / 4);
    if (s >= 1 && s < 9) {
        int l = s - 1;
        const float4* m4 = (const float4*)g_msg1;
#pragma unroll 4
        for (int n = 0; n < NN; n++) {
            float a = g_att1[b * NN + n];
            float4 m = m4[((b * NN + n) * RL + l) * (H / 4) + h4];
            v.x += a * m.x; v.y += a * m.y; v.z += a * m.z; v.w += a * m.w;
        }
    } else if (s >= 20 && s < 28) {
        int l = s - 20;
        const float4* m4 = (const float4*)g_msg2;
#pragma unroll 4
        for (int n = 0; n < NN; n++) {
            float a = g_att2[b * NN + n];
            float4 m = m4[((b * NN + n) * RL + l) * (H / 4) + h4];
            v.x += a * m.x; v.y += a * m.y; v.z += a * m.z; v.w += a * m.w;
        }
    }
    uint2 hv, lv; split4(v, hv, lv);
    ((uint2*)g_xh)[idx] = hv;
    ((uint2*)g_xl)[idx] = lv;
}

// ---------------- row softmax (warp/row) -> bf16 pairs -----------------------
__global__ __launch_bounds__(256) void softmax_rows_kernel()
{
    int warp = threadIdx.x >> 5, lane = threadIdx.x & 31;
    long long row = (long long)blockIdx.x * 8 + warp;
    const float4* r4 = (const float4*)(g_probs + row * S);
    float4 x[4];
    float m = -3.4e38f;
#pragma unroll
    for (int k = 0; k < 4; k++) {
        x[k] = r4[lane + 32 * k];
        m = fmaxf(m, fmaxf(fmaxf(x[k].x, x[k].y), fmaxf(x[k].z, x[k].w)));
    }
#pragma unroll
    for (int o = 16; o > 0; o >>= 1) m = fmaxf(m, __shfl_xor_sync(0xffffffffu, m, o));
    float s = 0.f;
#pragma unroll
    for (int k = 0; k < 4; k++) {
        x[k].x = __expf(x[k].x - m); x[k].y = __expf(x[k].y - m);
        x[k].z = __expf(x[k].z - m); x[k].w = __expf(x[k].w - m);
        s += x[k].x + x[k].y + x[k].z + x[k].w;
    }
#pragma unroll
    for (int o = 16; o > 0; o >>= 1) s += __shfl_xor_sync(0xffffffffu, s, o);
    float inv = 1.f / s;
    uint2* ph4 = (uint2*)(g_ph + row * S);
    uint2* pl4 = (uint2*)(g_pl + row * S);
#pragma unroll
    for (int k = 0; k < 4; k++) {
        x[k].x *= inv; x[k].y *= inv; x[k].z *= inv; x[k].w *= inv;
        uint2 hv, lv; split4(x[k], hv, lv);
        ph4[lane + 32 * k] = hv;
        pl4[lane + 32 * k] = lv;
    }
}

// ---------------- launch ----------------
extern "C" void kernel_launch(void* const* d_in, const int* in_sizes, int n_in,
                              void* d_out, int out_size)
{
    const float* xs    = (const float*)d_in[0];
    const float* n1emb = (const float*)d_in[1];
    const float* n2emb = (const float*)d_in[2];
    const float* dist1 = (const float*)d_in[3];
    const float* dist2 = (const float*)d_in[4];
    const float* Wq    = (const float*)d_in[5];
    const float* bq    = (const float*)d_in[6];
    const float* Wk    = (const float*)d_in[7];
    const float* bk    = (const float*)d_in[8];
    const float* Wv    = (const float*)d_in[9];
    const float* bv    = (const float*)d_in[10];
    const float* Wa    = (const float*)d_in[11];
    const float* ba    = (const float*)d_in[12];
    const float* Wattn = (const float*)d_in[13];
    const float* battn = (const float*)d_in[14];
    const float* wb    = (const float*)d_in[15];
    const float* bb    = (const float*)d_in[16];
    float* out = (float*)d_out;

    float *pp, *pm1, *pm2, *pqe, *pz, *pbias;
    __nv_bfloat16 *pwh, *pwl, *pwknh, *pwknl, *pqeh, *pqel, *pxh, *pxl,
                  *pqkh, *pqkl, *pvh, *pvl, *pph, *ppl, *pah, *pal;
    cudaGetSymbolAddress((void**)&pp,    g_probs);
    cudaGetSymbolAddress((void**)&pm1,   g_msg1);
    cudaGetSymbolAddress((void**)&pm2,   g_msg2);
    cudaGetSymbolAddress((void**)&pqe,   g_qe);
    cudaGetSymbolAddress((void**)&pz,    g_z);
    cudaGetSymbolAddress((void**)&pbias, g_bias);
    cudaGetSymbolAddress((void**)&pwh,   g_Wh);
    cudaGetSymbolAddress((void**)&pwl,   g_Wl);
    cudaGetSymbolAddress((void**)&pwknh, g_WkNh);
    cudaGetSymbolAddress((void**)&pwknl, g_WkNl);
    cudaGetSymbolAddress((void**)&pqeh,  g_qeh);
    cudaGetSymbolAddress((void**)&pqel,  g_qel);
    cudaGetSymbolAddress((void**)&pxh,   g_xh);
    cudaGetSymbolAddress((void**)&pxl,   g_xl);
    cudaGetSymbolAddress((void**)&pqkh,  g_qkh);
    cudaGetSymbolAddress((void**)&pqkl,  g_qkl);
    cudaGetSymbolAddress((void**)&pvh,   g_vTh);
    cudaGetSymbolAddress((void**)&pvl,   g_vTl);
    cudaGetSymbolAddress((void**)&pph,   g_ph);
    cudaGetSymbolAddress((void**)&ppl,   g_pl);
    cudaGetSymbolAddress((void**)&pah,   g_qAh);
    cudaGetSymbolAddress((void**)&pal,   g_qAl);

    cudaFuncSetAttribute(bgemm<0>, cudaFuncAttributeMaxDynamicSharedMemorySize, BG_SMEM);
    cudaFuncSetAttribute(bgemm<3>, cudaFuncAttributeMaxDynamicSharedMemorySize, BG_SMEM);
    cudaFuncSetAttribute(bgemm<4>, cudaFuncAttributeMaxDynamicSharedMemorySize, BG_SMEM);

    // prep
    tsplit_all<<<(1280 * H + H * NE + 1280 + 255) / 256, 256>>>(Wq, Wk, Wv, bq, bk, bv);
    u_kernel<<<49, 256>>>(Wa, Wattn, ba, battn);
    sgat_kernel<<<512 * (H / 4) / 256, 256>>>(xs);

    // qe = gathered regions @ Wq^T + bq (fp32 + pairs)
    bgemm<4><<<dim3(1, 4, 1), 256, BG_SMEM>>>(
        pah, pal, pwh, pwl, pbias, pqe, pqeh, pqel, nullptr, nullptr,
        H, H, NE, H, 1.f, 0, 0, 0);

    // z = qe @ Wk (original layout; N=768, K=256)
    bgemm<0><<<dim3(3, 4, 1), 256, BG_SMEM>>>(
        pqeh, pqel, pwknh, pwknl, nullptr, pz, nullptr, nullptr, nullptr, nullptr,
        NE, NE, H, NE, 1.f, 0, 0, 0);
    c_kernel<<<64, 256>>>();

    // neighbor attention via emb·z + messages (both branches)
    neigh_kernel<<<2 * Bn * NN, 256>>>(n1emb, n2emb);

    // gate attention + x pairs
    rscore_kernel<<<2 * Bn * 33, 128>>>(xs, pm1, pm2);
    rsoftmax_kernel<<<2 * Bn, 32>>>(dist1, dist2, wb, bb);
    build_x_kernel<<<(Bn * S * H / 4) / 256, 256>>>(xs);

    // fused q/k/v projections (N = 1280)
    bgemm<3><<<dim3(5, 128, 1), 256, BG_SMEM>>>(
        pxh, pxl, pwh, pwl, pbias, nullptr, pqkh, pqkl, pvh, pvl,
        H, H, 512, H, 1.f, 0, 0, 0);

    // scores = SCALE * q @ k^T (batched)
    bgemm<0><<<dim3(2, 4, 32), 256, BG_SMEM>>>(
        pqkh, pqkl, pqkh + 256, pqkl + 256, nullptr, pp,
        nullptr, nullptr, nullptr, nullptr,
        512, 512, S, NE, SCALE,
        (long long)S * 512, (long long)S * 512, (long long)S * S);

    softmax_rows_kernel<<<Bn * S / 8, 256>>>();

    // out = probs @ v (batched)
    bgemm<0><<<dim3(3, 4, 32), 256, BG_SMEM>>>(
        pph, ppl, pvh, pvl, nullptr, out, nullptr, nullptr, nullptr, nullptr,
        512, 512, H, S, 1.f,
        (long long)S * S, (long long)H * S, (long long)S * H);
}

// round 9
// speedup vs baseline: 3.1940x; 1.0608x over previous
#include <cuda_runtime.h>
#include <cuda_bf16.h>
#include <cstdint>

// ---------------- problem constants ----------------
namespace {
constexpr int Bn = 32;
constexpr int S  = 512;
constexpr int H  = 768;
constexpr int NN = 32;
constexpr int T  = 32;
constexpr int NE = 256;
constexpr int AE = 128;
constexpr int RL = 8;
constexpr float SCALE = 0.0625f;
constexpr float NEG   = 0.01f;
}

// ---------------- scratch ----------------
__device__ float g_probs[Bn * S * S];
__device__ float g_msg1 [Bn * NN * RL * H];
__device__ float g_msg2 [Bn * NN * RL * H];
__device__ float g_qe   [2 * Bn * RL * NE];
__device__ float g_qeP  [6 * 512 * NE];         // split-K partial slabs
__device__ float g_z    [2 * Bn * RL * H];
__device__ float g_zP   [2 * 512 * H];
__device__ float g_c    [2 * Bn * RL];
__device__ float g_att1 [Bn * NN];
__device__ float g_att2 [Bn * NN];
__device__ float g_u    [2 * H + 1];
__device__ float g_md   [2 * Bn * NN];
__device__ float g_feas [2 * Bn];
__device__ float g_bias [1280];

__device__ __nv_bfloat16 g_Wh  [1280 * H], g_Wl  [1280 * H];  // stacked WqT|WkT|WvT
__device__ __nv_bfloat16 g_WkNh[H * NE],   g_WkNl[H * NE];    // Wk original layout
__device__ __nv_bfloat16 g_qeh [512 * NE], g_qel [512 * NE];
__device__ __nv_bfloat16 g_xh  [Bn * S * H], g_xl [Bn * S * H];
__device__ __nv_bfloat16 g_qkh [Bn * S * 512], g_qkl[Bn * S * 512];
__device__ __nv_bfloat16 g_vTh [Bn * H * S], g_vTl[Bn * H * S];
__device__ __nv_bfloat16 g_ph  [Bn * S * S], g_pl [Bn * S * S];
__device__ __nv_bfloat16 g_qAh [512 * H],   g_qAl [512 * H];

// ---------------- helpers ----------------
__device__ __forceinline__ uint32_t smem_u32(const void* p) {
    uint32_t a;
    asm("{ .reg .u64 t; cvta.to.shared.u64 t, %1; cvt.u32.u64 %0, t; }" : "=r"(a) : "l"(p));
    return a;
}
__device__ __forceinline__ uint32_t bpack(__nv_bfloat16 a, __nv_bfloat16 b) {
    __nv_bfloat162 t = __halves2bfloat162(a, b);
    return *reinterpret_cast<uint32_t*>(&t);
}
__device__ __forceinline__ uint32_t fpack(float a, float b) {
    __nv_bfloat162 t = __floats2bfloat162_rn(a, b);
    return *reinterpret_cast<uint32_t*>(&t);
}
__device__ __forceinline__ void split4(float4 v, uint2& hv, uint2& lv) {
    __nv_bfloat16 h0 = __float2bfloat16(v.x), h1 = __float2bfloat16(v.y);
    __nv_bfloat16 h2 = __float2bfloat16(v.z), h3 = __float2bfloat16(v.w);
    hv.x = bpack(h0, h1); hv.y = bpack(h2, h3);
    lv.x = fpack(v.x - __bfloat162float(h0), v.y - __bfloat162float(h1));
    lv.y = fpack(v.z - __bfloat162float(h2), v.w - __bfloat162float(h3));
}
__device__ __forceinline__ void ldsm4(uint32_t& r0, uint32_t& r1, uint32_t& r2,
                                      uint32_t& r3, uint32_t a) {
    asm volatile("ldmatrix.sync.aligned.m8n8.x4.shared.b16 {%0,%1,%2,%3}, [%4];"
                 : "=r"(r0), "=r"(r1), "=r"(r2), "=r"(r3) : "r"(a));
}
__device__ __forceinline__ void mma16816(float* d, const uint32_t* a, const uint32_t* b) {
    asm volatile(
        "mma.sync.aligned.m16n8k16.row.col.f32.bf16.bf16.f32 "
        "{%0,%1,%2,%3}, {%4,%5,%6,%7}, {%8,%9}, {%0,%1,%2,%3};"
        : "+f"(d[0]), "+f"(d[1]), "+f"(d[2]), "+f"(d[3])
        : "r"(a[0]), "r"(a[1]), "r"(a[2]), "r"(a[3]), "r"(b[0]), "r"(b[1]));
}

// ================= all-bf16 cp.async bf16x3 GEMM, CTA 128x128 =================
// 8 warps (2x4), warp tile 64x32, BK=32, 4-stage pipeline.
// EPI 0: fp32 out (alpha*acc + bias?).  EPI 3: qkv routing (pairs / transposed pairs).
// SK: blockIdx.z = K-slice (length K); output slab at Cf + bz*sC.
constexpr int ROWB  = 80;
constexpr int MTILE = 128 * ROWB;     // 10240
constexpr int STG   = 4 * MTILE;      // 40960
constexpr int BG_SMEM = 4 * STG;      // 163840

template<int EPI, bool SK>
__global__ __launch_bounds__(256, 1) void bgemm(
    const __nv_bfloat16* __restrict__ Ahp, const __nv_bfloat16* __restrict__ Alp,
    const __nv_bfloat16* __restrict__ Bhp, const __nv_bfloat16* __restrict__ Blp,
    const float* __restrict__ bias, float* __restrict__ Cf,
    __nv_bfloat16* __restrict__ Ch, __nv_bfloat16* __restrict__ Cl,
    __nv_bfloat16* __restrict__ Dh, __nv_bfloat16* __restrict__ Dl,
    int lda, int ldb, int ldc, int K, float alpha,
    long long sA, long long sB, long long sC)
{
    extern __shared__ char smem[];
    const uint32_t sb = smem_u32(smem);
    const int tid = threadIdx.x, w = tid >> 5, lane = tid & 31;
    const int m0 = blockIdx.y * 128, n0 = blockIdx.x * 128, bz = blockIdx.z;
    int koff = 0;
    if (SK) {
        koff = bz * K;
        Cf += bz * sC;
    } else {
        Ahp += bz * sA; Alp += bz * sA;
        Bhp += bz * sB; Blp += bz * sB;
        if (EPI == 0) Cf += bz * sC;
    }

    const int wm = (w >> 2) * 64, wn = (w & 3) * 32;
    float acc[4][4][4];
#pragma unroll
    for (int a = 0; a < 4; a++)
#pragma unroll
        for (int b = 0; b < 4; b++)
#pragma unroll
            for (int c = 0; c < 4; c++) acc[a][b][c] = 0.f;

    const int nch = K >> 5;

    auto issue = [&](int c) {
        if (c < nch) {
            const int k0 = (c << 5) + koff;
            const uint32_t dstb = sb + (c & 3) * STG;
#pragma unroll
            for (int mat = 0; mat < 4; mat++) {
                const __nv_bfloat16* g = (mat == 0) ? Ahp : (mat == 1) ? Alp
                                       : (mat == 2) ? Bhp : Blp;
                const int rb = (mat < 2) ? m0 : n0;
                const int ld = (mat < 2) ? lda : ldb;
#pragma unroll
                for (int it = 0; it < 2; it++) {
                    int i = (it << 8) + tid, row = i >> 2, c16 = i & 3;
                    const __nv_bfloat16* src = g + (long long)(rb + row) * ld + k0 + (c16 << 3);
                    asm volatile("cp.async.cg.shared.global [%0], [%1], 16;"
                                 :: "r"(dstb + mat * MTILE + row * ROWB + (c16 << 4)), "l"(src));
                }
            }
        }
        asm volatile("cp.async.commit_group;");
    };

    const int q = lane >> 3, r = lane & 7;
    const int aRow = ((q & 1) << 3) + r;
    const int aCol = (q >> 1) << 4;
    const int bRow = ((q >> 1) << 3) + r;
    const int bCol = (q & 1) << 4;

    auto compute = [&](int c) {
        const uint32_t Ah = sb + (c & 3) * STG;
        const uint32_t Al = Ah + MTILE, Bh = Ah + 2 * MTILE, Bl = Ah + 3 * MTILE;
#pragma unroll
        for (int s = 0; s < 2; s++) {
            const int kOff = s * 32;
            uint32_t ah[4][4], al[4][4];
#pragma unroll
            for (int mt = 0; mt < 4; mt++) {
                uint32_t off = (uint32_t)(wm + mt * 16 + aRow) * ROWB + kOff + aCol;
                ldsm4(ah[mt][0], ah[mt][1], ah[mt][2], ah[mt][3], Ah + off);
                ldsm4(al[mt][0], al[mt][1], al[mt][2], al[mt][3], Al + off);
            }
            uint32_t bh[4][2], bl[4][2];
#pragma unroll
            for (int np = 0; np < 2; np++) {
                uint32_t off = (uint32_t)(wn + np * 16 + bRow) * ROWB + kOff + bCol;
                ldsm4(bh[2 * np][0], bh[2 * np][1],
                      bh[2 * np + 1][0], bh[2 * np + 1][1], Bh + off);
                ldsm4(bl[2 * np][0], bl[2 * np][1],
                      bl[2 * np + 1][0], bl[2 * np + 1][1], Bl + off);
            }
#pragma unroll
            for (int mt = 0; mt < 4; mt++)
#pragma unroll
                for (int nt = 0; nt < 4; nt++) {
                    mma16816(acc[mt][nt], ah[mt], bh[nt]);
                    mma16816(acc[mt][nt], ah[mt], bl[nt]);
                    mma16816(acc[mt][nt], al[mt], bh[nt]);
                }
        }
    };

    issue(0); issue(1); issue(2);
    for (int c = 0; c < nch; c++) {
        asm volatile("cp.async.wait_group 2;");
        __syncthreads();
        issue(c + 3);
        compute(c);
        __syncthreads();
    }

    const int gid = lane >> 2, tig = lane & 3;
#pragma unroll
    for (int mt = 0; mt < 4; mt++)
#pragma unroll
        for (int half = 0; half < 2; half++) {
            const long long m = m0 + wm + mt * 16 + gid + half * 8;
#pragma unroll
            for (int nt = 0; nt < 4; nt++) {
                float v0 = acc[mt][nt][half * 2 + 0];
                float v1 = acc[mt][nt][half * 2 + 1];
                const int n = n0 + wn + nt * 8 + tig * 2;
                if (EPI == 0) {
                    v0 *= alpha; v1 *= alpha;
                    if (bias) { v0 += bias[n]; v1 += bias[n + 1]; }
                    *(float2*)&Cf[m * ldc + n] = make_float2(v0, v1);
                } else {  // EPI == 3
                    v0 += bias[n]; v1 += bias[n + 1];
                    if (n0 < 512) {
                        __nv_bfloat16 h0 = __float2bfloat16(v0), h1 = __float2bfloat16(v1);
                        *(uint32_t*)&Ch[m * 512 + n] = bpack(h0, h1);
                        *(uint32_t*)&Cl[m * 512 + n] =
                            fpack(v0 - __bfloat162float(h0), v1 - __bfloat162float(h1));
                    } else {
                        const int nv = n - 512;
                        const long long b = m >> 9, t = m & 511;
                        __nv_bfloat16 h0 = __float2bfloat16(v0), h1 = __float2bfloat16(v1);
                        Dh[(b * 768 + nv) * 512 + t] = h0;
                        Dl[(b * 768 + nv) * 512 + t] = __float2bfloat16(v0 - __bfloat162float(h0));
                        Dh[(b * 768 + nv + 1) * 512 + t] = h1;
                        Dl[(b * 768 + nv + 1) * 512 + t] = __float2bfloat16(v1 - __bfloat162float(h1));
                    }
                }
            }
        }
}

// ---------------- split-K finish: qe = sum(slabs) + bq; emit fp32 + pairs ----
__global__ void qe_finish()
{
    int idx = blockIdx.x * 256 + threadIdx.x;   // 32768 float4s
    int n4 = (idx % (NE / 4)) * 4;
    float4 s = ((const float4*)g_qeP)[idx];
#pragma unroll
    for (int k = 1; k < 6; k++) {
        float4 p = ((const float4*)g_qeP)[k * (512 * NE / 4) + idx];
        s.x += p.x; s.y += p.y; s.z += p.z; s.w += p.w;
    }
    s.x += g_bias[n4]; s.y += g_bias[n4 + 1];
    s.z += g_bias[n4 + 2]; s.w += g_bias[n4 + 3];
    ((float4*)g_qe)[idx] = s;
    uint2 hv, lv; split4(s, hv, lv);
    ((uint2*)g_qeh)[idx] = hv;
    ((uint2*)g_qel)[idx] = lv;
}

// ---------------- split-K finish: z = slab0 + slab1 --------------------------
__global__ void z_finish()
{
    int idx = blockIdx.x * 256 + threadIdx.x;   // 98304 float4s
    float4 a = ((const float4*)g_zP)[idx];
    float4 b = ((const float4*)g_zP)[512 * H / 4 + idx];
    a.x += b.x; a.y += b.y; a.z += b.z; a.w += b.w;
    ((float4*)g_z)[idx] = a;
}

// ---------------- weights: stacked WT pairs + WkN pairs + bias ---------------
__global__ void tsplit_all(const float* __restrict__ Wq, const float* __restrict__ Wk,
                           const float* __restrict__ Wv, const float* __restrict__ bq,
                           const float* __restrict__ bk, const float* __restrict__ bv)
{
    int idx = blockIdx.x * 256 + threadIdx.x;
    if (idx < 1280 * H) {
        int n = idx / H, k = idx - n * H;
        float x = (n < 256) ? Wq[(long long)k * NE + n]
                : (n < 512) ? Wk[(long long)k * NE + (n - 256)]
                            : Wv[(long long)k * H + (n - 512)];
        __nv_bfloat16 h = __float2bfloat16(x);
        g_Wh[idx] = h;
        g_Wl[idx] = __float2bfloat16(x - __bfloat162float(h));
    } else if (idx < 1280 * H + H * NE) {
        int local = idx - 1280 * H;
        float x = Wk[local];
        __nv_bfloat16 h = __float2bfloat16(x);
        g_WkNh[local] = h;
        g_WkNl[local] = __float2bfloat16(x - __bfloat162float(h));
    } else if (idx < 1280 * H + H * NE + 1280) {
        int j = idx - 1280 * H - H * NE;
        g_bias[j] = (j < 256) ? bq[j] : (j < 512) ? bk[j - 256] : bv[j - 512];
    }
}

// ---------------- gather + split region rows for qe GEMM ---------------------
__global__ void sgat_kernel(const float* __restrict__ xs)
{
    int idx = blockIdx.x * 256 + threadIdx.x;
    int m = idx / (H / 4), r4 = idx - m * (H / 4);
    int br = m >> 8, b = (m >> 3) & 31, l = m & 7;
    float4 v = ((const float4*)(xs + ((long long)b * S + (br ? 20 : 1) + l) * H))[r4];
    uint2 hv, lv; split4(v, hv, lv);
    ((uint2*)g_qAh)[idx] = hv;
    ((uint2*)g_qAl)[idx] = lv;
}

// ---------------- c[row] = qe[row]·bk ----------------------------------------
__global__ void c_kernel()
{
    int row = blockIdx.x * 8 + (threadIdx.x >> 5);
    int lane = threadIdx.x & 31;
    float p = 0.f;
#pragma unroll
    for (int i = 0; i < 8; i++) {
        int e = lane + i * 32;
        p += g_qe[row * NE + e] * g_bias[256 + e];
    }
#pragma unroll
    for (int o = 16; o > 0; o >>= 1) p += __shfl_xor_sync(0xffffffffu, p, o);
    if (lane == 0) g_c[row] = p;
}

// ---------------- u = Wa @ Wattn halves; cbase -------------------------------
__global__ void u_kernel(const float* __restrict__ Wa, const float* __restrict__ Wattn,
                         const float* __restrict__ ba, const float* __restrict__ battn)
{
    if (blockIdx.x < 48) {
        int gt = blockIdx.x * 256 + threadIdx.x;
        int g = gt >> 3, sub = gt & 7;
        int j = g / H, h = g - j * H;
        float acc = 0.f;
#pragma unroll 4
        for (int a = sub; a < AE; a += 8) acc += Wa[h * AE + a] * Wattn[j * AE + a];
        acc += __shfl_down_sync(0xffffffffu, acc, 4, 8);
        acc += __shfl_down_sync(0xffffffffu, acc, 2, 8);
        acc += __shfl_down_sync(0xffffffffu, acc, 1, 8);
        if (sub == 0) g_u[g] = acc;
    } else {
        __shared__ float red[256];
        int tid = threadIdx.x;
        float v = 0.f;
        if (tid < AE) v = ba[tid] * (Wattn[tid] + Wattn[AE + tid]);
        red[tid] = v; __syncthreads();
        for (int s2 = 128; s2 > 0; s2 >>= 1) {
            if (tid < s2) red[tid] += red[tid + s2];
            __syncthreads();
        }
        if (tid == 0) g_u[2 * H] = red[0] + battn[0];
    }
}

// ---------------- per-(br,b,n): scores from z -> softmax -> message ----------
__global__ __launch_bounds__(256) void neigh_kernel(
    const float* __restrict__ e1, const float* __restrict__ e2)
{
    __shared__ float zs[RL * H];
    __shared__ float es[T * 193];
    __shared__ float aw[RL * T];
    __shared__ float cs[RL];
    int br = blockIdx.x >> 10;
    int b = (blockIdx.x >> 5) & 31, n = blockIdx.x & 31;
    int tid = threadIdx.x;
    const float* emb = (br ? e2 : e1) + (long long)(b * NN + n) * T * H;
    const float4* eb4 = (const float4*)emb;

    const float4* z4 = (const float4*)(g_z + (long long)(br * 256 + b * 8) * H);
#pragma unroll
    for (int it = 0; it < 6; it++) {
        int i = it * 256 + tid;
        *(float4*)&zs[i * 4] = z4[i];
    }
    if (tid < 8) cs[tid] = g_c[br * 256 + b * 8 + tid];
    __syncthreads();

    int l = tid >> 5, tt = tid & 31;
    float sacc = 0.f;
#pragma unroll
    for (int ch = 0; ch < 4; ch++) {
        for (int i = tid; i < T * 48; i += 256) {
            int t2 = i / 48, h4 = i - t2 * 48;
            float4 v = eb4[t2 * (H / 4) + ch * 48 + h4];
            float* d = &es[t2 * 193 + h4 * 4];
            d[0] = v.x; d[1] = v.y; d[2] = v.z; d[3] = v.w;
        }
        __syncthreads();
        const float* er = es + tt * 193;
        const float* zr = zs + l * H + ch * 192;
#pragma unroll 8
        for (int h = 0; h < 192; h++) sacc += er[h] * zr[h];
        __syncthreads();
    }
    float s = (sacc + cs[l]) * SCALE;
    float m = s;
#pragma unroll
    for (int o = 16; o > 0; o >>= 1) m = fmaxf(m, __shfl_xor_sync(0xffffffffu, m, o));
    float ex = __expf(s - m), sum = ex;
#pragma unroll
    for (int o = 16; o > 0; o >>= 1) sum += __shfl_xor_sync(0xffffffffu, sum, o);
    aw[l * T + tt] = ex / sum;
    __syncthreads();

    float* msg = (br ? g_msg2 : g_msg1) + (long long)(b * NN + n) * RL * H;
    float4* mb4 = (float4*)msg;
#pragma unroll
    for (int it = 0; it < RL * H / 4 / 256; it++) {
        int idx = it * 256 + tid;
        int l2 = idx / (H / 4), h4 = idx - l2 * (H / 4);
        float4 acc = make_float4(0.f, 0.f, 0.f, 0.f);
        const float* awr = aw + l2 * T;
#pragma unroll 8
        for (int t2 = 0; t2 < T; t2++) {
            float wgt = awr[t2];
            float4 e = eb4[t2 * (H / 4) + h4];
            acc.x += wgt * e.x; acc.y += wgt * e.y;
            acc.z += wgt * e.z; acc.w += wgt * e.w;
        }
        mb4[idx] = acc;
    }
}

// ---------------- region gate dots -------------------------------------------
__global__ __launch_bounds__(128) void rscore_kernel(
    const float* __restrict__ xs, const float* __restrict__ msg1,
    const float* __restrict__ msg2)
{
    __shared__ float wred[4];
    int id = blockIdx.x;
    int br = id / (Bn * 33);
    int rem = id - br * (Bn * 33);
    int b = rem / 33, j = rem - b * 33;
    int tid = threadIdx.x;

    const float* src;
    const float* uvec;
    if (j < NN) {
        src = (br ? msg2 : msg1) + (long long)(b * NN + j) * RL * H;
        uvec = g_u + H;
    } else {
        src = xs + ((long long)b * S + (br ? 20 : 1)) * H;
        uvec = g_u;
    }
    const float4* s4 = (const float4*)src;
    float p = 0.f;
#pragma unroll
    for (int it = 0; it < RL * H / 4 / 128; it++) {
        int i = it * 128 + tid;
        float4 v = s4[i];
        const float* up = uvec + (i % (H / 4)) * 4;
        p += v.x * up[0] + v.y * up[1] + v.z * up[2] + v.w * up[3];
    }
#pragma unroll
    for (int o = 16; o > 0; o >>= 1) p += __shfl_xor_sync(0xffffffffu, p, o);
    if ((tid & 31) == 0) wred[tid >> 5] = p;
    __syncthreads();
    if (tid == 0) {
        float tot = (wred[0] + wred[1] + wred[2] + wred[3]) * (1.f / RL);
        if (j < NN) g_md[(br * Bn + b) * NN + j] = tot;
        else        g_feas[br * Bn + b] = tot;
    }
}

__global__ void rsoftmax_kernel(const float* __restrict__ dist1,
                                const float* __restrict__ dist2,
                                const float* __restrict__ wb,
                                const float* __restrict__ bb)
{
    int br = blockIdx.x >> 5, b = blockIdx.x & 31;
    int lane = threadIdx.x;
    float pre = g_feas[br * Bn + b] + g_md[(br * Bn + b) * NN + lane] + g_u[2 * H];
    float z = pre >= 0.f ? pre : NEG * pre;
    const float* dist = br ? dist2 : dist1;
    float v = z + dist[b * NN + lane] * wb[0] + bb[0];
    float m = v;
#pragma unroll
    for (int o = 16; o > 0; o >>= 1) m = fmaxf(m, __shfl_xor_sync(0xffffffffu, m, o));
    float e = __expf(v - m), s = e;
#pragma unroll
    for (int o = 16; o > 0; o >>= 1) s += __shfl_xor_sync(0xffffffffu, s, o);
    (br ? g_att2 : g_att1)[b * NN + lane] = e / s;
}

// ---------------- x = xs (+ gated messages) -> bf16 pairs --------------------
__global__ void build_x_kernel(const float* __restrict__ xs)
{
    int idx = blockIdx.x * 256 + threadIdx.x;
    float4 v = ((const float4*)xs)[idx];
    int h4 = idx % (H / 4);
    int s = (idx / (H / 4)) % S;
    int b = idx / (S * H / 4);
    if (s >= 1 && s < 9) {
        int l = s - 1;
        const float4* m4 = (const float4*)g_msg1;
#pragma unroll 4
        for (int n = 0; n < NN; n++) {
            float a = g_att1[b * NN + n];
            float4 m = m4[((b * NN + n) * RL + l) * (H / 4) + h4];
            v.x += a * m.x; v.y += a * m.y; v.z += a * m.z; v.w += a * m.w;
        }
    } else if (s >= 20 && s < 28) {
        int l = s - 20;
        const float4* m4 = (const float4*)g_msg2;
#pragma unroll 4
        for (int n = 0; n < NN; n++) {
            float a = g_att2[b * NN + n];
            float4 m = m4[((b * NN + n) * RL + l) * (H / 4) + h4];
            v.x += a * m.x; v.y += a * m.y; v.z += a * m.z; v.w += a * m.w;
        }
    }
    uint2 hv, lv; split4(v, hv, lv);
    ((uint2*)g_xh)[idx] = hv;
    ((uint2*)g_xl)[idx] = lv;
}

// ---------------- row softmax (warp/row) -> bf16 pairs -----------------------
__global__ __launch_bounds__(256) void softmax_rows_kernel()
{
    int warp = threadIdx.x >> 5, lane = threadIdx.x & 31;
    long long row = (long long)blockIdx.x * 8 + warp;
    const float4* r4 = (const float4*)(g_probs + row * S);
    float4 x[4];
    float m = -3.4e38f;
#pragma unroll
    for (int k = 0; k < 4; k++) {
        x[k] = r4[lane + 32 * k];
        m = fmaxf(m, fmaxf(fmaxf(x[k].x, x[k].y), fmaxf(x[k].z, x[k].w)));
    }
#pragma unroll
    for (int o = 16; o > 0; o >>= 1) m = fmaxf(m, __shfl_xor_sync(0xffffffffu, m, o));
    float s = 0.f;
#pragma unroll
    for (int k = 0; k < 4; k++) {
        x[k].x = __expf(x[k].x - m); x[k].y = __expf(x[k].y - m);
        x[k].z = __expf(x[k].z - m); x[k].w = __expf(x[k].w - m);
        s += x[k].x + x[k].y + x[k].z + x[k].w;
    }
#pragma unroll
    for (int o = 16; o > 0; o >>= 1) s += __shfl_xor_sync(0xffffffffu, s, o);
    float inv = 1.f / s;
    uint2* ph4 = (uint2*)(g_ph + row * S);
    uint2* pl4 = (uint2*)(g_pl + row * S);
#pragma unroll
    for (int k = 0; k < 4; k++) {
        x[k].x *= inv; x[k].y *= inv; x[k].z *= inv; x[k].w *= inv;
        uint2 hv, lv; split4(x[k], hv, lv);
        ph4[lane + 32 * k] = hv;
        pl4[lane + 32 * k] = lv;
    }
}

// ---------------- launch ----------------
extern "C" void kernel_launch(void* const* d_in, const int* in_sizes, int n_in,
                              void* d_out, int out_size)
{
    const float* xs    = (const float*)d_in[0];
    const float* n1emb = (const float*)d_in[1];
    const float* n2emb = (const float*)d_in[2];
    const float* dist1 = (const float*)d_in[3];
    const float* dist2 = (const float*)d_in[4];
    const float* Wq    = (const float*)d_in[5];
    const float* bq    = (const float*)d_in[6];
    const float* Wk    = (const float*)d_in[7];
    const float* bk    = (const float*)d_in[8];
    const float* Wv    = (const float*)d_in[9];
    const float* bv    = (const float*)d_in[10];
    const float* Wa    = (const float*)d_in[11];
    const float* ba    = (const float*)d_in[12];
    const float* Wattn = (const float*)d_in[13];
    const float* battn = (const float*)d_in[14];
    const float* wb    = (const float*)d_in[15];
    const float* bb    = (const float*)d_in[16];
    float* out = (float*)d_out;

    float *pp, *pm1, *pm2, *pqeP, *pzP, *pbias;
    __nv_bfloat16 *pwh, *pwl, *pwknh, *pwknl, *pqeh, *pqel, *pxh, *pxl,
                  *pqkh, *pqkl, *pvh, *pvl, *pph, *ppl, *pah, *pal;
    cudaGetSymbolAddress((void**)&pp,    g_probs);
    cudaGetSymbolAddress((void**)&pm1,   g_msg1);
    cudaGetSymbolAddress((void**)&pm2,   g_msg2);
    cudaGetSymbolAddress((void**)&pqeP,  g_qeP);
    cudaGetSymbolAddress((void**)&pzP,   g_zP);
    cudaGetSymbolAddress((void**)&pbias, g_bias);
    cudaGetSymbolAddress((void**)&pwh,   g_Wh);
    cudaGetSymbolAddress((void**)&pwl,   g_Wl);
    cudaGetSymbolAddress((void**)&pwknh, g_WkNh);
    cudaGetSymbolAddress((void**)&pwknl, g_WkNl);
    cudaGetSymbolAddress((void**)&pqeh,  g_qeh);
    cudaGetSymbolAddress((void**)&pqel,  g_qel);
    cudaGetSymbolAddress((void**)&pxh,   g_xh);
    cudaGetSymbolAddress((void**)&pxl,   g_xl);
    cudaGetSymbolAddress((void**)&pqkh,  g_qkh);
    cudaGetSymbolAddress((void**)&pqkl,  g_qkl);
    cudaGetSymbolAddress((void**)&pvh,   g_vTh);
    cudaGetSymbolAddress((void**)&pvl,   g_vTl);
    cudaGetSymbolAddress((void**)&pph,   g_ph);
    cudaGetSymbolAddress((void**)&ppl,   g_pl);
    cudaGetSymbolAddress((void**)&pah,   g_qAh);
    cudaGetSymbolAddress((void**)&pal,   g_qAl);

    cudaFuncSetAttribute(bgemm<0, false>, cudaFuncAttributeMaxDynamicSharedMemorySize, BG_SMEM);
    cudaFuncSetAttribute(bgemm<0, true>,  cudaFuncAttributeMaxDynamicSharedMemorySize, BG_SMEM);
    cudaFuncSetAttribute(bgemm<3, false>, cudaFuncAttributeMaxDynamicSharedMemorySize, BG_SMEM);

    // prep
    tsplit_all<<<(1280 * H + H * NE + 1280 + 255) / 256, 256>>>(Wq, Wk, Wv, bq, bk, bv);
    u_kernel<<<49, 256>>>(Wa, Wattn, ba, battn);
    sgat_kernel<<<512 * (H / 4) / 256, 256>>>(xs);

    // qe slabs: split-K 6 x 128 over K=768  (grid 2x4x6 = 48 CTAs)
    bgemm<0, true><<<dim3(2, 4, 6), 256, BG_SMEM>>>(
        pah, pal, pwh, pwl, nullptr, pqeP, nullptr, nullptr, nullptr, nullptr,
        H, H, NE, 128, 1.f, 0, 0, (long long)512 * NE);
    qe_finish<<<128, 256>>>();

    // z slabs: split-K 2 x 128 over K=256 (grid 6x4x2 = 48 CTAs)
    bgemm<0, true><<<dim3(6, 4, 2), 256, BG_SMEM>>>(
        pqeh, pqel, pwknh, pwknl, nullptr, pzP, nullptr, nullptr, nullptr, nullptr,
        NE, NE, H, 128, 1.f, 0, 0, (long long)512 * H);
    z_finish<<<384, 256>>>();
    c_kernel<<<64, 256>>>();

    // neighbor attention via emb·z + messages (both branches)
    neigh_kernel<<<2 * Bn * NN, 256>>>(n1emb, n2emb);

    // gate attention + x pairs
    rscore_kernel<<<2 * Bn * 33, 128>>>(xs, pm1, pm2);
    rsoftmax_kernel<<<2 * Bn, 32>>>(dist1, dist2, wb, bb);
    build_x_kernel<<<(Bn * S * H / 4) / 256, 256>>>(xs);

    // fused q/k/v projections: M = Bn*S = 16384 -> 128 M-tiles, N = 1280 -> 10 N-tiles
    bgemm<3, false><<<dim3(10, 128, 1), 256, BG_SMEM>>>(
        pxh, pxl, pwh, pwl, pbias, nullptr, pqkh, pqkl, pvh, pvl,
        H, H, 512, H, 1.f, 0, 0, 0);

    // scores = SCALE * q @ k^T (batched, grid 4x4x32 = 512)
    bgemm<0, false><<<dim3(4, 4, 32), 256, BG_SMEM>>>(
        pqkh, pqkl, pqkh + 256, pqkl + 256, nullptr, pp,
        nullptr, nullptr, nullptr, nullptr,
        512, 512, S, NE, SCALE,
        (long long)S * 512, (long long)S * 512, (long long)S * S);

    softmax_rows_kernel<<<Bn * S / 8, 256>>>();

    // out = probs @ v (batched, grid 6x4x32 = 768)
    bgemm<0, false><<<dim3(6, 4, 32), 256, BG_SMEM>>>(
        pph, ppl, pvh, pvl, nullptr, out, nullptr, nullptr, nullptr, nullptr,
        512, 512, H, S, 1.f,
        (long long)S * S, (long long)H * S, (long long)S * H);
}

// round 10
// speedup vs baseline: 3.2292x; 1.0110x over previous
#include <cuda_runtime.h>
#include <cuda_bf16.h>
#include <cstdint>

// ---------------- problem constants ----------------
namespace {
constexpr int Bn = 32;
constexpr int S  = 512;
constexpr int H  = 768;
constexpr int NN = 32;
constexpr int T  = 32;
constexpr int NE = 256;
constexpr int AE = 128;
constexpr int RL = 8;
constexpr float SCALE = 0.0625f;
constexpr float NEG   = 0.01f;
}

// ---------------- scratch ----------------
__device__ float g_probs[Bn * S * S];
__device__ float g_msg1 [Bn * NN * RL * H];
__device__ float g_msg2 [Bn * NN * RL * H];
__device__ float g_qe   [2 * Bn * RL * NE];
__device__ float g_qeP  [6 * 512 * NE];         // split-K partial slabs
__device__ float g_z    [2 * Bn * RL * H];
__device__ float g_zP   [2 * 512 * H];
__device__ float g_c    [2 * Bn * RL];
__device__ float g_att1 [Bn * NN];
__device__ float g_att2 [Bn * NN];
__device__ float g_u    [2 * H + 1];
__device__ float g_md   [2 * Bn * NN];
__device__ float g_feas [2 * Bn];
__device__ float g_bias [1280];

__device__ __nv_bfloat16 g_Wh  [1280 * H], g_Wl  [1280 * H];  // stacked WqT|WkT|WvT
__device__ __nv_bfloat16 g_WkNh[H * NE],   g_WkNl[H * NE];    // Wk original layout
__device__ __nv_bfloat16 g_qeh [512 * NE], g_qel [512 * NE];
__device__ __nv_bfloat16 g_xh  [Bn * S * H], g_xl [Bn * S * H];
__device__ __nv_bfloat16 g_qkh [Bn * S * 512], g_qkl[Bn * S * 512];
__device__ __nv_bfloat16 g_vTh [Bn * H * S], g_vTl[Bn * H * S];
__device__ __nv_bfloat16 g_ph  [Bn * S * S], g_pl [Bn * S * S];
__device__ __nv_bfloat16 g_qAh [512 * H],   g_qAl [512 * H];

// ---------------- helpers ----------------
__device__ __forceinline__ uint32_t smem_u32(const void* p) {
    uint32_t a;
    asm("{ .reg .u64 t; cvta.to.shared.u64 t, %1; cvt.u32.u64 %0, t; }" : "=r"(a) : "l"(p));
    return a;
}
__device__ __forceinline__ uint32_t bpack(__nv_bfloat16 a, __nv_bfloat16 b) {
    __nv_bfloat162 t = __halves2bfloat162(a, b);
    return *reinterpret_cast<uint32_t*>(&t);
}
__device__ __forceinline__ uint32_t fpack(float a, float b) {
    __nv_bfloat162 t = __floats2bfloat162_rn(a, b);
    return *reinterpret_cast<uint32_t*>(&t);
}
__device__ __forceinline__ void split4(float4 v, uint2& hv, uint2& lv) {
    __nv_bfloat16 h0 = __float2bfloat16(v.x), h1 = __float2bfloat16(v.y);
    __nv_bfloat16 h2 = __float2bfloat16(v.z), h3 = __float2bfloat16(v.w);
    hv.x = bpack(h0, h1); hv.y = bpack(h2, h3);
    lv.x = fpack(v.x - __bfloat162float(h0), v.y - __bfloat162float(h1));
    lv.y = fpack(v.z - __bfloat162float(h2), v.w - __bfloat162float(h3));
}
__device__ __forceinline__ void ldsm4(uint32_t& r0, uint32_t& r1, uint32_t& r2,
                                      uint32_t& r3, uint32_t a) {
    asm volatile("ldmatrix.sync.aligned.m8n8.x4.shared.b16 {%0,%1,%2,%3}, [%4];"
                 : "=r"(r0), "=r"(r1), "=r"(r2), "=r"(r3) : "r"(a));
}
__device__ __forceinline__ void mma16816(float* d, const uint32_t* a, const uint32_t* b) {
    asm volatile(
        "mma.sync.aligned.m16n8k16.row.col.f32.bf16.bf16.f32 "
        "{%0,%1,%2,%3}, {%4,%5,%6,%7}, {%8,%9}, {%0,%1,%2,%3};"
        : "+f"(d[0]), "+f"(d[1]), "+f"(d[2]), "+f"(d[3])
        : "r"(a[0]), "r"(a[1]), "r"(a[2]), "r"(a[3]), "r"(b[0]), "r"(b[1]));
}

// ================= all-bf16 cp.async bf16x3 GEMM, CTA 128x128 =================
// 8 warps (2x4), warp tile 64x32, BK=32, 4-stage pipeline.
// EPI 0: fp32 out (alpha*acc + bias?).  EPI 3: qkv routing (pairs / transposed pairs).
// SK: blockIdx.z = K-slice (length K); output slab at Cf + bz*sC.
constexpr int ROWB  = 80;
constexpr int MTILE = 128 * ROWB;     // 10240
constexpr int STG   = 4 * MTILE;      // 40960
constexpr int BG_SMEM = 4 * STG;      // 163840

template<int EPI, bool SK>
__global__ __launch_bounds__(256, 1) void bgemm(
    const __nv_bfloat16* __restrict__ Ahp, const __nv_bfloat16* __restrict__ Alp,
    const __nv_bfloat16* __restrict__ Bhp, const __nv_bfloat16* __restrict__ Blp,
    const float* __restrict__ bias, float* __restrict__ Cf,
    __nv_bfloat16* __restrict__ Ch, __nv_bfloat16* __restrict__ Cl,
    __nv_bfloat16* __restrict__ Dh, __nv_bfloat16* __restrict__ Dl,
    int lda, int ldb, int ldc, int K, float alpha,
    long long sA, long long sB, long long sC)
{
    extern __shared__ char smem[];
    const uint32_t sb = smem_u32(smem);
    const int tid = threadIdx.x, w = tid >> 5, lane = tid & 31;
    const int m0 = blockIdx.y * 128, n0 = blockIdx.x * 128, bz = blockIdx.z;
    int koff = 0;
    if (SK) {
        koff = bz * K;
        Cf += bz * sC;
    } else {
        Ahp += bz * sA; Alp += bz * sA;
        Bhp += bz * sB; Blp += bz * sB;
        if (EPI == 0) Cf += bz * sC;
    }

    const int wm = (w >> 2) * 64, wn = (w & 3) * 32;
    float acc[4][4][4];
#pragma unroll
    for (int a = 0; a < 4; a++)
#pragma unroll
        for (int b = 0; b < 4; b++)
#pragma unroll
            for (int c = 0; c < 4; c++) acc[a][b][c] = 0.f;

    const int nch = K >> 5;

    auto issue = [&](int c) {
        if (c < nch) {
            const int k0 = (c << 5) + koff;
            const uint32_t dstb = sb + (c & 3) * STG;
#pragma unroll
            for (int mat = 0; mat < 4; mat++) {
                const __nv_bfloat16* g = (mat == 0) ? Ahp : (mat == 1) ? Alp
                                       : (mat == 2) ? Bhp : Blp;
                const int rb = (mat < 2) ? m0 : n0;
                const int ld = (mat < 2) ? lda : ldb;
#pragma unroll
                for (int it = 0; it < 2; it++) {
                    int i = (it << 8) + tid, row = i >> 2, c16 = i & 3;
                    const __nv_bfloat16* src = g + (long long)(rb + row) * ld + k0 + (c16 << 3);
                    asm volatile("cp.async.cg.shared.global [%0], [%1], 16;"
                                 :: "r"(dstb + mat * MTILE + row * ROWB + (c16 << 4)), "l"(src));
                }
            }
        }
        asm volatile("cp.async.commit_group;");
    };

    const int q = lane >> 3, r = lane & 7;
    const int aRow = ((q & 1) << 3) + r;
    const int aCol = (q >> 1) << 4;
    const int bRow = ((q >> 1) << 3) + r;
    const int bCol = (q & 1) << 4;

    auto compute = [&](int c) {
        const uint32_t Ah = sb + (c & 3) * STG;
        const uint32_t Al = Ah + MTILE, Bh = Ah + 2 * MTILE, Bl = Ah + 3 * MTILE;
#pragma unroll
        for (int s = 0; s < 2; s++) {
            const int kOff = s * 32;
            uint32_t ah[4][4], al[4][4];
#pragma unroll
            for (int mt = 0; mt < 4; mt++) {
                uint32_t off = (uint32_t)(wm + mt * 16 + aRow) * ROWB + kOff + aCol;
                ldsm4(ah[mt][0], ah[mt][1], ah[mt][2], ah[mt][3], Ah + off);
                ldsm4(al[mt][0], al[mt][1], al[mt][2], al[mt][3], Al + off);
            }
            uint32_t bh[4][2], bl[4][2];
#pragma unroll
            for (int np = 0; np < 2; np++) {
                uint32_t off = (uint32_t)(wn + np * 16 + bRow) * ROWB + kOff + bCol;
                ldsm4(bh[2 * np][0], bh[2 * np][1],
                      bh[2 * np + 1][0], bh[2 * np + 1][1], Bh + off);
                ldsm4(bl[2 * np][0], bl[2 * np][1],
                      bl[2 * np + 1][0], bl[2 * np + 1][1], Bl + off);
            }
#pragma unroll
            for (int mt = 0; mt < 4; mt++)
#pragma unroll
                for (int nt = 0; nt < 4; nt++) {
                    mma16816(acc[mt][nt], ah[mt], bh[nt]);
                    mma16816(acc[mt][nt], ah[mt], bl[nt]);
                    mma16816(acc[mt][nt], al[mt], bh[nt]);
                }
        }
    };

    issue(0); issue(1); issue(2);
    for (int c = 0; c < nch; c++) {
        asm volatile("cp.async.wait_group 2;");
        __syncthreads();
        issue(c + 3);
        compute(c);
        __syncthreads();
    }

    const int gid = lane >> 2, tig = lane & 3;
#pragma unroll
    for (int mt = 0; mt < 4; mt++)
#pragma unroll
        for (int half = 0; half < 2; half++) {
            const long long m = m0 + wm + mt * 16 + gid + half * 8;
#pragma unroll
            for (int nt = 0; nt < 4; nt++) {
                float v0 = acc[mt][nt][half * 2 + 0];
                float v1 = acc[mt][nt][half * 2 + 1];
                const int n = n0 + wn + nt * 8 + tig * 2;
                if (EPI == 0) {
                    v0 *= alpha; v1 *= alpha;
                    if (bias) { v0 += bias[n]; v1 += bias[n + 1]; }
                    *(float2*)&Cf[m * ldc + n] = make_float2(v0, v1);
                } else {  // EPI == 3
                    v0 += bias[n]; v1 += bias[n + 1];
                    if (n0 < 512) {
                        __nv_bfloat16 h0 = __float2bfloat16(v0), h1 = __float2bfloat16(v1);
                        *(uint32_t*)&Ch[m * 512 + n] = bpack(h0, h1);
                        *(uint32_t*)&Cl[m * 512 + n] =
                            fpack(v0 - __bfloat162float(h0), v1 - __bfloat162float(h1));
                    } else {
                        const int nv = n - 512;
                        const long long b = m >> 9, t = m & 511;
                        __nv_bfloat16 h0 = __float2bfloat16(v0), h1 = __float2bfloat16(v1);
                        Dh[(b * 768 + nv) * 512 + t] = h0;
                        Dl[(b * 768 + nv) * 512 + t] = __float2bfloat16(v0 - __bfloat162float(h0));
                        Dh[(b * 768 + nv + 1) * 512 + t] = h1;
                        Dl[(b * 768 + nv + 1) * 512 + t] = __float2bfloat16(v1 - __bfloat162float(h1));
                    }
                }
            }
        }
}

// ---------------- split-K finish: qe = sum(slabs) + bq; emit fp32 + pairs ----
__global__ void qe_finish()
{
    int idx = blockIdx.x * 256 + threadIdx.x;   // 32768 float4s
    int n4 = (idx % (NE / 4)) * 4;
    float4 s = ((const float4*)g_qeP)[idx];
#pragma unroll
    for (int k = 1; k < 6; k++) {
        float4 p = ((const float4*)g_qeP)[k * (512 * NE / 4) + idx];
        s.x += p.x; s.y += p.y; s.z += p.z; s.w += p.w;
    }
    s.x += g_bias[n4]; s.y += g_bias[n4 + 1];
    s.z += g_bias[n4 + 2]; s.w += g_bias[n4 + 3];
    ((float4*)g_qe)[idx] = s;
    uint2 hv, lv; split4(s, hv, lv);
    ((uint2*)g_qeh)[idx] = hv;
    ((uint2*)g_qel)[idx] = lv;
}

// ---------------- split-K finish: z = slab0 + slab1 --------------------------
__global__ void z_finish()
{
    int idx = blockIdx.x * 256 + threadIdx.x;   // 98304 float4s
    float4 a = ((const float4*)g_zP)[idx];
    float4 b = ((const float4*)g_zP)[512 * H / 4 + idx];
    a.x += b.x; a.y += b.y; a.z += b.z; a.w += b.w;
    ((float4*)g_z)[idx] = a;
}

// ---------------- weights: stacked WT pairs + WkN pairs + bias ---------------
__global__ void tsplit_all(const float* __restrict__ Wq, const float* __restrict__ Wk,
                           const float* __restrict__ Wv, const float* __restrict__ bq,
                           const float* __restrict__ bk, const float* __restrict__ bv)
{
    int idx = blockIdx.x * 256 + threadIdx.x;
    if (idx < 1280 * H) {
        int n = idx / H, k = idx - n * H;
        float x = (n < 256) ? Wq[(long long)k * NE + n]
                : (n < 512) ? Wk[(long long)k * NE + (n - 256)]
                            : Wv[(long long)k * H + (n - 512)];
        __nv_bfloat16 h = __float2bfloat16(x);
        g_Wh[idx] = h;
        g_Wl[idx] = __float2bfloat16(x - __bfloat162float(h));
    } else if (idx < 1280 * H + H * NE) {
        int local = idx - 1280 * H;
        float x = Wk[local];
        __nv_bfloat16 h = __float2bfloat16(x);
        g_WkNh[local] = h;
        g_WkNl[local] = __float2bfloat16(x - __bfloat162float(h));
    } else if (idx < 1280 * H + H * NE + 1280) {
        int j = idx - 1280 * H - H * NE;
        g_bias[j] = (j < 256) ? bq[j] : (j < 512) ? bk[j - 256] : bv[j - 512];
    }
}

// ---------------- gather + split region rows for qe GEMM ---------------------
__global__ void sgat_kernel(const float* __restrict__ xs)
{
    int idx = blockIdx.x * 256 + threadIdx.x;
    int m = idx / (H / 4), r4 = idx - m * (H / 4);
    int br = m >> 8, b = (m >> 3) & 31, l = m & 7;
    float4 v = ((const float4*)(xs + ((long long)b * S + (br ? 20 : 1) + l) * H))[r4];
    uint2 hv, lv; split4(v, hv, lv);
    ((uint2*)g_qAh)[idx] = hv;
    ((uint2*)g_qAl)[idx] = lv;
}

// ---------------- c[row] = qe[row]·bk ----------------------------------------
__global__ void c_kernel()
{
    int row = blockIdx.x * 8 + (threadIdx.x >> 5);
    int lane = threadIdx.x & 31;
    float p = 0.f;
#pragma unroll
    for (int i = 0; i < 8; i++) {
        int e = lane + i * 32;
        p += g_qe[row * NE + e] * g_bias[256 + e];
    }
#pragma unroll
    for (int o = 16; o > 0; o >>= 1) p += __shfl_xor_sync(0xffffffffu, p, o);
    if (lane == 0) g_c[row] = p;
}

// ---------------- u = Wa @ Wattn halves; cbase -------------------------------
__global__ void u_kernel(const float* __restrict__ Wa, const float* __restrict__ Wattn,
                         const float* __restrict__ ba, const float* __restrict__ battn)
{
    if (blockIdx.x < 48) {
        int gt = blockIdx.x * 256 + threadIdx.x;
        int g = gt >> 3, sub = gt & 7;
        int j = g / H, h = g - j * H;
        float acc = 0.f;
#pragma unroll 4
        for (int a = sub; a < AE; a += 8) acc += Wa[h * AE + a] * Wattn[j * AE + a];
        acc += __shfl_down_sync(0xffffffffu, acc, 4, 8);
        acc += __shfl_down_sync(0xffffffffu, acc, 2, 8);
        acc += __shfl_down_sync(0xffffffffu, acc, 1, 8);
        if (sub == 0) g_u[g] = acc;
    } else {
        __shared__ float red[256];
        int tid = threadIdx.x;
        float v = 0.f;
        if (tid < AE) v = ba[tid] * (Wattn[tid] + Wattn[AE + tid]);
        red[tid] = v; __syncthreads();
        for (int s2 = 128; s2 > 0; s2 >>= 1) {
            if (tid < s2) red[tid] += red[tid + s2];
            __syncthreads();
        }
        if (tid == 0) g_u[2 * H] = red[0] + battn[0];
    }
}

// ---------------- per-(br,b,n): scores from z -> softmax -> message ----------
// es rows stride 196 floats (16B-aligned, conflict-free LDS.128 across lanes)
__global__ __launch_bounds__(256) void neigh_kernel(
    const float* __restrict__ e1, const float* __restrict__ e2)
{
    __shared__ float zs[RL * H];        // 24 KB
    __shared__ float es[T * 196];       // 25 KB (chunk Hc=192, stride 196)
    __shared__ float aw[RL * T];
    __shared__ float cs[RL];
    int br = blockIdx.x >> 10;
    int b = (blockIdx.x >> 5) & 31, n = blockIdx.x & 31;
    int tid = threadIdx.x;
    const float* emb = (br ? e2 : e1) + (long long)(b * NN + n) * T * H;
    const float4* eb4 = (const float4*)emb;

    const float4* z4 = (const float4*)(g_z + (long long)(br * 256 + b * 8) * H);
#pragma unroll
    for (int it = 0; it < 6; it++) {
        int i = it * 256 + tid;
        *(float4*)&zs[i * 4] = z4[i];
    }
    if (tid < 8) cs[tid] = g_c[br * 256 + b * 8 + tid];
    __syncthreads();

    int l = tid >> 5, tt = tid & 31;
    float sacc = 0.f;
#pragma unroll
    for (int ch = 0; ch < 4; ch++) {
        // fill chunk: 32 rows x 48 float4, aligned vector stores
        for (int i = tid; i < T * 48; i += 256) {
            int t2 = i / 48, h4 = i - t2 * 48;
            *(float4*)&es[t2 * 196 + h4 * 4] = eb4[t2 * (H / 4) + ch * 48 + h4];
        }
        __syncthreads();
        const float4* er = (const float4*)&es[tt * 196];
        const float4* zr = (const float4*)&zs[l * H + ch * 192];
#pragma unroll 8
        for (int j = 0; j < 48; j++) {
            float4 e = er[j], zv = zr[j];
            sacc += e.x * zv.x + e.y * zv.y + e.z * zv.z + e.w * zv.w;
        }
        __syncthreads();
    }
    float s = (sacc + cs[l]) * SCALE;
    float m = s;
#pragma unroll
    for (int o = 16; o > 0; o >>= 1) m = fmaxf(m, __shfl_xor_sync(0xffffffffu, m, o));
    float ex = __expf(s - m), sum = ex;
#pragma unroll
    for (int o = 16; o > 0; o >>= 1) sum += __shfl_xor_sync(0xffffffffu, sum, o);
    aw[l * T + tt] = ex / sum;
    __syncthreads();

    float* msg = (br ? g_msg2 : g_msg1) + (long long)(b * NN + n) * RL * H;
    float4* mb4 = (float4*)msg;
#pragma unroll
    for (int it = 0; it < RL * H / 4 / 256; it++) {
        int idx = it * 256 + tid;
        int l2 = idx / (H / 4), h4 = idx - l2 * (H / 4);
        float4 acc = make_float4(0.f, 0.f, 0.f, 0.f);
        const float* awr = aw + l2 * T;
#pragma unroll 8
        for (int t2 = 0; t2 < T; t2++) {
            float wgt = awr[t2];
            float4 e = eb4[t2 * (H / 4) + h4];
            acc.x += wgt * e.x; acc.y += wgt * e.y;
            acc.z += wgt * e.z; acc.w += wgt * e.w;
        }
        mb4[idx] = acc;
    }
}

// ---------------- region gate dots -------------------------------------------
__global__ __launch_bounds__(128) void rscore_kernel(
    const float* __restrict__ xs, const float* __restrict__ msg1,
    const float* __restrict__ msg2)
{
    __shared__ float wred[4];
    int id = blockIdx.x;
    int br = id / (Bn * 33);
    int rem = id - br * (Bn * 33);
    int b = rem / 33, j = rem - b * 33;
    int tid = threadIdx.x;

    const float* src;
    const float* uvec;
    if (j < NN) {
        src = (br ? msg2 : msg1) + (long long)(b * NN + j) * RL * H;
        uvec = g_u + H;
    } else {
        src = xs + ((long long)b * S + (br ? 20 : 1)) * H;
        uvec = g_u;
    }
    const float4* s4 = (const float4*)src;
    float p = 0.f;
#pragma unroll
    for (int it = 0; it < RL * H / 4 / 128; it++) {
        int i = it * 128 + tid;
        float4 v = s4[i];
        const float* up = uvec + (i % (H / 4)) * 4;
        p += v.x * up[0] + v.y * up[1] + v.z * up[2] + v.w * up[3];
    }
#pragma unroll
    for (int o = 16; o > 0; o >>= 1) p += __shfl_xor_sync(0xffffffffu, p, o);
    if ((tid & 31) == 0) wred[tid >> 5] = p;
    __syncthreads();
    if (tid == 0) {
        float tot = (wred[0] + wred[1] + wred[2] + wred[3]) * (1.f / RL);
        if (j < NN) g_md[(br * Bn + b) * NN + j] = tot;
        else        g_feas[br * Bn + b] = tot;
    }
}

__global__ void rsoftmax_kernel(const float* __restrict__ dist1,
                                const float* __restrict__ dist2,
                                const float* __restrict__ wb,
                                const float* __restrict__ bb)
{
    int br = blockIdx.x >> 5, b = blockIdx.x & 31;
    int lane = threadIdx.x;
    float pre = g_feas[br * Bn + b] + g_md[(br * Bn + b) * NN + lane] + g_u[2 * H];
    float z = pre >= 0.f ? pre : NEG * pre;
    const float* dist = br ? dist2 : dist1;
    float v = z + dist[b * NN + lane] * wb[0] + bb[0];
    float m = v;
#pragma unroll
    for (int o = 16; o > 0; o >>= 1) m = fmaxf(m, __shfl_xor_sync(0xffffffffu, m, o));
    float e = __expf(v - m), s = e;
#pragma unroll
    for (int o = 16; o > 0; o >>= 1) s += __shfl_xor_sync(0xffffffffu, s, o);
    (br ? g_att2 : g_att1)[b * NN + lane] = e / s;
}

// ---------------- x = xs (+ gated messages) -> bf16 pairs --------------------
__global__ void build_x_kernel(const float* __restrict__ xs)
{
    int idx = blockIdx.x * 256 + threadIdx.x;
    float4 v = ((const float4*)xs)[idx];
    int h4 = idx % (H / 4);
    int s = (idx / (H / 4)) % S;
    int b = idx / (S * H / 4);
    if (s >= 1 && s < 9) {
        int l = s - 1;
        const float4* m4 = (const float4*)g_msg1;
#pragma unroll 4
        for (int n = 0; n < NN; n++) {
            float a = g_att1[b * NN + n];
            float4 m = m4[((b * NN + n) * RL + l) * (H / 4) + h4];
            v.x += a * m.x; v.y += a * m.y; v.z += a * m.z; v.w += a * m.w;
        }
    } else if (s >= 20 && s < 28) {
        int l = s - 20;
        const float4* m4 = (const float4*)g_msg2;
#pragma unroll 4
        for (int n = 0; n < NN; n++) {
            float a = g_att2[b * NN + n];
            float4 m = m4[((b * NN + n) * RL + l) * (H / 4) + h4];
            v.x += a * m.x; v.y += a * m.y; v.z += a * m.z; v.w += a * m.w;
        }
    }
    uint2 hv, lv; split4(v, hv, lv);
    ((uint2*)g_xh)[idx] = hv;
    ((uint2*)g_xl)[idx] = lv;
}

// ---------------- row softmax (warp/row) -> bf16 pairs -----------------------
__global__ __launch_bounds__(256) void softmax_rows_kernel()
{
    int warp = threadIdx.x >> 5, lane = threadIdx.x & 31;
    long long row = (long long)blockIdx.x * 8 + warp;
    const float4* r4 = (const float4*)(g_probs + row * S);
    float4 x[4];
    float m = -3.4e38f;
#pragma unroll
    for (int k = 0; k < 4; k++) {
        x[k] = r4[lane + 32 * k];
        m = fmaxf(m, fmaxf(fmaxf(x[k].x, x[k].y), fmaxf(x[k].z, x[k].w)));
    }
#pragma unroll
    for (int o = 16; o > 0; o >>= 1) m = fmaxf(m, __shfl_xor_sync(0xffffffffu, m, o));
    float s = 0.f;
#pragma unroll
    for (int k = 0; k < 4; k++) {
        x[k].x = __expf(x[k].x - m); x[k].y = __expf(x[k].y - m);
        x[k].z = __expf(x[k].z - m); x[k].w = __expf(x[k].w - m);
        s += x[k].x + x[k].y + x[k].z + x[k].w;
    }
#pragma unroll
    for (int o = 16; o > 0; o >>= 1) s += __shfl_xor_sync(0xffffffffu, s, o);
    float inv = 1.f / s;
    uint2* ph4 = (uint2*)(g_ph + row * S);
    uint2* pl4 = (uint2*)(g_pl + row * S);
#pragma unroll
    for (int k = 0; k < 4; k++) {
        x[k].x *= inv; x[k].y *= inv; x[k].z *= inv; x[k].w *= inv;
        uint2 hv, lv; split4(x[k], hv, lv);
        ph4[lane + 32 * k] = hv;
        pl4[lane + 32 * k] = lv;
    }
}

// ---------------- launch ----------------
extern "C" void kernel_launch(void* const* d_in, const int* in_sizes, int n_in,
                              void* d_out, int out_size)
{
    const float* xs    = (const float*)d_in[0];
    const float* n1emb = (const float*)d_in[1];
    const float* n2emb = (const float*)d_in[2];
    const float* dist1 = (const float*)d_in[3];
    const float* dist2 = (const float*)d_in[4];
    const float* Wq    = (const float*)d_in[5];
    const float* bq    = (const float*)d_in[6];
    const float* Wk    = (const float*)d_in[7];
    const float* bk    = (const float*)d_in[8];
    const float* Wv    = (const float*)d_in[9];
    const float* bv    = (const float*)d_in[10];
    const float* Wa    = (const float*)d_in[11];
    const float* ba    = (const float*)d_in[12];
    const float* Wattn = (const float*)d_in[13];
    const float* battn = (const float*)d_in[14];
    const float* wb    = (const float*)d_in[15];
    const float* bb    = (const float*)d_in[16];
    float* out = (float*)d_out;

    float *pp, *pm1, *pm2, *pqeP, *pzP, *pbias;
    __nv_bfloat16 *pwh, *pwl, *pwknh, *pwknl, *pqeh, *pqel, *pxh, *pxl,
                  *pqkh, *pqkl, *pvh, *pvl, *pph, *ppl, *pah, *pal;
    cudaGetSymbolAddress((void**)&pp,    g_probs);
    cudaGetSymbolAddress((void**)&pm1,   g_msg1);
    cudaGetSymbolAddress((void**)&pm2,   g_msg2);
    cudaGetSymbolAddress((void**)&pqeP,  g_qeP);
    cudaGetSymbolAddress((void**)&pzP,   g_zP);
    cudaGetSymbolAddress((void**)&pbias, g_bias);
    cudaGetSymbolAddress((void**)&pwh,   g_Wh);
    cudaGetSymbolAddress((void**)&pwl,   g_Wl);
    cudaGetSymbolAddress((void**)&pwknh, g_WkNh);
    cudaGetSymbolAddress((void**)&pwknl, g_WkNl);
    cudaGetSymbolAddress((void**)&pqeh,  g_qeh);
    cudaGetSymbolAddress((void**)&pqel,  g_qel);
    cudaGetSymbolAddress((void**)&pxh,   g_xh);
    cudaGetSymbolAddress((void**)&pxl,   g_xl);
    cudaGetSymbolAddress((void**)&pqkh,  g_qkh);
    cudaGetSymbolAddress((void**)&pqkl,  g_qkl);
    cudaGetSymbolAddress((void**)&pvh,   g_vTh);
    cudaGetSymbolAddress((void**)&pvl,   g_vTl);
    cudaGetSymbolAddress((void**)&pph,   g_ph);
    cudaGetSymbolAddress((void**)&ppl,   g_pl);
    cudaGetSymbolAddress((void**)&pah,   g_qAh);
    cudaGetSymbolAddress((void**)&pal,   g_qAl);

    cudaFuncSetAttribute(bgemm<0, false>, cudaFuncAttributeMaxDynamicSharedMemorySize, BG_SMEM);
    cudaFuncSetAttribute(bgemm<0, true>,  cudaFuncAttributeMaxDynamicSharedMemorySize, BG_SMEM);
    cudaFuncSetAttribute(bgemm<3, false>, cudaFuncAttributeMaxDynamicSharedMemorySize, BG_SMEM);

    // prep
    tsplit_all<<<(1280 * H + H * NE + 1280 + 255) / 256, 256>>>(Wq, Wk, Wv, bq, bk, bv);
    u_kernel<<<49, 256>>>(Wa, Wattn, ba, battn);
    sgat_kernel<<<512 * (H / 4) / 256, 256>>>(xs);

    // qe slabs: split-K 6 x 128 over K=768  (grid 2x4x6 = 48 CTAs)
    bgemm<0, true><<<dim3(2, 4, 6), 256, BG_SMEM>>>(
        pah, pal, pwh, pwl, nullptr, pqeP, nullptr, nullptr, nullptr, nullptr,
        H, H, NE, 128, 1.f, 0, 0, (long long)512 * NE);
    qe_finish<<<128, 256>>>();

    // z slabs: split-K 2 x 128 over K=256 (grid 6x4x2 = 48 CTAs)
    bgemm<0, true><<<dim3(6, 4, 2), 256, BG_SMEM>>>(
        pqeh, pqel, pwknh, pwknl, nullptr, pzP, nullptr, nullptr, nullptr, nullptr,
        NE, NE, H, 128, 1.f, 0, 0, (long long)512 * H);
    z_finish<<<384, 256>>>();
    c_kernel<<<64, 256>>>();

    // neighbor attention via emb·z + messages (both branches)
    neigh_kernel<<<2 * Bn * NN, 256>>>(n1emb, n2emb);

    // gate attention + x pairs
    rscore_kernel<<<2 * Bn * 33, 128>>>(xs, pm1, pm2);
    rsoftmax_kernel<<<2 * Bn, 32>>>(dist1, dist2, wb, bb);
    build_x_kernel<<<(Bn * S * H / 4) / 256, 256>>>(xs);

    // fused q/k/v projections: M = Bn*S = 16384 -> 128 M-tiles, N = 1280 -> 10 N-tiles
    bgemm<3, false><<<dim3(10, 128, 1), 256, BG_SMEM>>>(
        pxh, pxl, pwh, pwl, pbias, nullptr, pqkh, pqkl, pvh, pvl,
        H, H, 512, H, 1.f, 0, 0, 0);

    // scores = SCALE * q @ k^T (batched, grid 4x4x32 = 512)
    bgemm<0, false><<<dim3(4, 4, 32), 256, BG_SMEM>>>(
        pqkh, pqkl, pqkh + 256, pqkl + 256, nullptr, pp,
        nullptr, nullptr, nullptr, nullptr,
        512, 512, S, NE, SCALE,
        (long long)S * 512, (long long)S * 512, (long long)S * S);

    softmax_rows_kernel<<<Bn * S / 8, 256>>>();

    // out = probs @ v (batched, grid 6x4x32 = 768)
    bgemm<0, false><<<dim3(6, 4, 32), 256, BG_SMEM>>>(
        pph, ppl, pvh, pvl, nullptr, out, nullptr, nullptr, nullptr, nullptr,
        512, 512, H, S, 1.f,
        (long long)S * S, (long long)H * S, (long long)S * H);
}

// round 11
// speedup vs baseline: 3.2715x; 1.0131x over previous
#include <cuda_runtime.h>
#include <cuda_bf16.h>
#include <cstdint>

// ---------------- problem constants ----------------
namespace {
constexpr int Bn = 32;
constexpr int S  = 512;
constexpr int H  = 768;
constexpr int NN = 32;
constexpr int T  = 32;
constexpr int NE = 256;
constexpr int AE = 128;
constexpr int RL = 8;
constexpr float SCALE = 0.0625f;
constexpr float NEG   = 0.01f;
}

// ---------------- scratch ----------------
__device__ float g_probs[Bn * S * S];
__device__ float g_msg1 [Bn * NN * RL * H];
__device__ float g_msg2 [Bn * NN * RL * H];
__device__ float g_qe   [2 * Bn * RL * NE];
__device__ float g_qeP  [6 * 512 * NE];         // split-K partial slabs
__device__ float g_z    [2 * Bn * RL * H];
__device__ float g_zP   [2 * 512 * H];
__device__ float g_c    [2 * Bn * RL];
__device__ float g_att1 [Bn * NN];
__device__ float g_att2 [Bn * NN];
__device__ float g_u    [2 * H + 1];
__device__ float g_md   [2 * Bn * NN];
__device__ float g_feas [2 * Bn];
__device__ float g_bias [1280];

__device__ __nv_bfloat16 g_Wh  [1280 * H], g_Wl  [1280 * H];  // stacked WqT|WkT|WvT
__device__ __nv_bfloat16 g_WkNh[H * NE],   g_WkNl[H * NE];    // Wk original layout
__device__ __nv_bfloat16 g_qeh [512 * NE], g_qel [512 * NE];
__device__ __nv_bfloat16 g_xh  [Bn * S * H], g_xl [Bn * S * H];
__device__ __nv_bfloat16 g_qkh [Bn * S * 512], g_qkl[Bn * S * 512];
__device__ __nv_bfloat16 g_vTh [Bn * H * S], g_vTl[Bn * H * S];
__device__ __nv_bfloat16 g_ph  [Bn * S * S], g_pl [Bn * S * S];
__device__ __nv_bfloat16 g_qAh [512 * H],   g_qAl [512 * H];

// ---------------- helpers ----------------
__device__ __forceinline__ uint32_t smem_u32(const void* p) {
    uint32_t a;
    asm("{ .reg .u64 t; cvta.to.shared.u64 t, %1; cvt.u32.u64 %0, t; }" : "=r"(a) : "l"(p));
    return a;
}
__device__ __forceinline__ uint32_t bpack(__nv_bfloat16 a, __nv_bfloat16 b) {
    __nv_bfloat162 t = __halves2bfloat162(a, b);
    return *reinterpret_cast<uint32_t*>(&t);
}
__device__ __forceinline__ uint32_t fpack(float a, float b) {
    __nv_bfloat162 t = __floats2bfloat162_rn(a, b);
    return *reinterpret_cast<uint32_t*>(&t);
}
__device__ __forceinline__ void split4(float4 v, uint2& hv, uint2& lv) {
    __nv_bfloat16 h0 = __float2bfloat16(v.x), h1 = __float2bfloat16(v.y);
    __nv_bfloat16 h2 = __float2bfloat16(v.z), h3 = __float2bfloat16(v.w);
    hv.x = bpack(h0, h1); hv.y = bpack(h2, h3);
    lv.x = fpack(v.x - __bfloat162float(h0), v.y - __bfloat162float(h1));
    lv.y = fpack(v.z - __bfloat162float(h2), v.w - __bfloat162float(h3));
}
__device__ __forceinline__ void ldsm4(uint32_t& r0, uint32_t& r1, uint32_t& r2,
                                      uint32_t& r3, uint32_t a) {
    asm volatile("ldmatrix.sync.aligned.m8n8.x4.shared.b16 {%0,%1,%2,%3}, [%4];"
                 : "=r"(r0), "=r"(r1), "=r"(r2), "=r"(r3) : "r"(a));
}
__device__ __forceinline__ void mma16816(float* d, const uint32_t* a, const uint32_t* b) {
    asm volatile(
        "mma.sync.aligned.m16n8k16.row.col.f32.bf16.bf16.f32 "
        "{%0,%1,%2,%3}, {%4,%5,%6,%7}, {%8,%9}, {%0,%1,%2,%3};"
        : "+f"(d[0]), "+f"(d[1]), "+f"(d[2]), "+f"(d[3])
        : "r"(a[0]), "r"(a[1]), "r"(a[2]), "r"(a[3]), "r"(b[0]), "r"(b[1]));
}

// ================= all-bf16 cp.async bf16x3 GEMM, CTA 128x128 =================
// 8 warps (2x4), warp tile 64x32, BK=32, 4-stage pipeline.
// EPI 0: fp32 out (alpha*acc + bias?).  EPI 3: qkv routing — qk tiles (n0<512)
// store bf16 pairs directly; v tiles (n0>=512) transpose via SMEM then store
// coalesced bf16 pairs.
// SK: blockIdx.z = K-slice (length K); output slab at Cf + bz*sC.
constexpr int ROWB  = 80;
constexpr int MTILE = 128 * ROWB;     // 10240
constexpr int STG   = 4 * MTILE;      // 40960
constexpr int BG_SMEM = 4 * STG;      // 163840

template<int EPI, bool SK>
__global__ __launch_bounds__(256, 1) void bgemm(
    const __nv_bfloat16* __restrict__ Ahp, const __nv_bfloat16* __restrict__ Alp,
    const __nv_bfloat16* __restrict__ Bhp, const __nv_bfloat16* __restrict__ Blp,
    const float* __restrict__ bias, float* __restrict__ Cf,
    __nv_bfloat16* __restrict__ Ch, __nv_bfloat16* __restrict__ Cl,
    __nv_bfloat16* __restrict__ Dh, __nv_bfloat16* __restrict__ Dl,
    int lda, int ldb, int ldc, int K, float alpha,
    long long sA, long long sB, long long sC)
{
    extern __shared__ char smem[];
    const uint32_t sb = smem_u32(smem);
    const int tid = threadIdx.x, w = tid >> 5, lane = tid & 31;
    const int m0 = blockIdx.y * 128, n0 = blockIdx.x * 128, bz = blockIdx.z;
    int koff = 0;
    if (SK) {
        koff = bz * K;
        Cf += bz * sC;
    } else {
        Ahp += bz * sA; Alp += bz * sA;
        Bhp += bz * sB; Blp += bz * sB;
        if (EPI == 0) Cf += bz * sC;
    }

    const int wm = (w >> 2) * 64, wn = (w & 3) * 32;
    float acc[4][4][4];
#pragma unroll
    for (int a = 0; a < 4; a++)
#pragma unroll
        for (int b = 0; b < 4; b++)
#pragma unroll
            for (int c = 0; c < 4; c++) acc[a][b][c] = 0.f;

    const int nch = K >> 5;

    auto issue = [&](int c) {
        if (c < nch) {
            const int k0 = (c << 5) + koff;
            const uint32_t dstb = sb + (c & 3) * STG;
#pragma unroll
            for (int mat = 0; mat < 4; mat++) {
                const __nv_bfloat16* g = (mat == 0) ? Ahp : (mat == 1) ? Alp
                                       : (mat == 2) ? Bhp : Blp;
                const int rb = (mat < 2) ? m0 : n0;
                const int ld = (mat < 2) ? lda : ldb;
#pragma unroll
                for (int it = 0; it < 2; it++) {
                    int i = (it << 8) + tid, row = i >> 2, c16 = i & 3;
                    const __nv_bfloat16* src = g + (long long)(rb + row) * ld + k0 + (c16 << 3);
                    asm volatile("cp.async.cg.shared.global [%0], [%1], 16;"
                                 :: "r"(dstb + mat * MTILE + row * ROWB + (c16 << 4)), "l"(src));
                }
            }
        }
        asm volatile("cp.async.commit_group;");
    };

    const int q = lane >> 3, r = lane & 7;
    const int aRow = ((q & 1) << 3) + r;
    const int aCol = (q >> 1) << 4;
    const int bRow = ((q >> 1) << 3) + r;
    const int bCol = (q & 1) << 4;

    auto compute = [&](int c) {
        const uint32_t Ah = sb + (c & 3) * STG;
        const uint32_t Al = Ah + MTILE, Bh = Ah + 2 * MTILE, Bl = Ah + 3 * MTILE;
#pragma unroll
        for (int s = 0; s < 2; s++) {
            const int kOff = s * 32;
            uint32_t ah[4][4], al[4][4];
#pragma unroll
            for (int mt = 0; mt < 4; mt++) {
                uint32_t off = (uint32_t)(wm + mt * 16 + aRow) * ROWB + kOff + aCol;
                ldsm4(ah[mt][0], ah[mt][1], ah[mt][2], ah[mt][3], Ah + off);
                ldsm4(al[mt][0], al[mt][1], al[mt][2], al[mt][3], Al + off);
            }
            uint32_t bh[4][2], bl[4][2];
#pragma unroll
            for (int np = 0; np < 2; np++) {
                uint32_t off = (uint32_t)(wn + np * 16 + bRow) * ROWB + kOff + bCol;
                ldsm4(bh[2 * np][0], bh[2 * np][1],
                      bh[2 * np + 1][0], bh[2 * np + 1][1], Bh + off);
                ldsm4(bl[2 * np][0], bl[2 * np][1],
                      bl[2 * np + 1][0], bl[2 * np + 1][1], Bl + off);
            }
#pragma unroll
            for (int mt = 0; mt < 4; mt++)
#pragma unroll
                for (int nt = 0; nt < 4; nt++) {
                    mma16816(acc[mt][nt], ah[mt], bh[nt]);
                    mma16816(acc[mt][nt], ah[mt], bl[nt]);
                    mma16816(acc[mt][nt], al[mt], bh[nt]);
                }
        }
    };

    issue(0); issue(1); issue(2);
    for (int c = 0; c < nch; c++) {
        asm volatile("cp.async.wait_group 2;");
        __syncthreads();
        issue(c + 3);
        compute(c);
        __syncthreads();
    }

    const int gid = lane >> 2, tig = lane & 3;

    if (EPI == 3 && n0 >= 512) {
        // v tile: transpose through SMEM (pipeline buffers are dead), then
        // write coalesced bf16 hi/lo pairs to the [b, nv, t] layout.
        float* st = (float*)smem;   // [n][m], stride 132 (conflict-free octets)
        __syncthreads();
#pragma unroll
        for (int mt = 0; mt < 4; mt++)
#pragma unroll
            for (int half = 0; half < 2; half++) {
                const int m = wm + mt * 16 + gid + half * 8;
#pragma unroll
                for (int nt = 0; nt < 4; nt++) {
                    const int n = wn + nt * 8 + tig * 2;
                    st[n * 132 + m]       = acc[mt][nt][half * 2 + 0] + bias[n0 + n];
                    st[(n + 1) * 132 + m] = acc[mt][nt][half * 2 + 1] + bias[n0 + n + 1];
                }
            }
        __syncthreads();
        const long long bb2 = m0 >> 9;
        const int t0 = m0 & 511, nvb = n0 - 512;
#pragma unroll
        for (int it = 0; it < 32; it++) {
            int i = it * 256 + tid;                 // 128 n-rows x 64 uint32
            int n = i >> 6, mc = (i & 63) << 1;
            float v0 = st[n * 132 + mc], v1 = st[n * 132 + mc + 1];
            __nv_bfloat16 h0 = __float2bfloat16(v0), h1 = __float2bfloat16(v1);
            long long gi = (bb2 * 768 + nvb + n) * 512 + t0 + mc;
            *(uint32_t*)&Dh[gi] = bpack(h0, h1);
            *(uint32_t*)&Dl[gi] =
                fpack(v0 - __bfloat162float(h0), v1 - __bfloat162float(h1));
        }
    } else {
#pragma unroll
        for (int mt = 0; mt < 4; mt++)
#pragma unroll
            for (int half = 0; half < 2; half++) {
                const long long m = m0 + wm + mt * 16 + gid + half * 8;
#pragma unroll
                for (int nt = 0; nt < 4; nt++) {
                    float v0 = acc[mt][nt][half * 2 + 0];
                    float v1 = acc[mt][nt][half * 2 + 1];
                    const int n = n0 + wn + nt * 8 + tig * 2;
                    if (EPI == 0) {
                        v0 *= alpha; v1 *= alpha;
                        if (bias) { v0 += bias[n]; v1 += bias[n + 1]; }
                        *(float2*)&Cf[m * ldc + n] = make_float2(v0, v1);
                    } else {  // EPI == 3, qk half
                        v0 += bias[n]; v1 += bias[n + 1];
                        __nv_bfloat16 h0 = __float2bfloat16(v0), h1 = __float2bfloat16(v1);
                        *(uint32_t*)&Ch[m * 512 + n] = bpack(h0, h1);
                        *(uint32_t*)&Cl[m * 512 + n] =
                            fpack(v0 - __bfloat162float(h0), v1 - __bfloat162float(h1));
                    }
                }
            }
    }
}

// ---------------- split-K finish: qe = sum(slabs) + bq; emit fp32 + pairs ----
__global__ void qe_finish()
{
    int idx = blockIdx.x * 256 + threadIdx.x;   // 32768 float4s
    int n4 = (idx % (NE / 4)) * 4;
    float4 s = ((const float4*)g_qeP)[idx];
#pragma unroll
    for (int k = 1; k < 6; k++) {
        float4 p = ((const float4*)g_qeP)[k * (512 * NE / 4) + idx];
        s.x += p.x; s.y += p.y; s.z += p.z; s.w += p.w;
    }
    s.x += g_bias[n4]; s.y += g_bias[n4 + 1];
    s.z += g_bias[n4 + 2]; s.w += g_bias[n4 + 3];
    ((float4*)g_qe)[idx] = s;
    uint2 hv, lv; split4(s, hv, lv);
    ((uint2*)g_qeh)[idx] = hv;
    ((uint2*)g_qel)[idx] = lv;
}

// ---------------- split-K finish: z = slab0 + slab1 --------------------------
__global__ void z_finish()
{
    int idx = blockIdx.x * 256 + threadIdx.x;   // 98304 float4s
    float4 a = ((const float4*)g_zP)[idx];
    float4 b = ((const float4*)g_zP)[512 * H / 4 + idx];
    a.x += b.x; a.y += b.y; a.z += b.z; a.w += b.w;
    ((float4*)g_z)[idx] = a;
}

// ---------------- weights: stacked WT pairs + WkN pairs + bias ---------------
__global__ void tsplit_all(const float* __restrict__ Wq, const float* __restrict__ Wk,
                           const float* __restrict__ Wv, const float* __restrict__ bq,
                           const float* __restrict__ bk, const float* __restrict__ bv)
{
    int idx = blockIdx.x * 256 + threadIdx.x;
    if (idx < 1280 * H) {
        int n = idx / H, k = idx - n * H;
        float x = (n < 256) ? Wq[(long long)k * NE + n]
                : (n < 512) ? Wk[(long long)k * NE + (n - 256)]
                            : Wv[(long long)k * H + (n - 512)];
        __nv_bfloat16 h = __float2bfloat16(x);
        g_Wh[idx] = h;
        g_Wl[idx] = __float2bfloat16(x - __bfloat162float(h));
    } else if (idx < 1280 * H + H * NE) {
        int local = idx - 1280 * H;
        float x = Wk[local];
        __nv_bfloat16 h = __float2bfloat16(x);
        g_WkNh[local] = h;
        g_WkNl[local] = __float2bfloat16(x - __bfloat162float(h));
    } else if (idx < 1280 * H + H * NE + 1280) {
        int j = idx - 1280 * H - H * NE;
        g_bias[j] = (j < 256) ? bq[j] : (j < 512) ? bk[j - 256] : bv[j - 512];
    }
}

// ---------------- gather + split region rows for qe GEMM ---------------------
__global__ void sgat_kernel(const float* __restrict__ xs)
{
    int idx = blockIdx.x * 256 + threadIdx.x;
    int m = idx / (H / 4), r4 = idx - m * (H / 4);
    int br = m >> 8, b = (m >> 3) & 31, l = m & 7;
    float4 v = ((const float4*)(xs + ((long long)b * S + (br ? 20 : 1) + l) * H))[r4];
    uint2 hv, lv; split4(v, hv, lv);
    ((uint2*)g_qAh)[idx] = hv;
    ((uint2*)g_qAl)[idx] = lv;
}

// ---------------- c[row] = qe[row]·bk ----------------------------------------
__global__ void c_kernel()
{
    int row = blockIdx.x * 8 + (threadIdx.x >> 5);
    int lane = threadIdx.x & 31;
    float p = 0.f;
#pragma unroll
    for (int i = 0; i < 8; i++) {
        int e = lane + i * 32;
        p += g_qe[row * NE + e] * g_bias[256 + e];
    }
#pragma unroll
    for (int o = 16; o > 0; o >>= 1) p += __shfl_xor_sync(0xffffffffu, p, o);
    if (lane == 0) g_c[row] = p;
}

// ---------------- u = Wa @ Wattn halves; cbase -------------------------------
__global__ void u_kernel(const float* __restrict__ Wa, const float* __restrict__ Wattn,
                         const float* __restrict__ ba, const float* __restrict__ battn)
{
    if (blockIdx.x < 48) {
        int gt = blockIdx.x * 256 + threadIdx.x;
        int g = gt >> 3, sub = gt & 7;
        int j = g / H, h = g - j * H;
        float acc = 0.f;
#pragma unroll 4
        for (int a = sub; a < AE; a += 8) acc += Wa[h * AE + a] * Wattn[j * AE + a];
        acc += __shfl_down_sync(0xffffffffu, acc, 4, 8);
        acc += __shfl_down_sync(0xffffffffu, acc, 2, 8);
        acc += __shfl_down_sync(0xffffffffu, acc, 1, 8);
        if (sub == 0) g_u[g] = acc;
    } else {
        __shared__ float red[256];
        int tid = threadIdx.x;
        float v = 0.f;
        if (tid < AE) v = ba[tid] * (Wattn[tid] + Wattn[AE + tid]);
        red[tid] = v; __syncthreads();
        for (int s2 = 128; s2 > 0; s2 >>= 1) {
            if (tid < s2) red[tid] += red[tid + s2];
            __syncthreads();
        }
        if (tid == 0) g_u[2 * H] = red[0] + battn[0];
    }
}

// ---------------- per-(br,b,n): scores from z -> softmax -> message ----------
// es rows stride 196 floats (16B-aligned, conflict-free LDS.128 across lanes)
__global__ __launch_bounds__(256) void neigh_kernel(
    const float* __restrict__ e1, const float* __restrict__ e2)
{
    __shared__ float zs[RL * H];        // 24 KB
    __shared__ float es[T * 196];       // 25 KB (chunk Hc=192, stride 196)
    __shared__ float aw[RL * T];
    __shared__ float cs[RL];
    int br = blockIdx.x >> 10;
    int b = (blockIdx.x >> 5) & 31, n = blockIdx.x & 31;
    int tid = threadIdx.x;
    const float* emb = (br ? e2 : e1) + (long long)(b * NN + n) * T * H;
    const float4* eb4 = (const float4*)emb;

    const float4* z4 = (const float4*)(g_z + (long long)(br * 256 + b * 8) * H);
#pragma unroll
    for (int it = 0; it < 6; it++) {
        int i = it * 256 + tid;
        *(float4*)&zs[i * 4] = z4[i];
    }
    if (tid < 8) cs[tid] = g_c[br * 256 + b * 8 + tid];
    __syncthreads();

    int l = tid >> 5, tt = tid & 31;
    float sacc = 0.f;
#pragma unroll
    for (int ch = 0; ch < 4; ch++) {
        for (int i = tid; i < T * 48; i += 256) {
            int t2 = i / 48, h4 = i - t2 * 48;
            *(float4*)&es[t2 * 196 + h4 * 4] = eb4[t2 * (H / 4) + ch * 48 + h4];
        }
        __syncthreads();
        const float4* er = (const float4*)&es[tt * 196];
        const float4* zr = (const float4*)&zs[l * H + ch * 192];
#pragma unroll 8
        for (int j = 0; j < 48; j++) {
            float4 e = er[j], zv = zr[j];
            sacc += e.x * zv.x + e.y * zv.y + e.z * zv.z + e.w * zv.w;
        }
        __syncthreads();
    }
    float s = (sacc + cs[l]) * SCALE;
    float m = s;
#pragma unroll
    for (int o = 16; o > 0; o >>= 1) m = fmaxf(m, __shfl_xor_sync(0xffffffffu, m, o));
    float ex = __expf(s - m), sum = ex;
#pragma unroll
    for (int o = 16; o > 0; o >>= 1) sum += __shfl_xor_sync(0xffffffffu, sum, o);
    aw[l * T + tt] = ex / sum;
    __syncthreads();

    float* msg = (br ? g_msg2 : g_msg1) + (long long)(b * NN + n) * RL * H;
    float4* mb4 = (float4*)msg;
#pragma unroll
    for (int it = 0; it < RL * H / 4 / 256; it++) {
        int idx = it * 256 + tid;
        int l2 = idx / (H / 4), h4 = idx - l2 * (H / 4);
        float4 acc = make_float4(0.f, 0.f, 0.f, 0.f);
        const float* awr = aw + l2 * T;
#pragma unroll 8
        for (int t2 = 0; t2 < T; t2++) {
            float wgt = awr[t2];
            float4 e = eb4[t2 * (H / 4) + h4];
            acc.x += wgt * e.x; acc.y += wgt * e.y;
            acc.z += wgt * e.z; acc.w += wgt * e.w;
        }
        mb4[idx] = acc;
    }
}

// ---------------- region gate dots -------------------------------------------
__global__ __launch_bounds__(128) void rscore_kernel(
    const float* __restrict__ xs, const float* __restrict__ msg1,
    const float* __restrict__ msg2)
{
    __shared__ float wred[4];
    int id = blockIdx.x;
    int br = id / (Bn * 33);
    int rem = id - br * (Bn * 33);
    int b = rem / 33, j = rem - b * 33;
    int tid = threadIdx.x;

    const float* src;
    const float* uvec;
    if (j < NN) {
        src = (br ? msg2 : msg1) + (long long)(b * NN + j) * RL * H;
        uvec = g_u + H;
    } else {
        src = xs + ((long long)b * S + (br ? 20 : 1)) * H;
        uvec = g_u;
    }
    const float4* s4 = (const float4*)src;
    float p = 0.f;
#pragma unroll
    for (int it = 0; it < RL * H / 4 / 128; it++) {
        int i = it * 128 + tid;
        float4 v = s4[i];
        const float* up = uvec + (i % (H / 4)) * 4;
        p += v.x * up[0] + v.y * up[1] + v.z * up[2] + v.w * up[3];
    }
#pragma unroll
    for (int o = 16; o > 0; o >>= 1) p += __shfl_xor_sync(0xffffffffu, p, o);
    if ((tid & 31) == 0) wred[tid >> 5] = p;
    __syncthreads();
    if (tid == 0) {
        float tot = (wred[0] + wred[1] + wred[2] + wred[3]) * (1.f / RL);
        if (j < NN) g_md[(br * Bn + b) * NN + j] = tot;
        else        g_feas[br * Bn + b] = tot;
    }
}

__global__ void rsoftmax_kernel(const float* __restrict__ dist1,
                                const float* __restrict__ dist2,
                                const float* __restrict__ wb,
                                const float* __restrict__ bb)
{
    int br = blockIdx.x >> 5, b = blockIdx.x & 31;
    int lane = threadIdx.x;
    float pre = g_feas[br * Bn + b] + g_md[(br * Bn + b) * NN + lane] + g_u[2 * H];
    float z = pre >= 0.f ? pre : NEG * pre;
    const float* dist = br ? dist2 : dist1;
    float v = z + dist[b * NN + lane] * wb[0] + bb[0];
    float m = v;
#pragma unroll
    for (int o = 16; o > 0; o >>= 1) m = fmaxf(m, __shfl_xor_sync(0xffffffffu, m, o));
    float e = __expf(v - m), s = e;
#pragma unroll
    for (int o = 16; o > 0; o >>= 1) s += __shfl_xor_sync(0xffffffffu, s, o);
    (br ? g_att2 : g_att1)[b * NN + lane] = e / s;
}

// ---------------- x = xs (+ gated messages) -> bf16 pairs --------------------
__global__ void build_x_kernel(const float* __restrict__ xs)
{
    int idx = blockIdx.x * 256 + threadIdx.x;
    float4 v = ((const float4*)xs)[idx];
    int h4 = idx % (H / 4);
    int s = (idx / (H / 4)) % S;
    int b = idx / (S * H / 4);
    if (s >= 1 && s < 9) {
        int l = s - 1;
        const float4* m4 = (const float4*)g_msg1;
#pragma unroll 4
        for (int n = 0; n < NN; n++) {
            float a = g_att1[b * NN + n];
            float4 m = m4[((b * NN + n) * RL + l) * (H / 4) + h4];
            v.x += a * m.x; v.y += a * m.y; v.z += a * m.z; v.w += a * m.w;
        }
    } else if (s >= 20 && s < 28) {
        int l = s - 20;
        const float4* m4 = (const float4*)g_msg2;
#pragma unroll 4
        for (int n = 0; n < NN; n++) {
            float a = g_att2[b * NN + n];
            float4 m = m4[((b * NN + n) * RL + l) * (H / 4) + h4];
            v.x += a * m.x; v.y += a * m.y; v.z += a * m.z; v.w += a * m.w;
        }
    }
    uint2 hv, lv; split4(v, hv, lv);
    ((uint2*)g_xh)[idx] = hv;
    ((uint2*)g_xl)[idx] = lv;
}

// ---------------- row softmax (warp/row) -> bf16 pairs -----------------------
__global__ __launch_bounds__(256) void softmax_rows_kernel()
{
    int warp = threadIdx.x >> 5, lane = threadIdx.x & 31;
    long long row = (long long)blockIdx.x * 8 + warp;
    const float4* r4 = (const float4*)(g_probs + row * S);
    float4 x[4];
    float m = -3.4e38f;
#pragma unroll
    for (int k = 0; k < 4; k++) {
        x[k] = r4[lane + 32 * k];
        m = fmaxf(m, fmaxf(fmaxf(x[k].x, x[k].y), fmaxf(x[k].z, x[k].w)));
    }
#pragma unroll
    for (int o = 16; o > 0; o >>= 1) m = fmaxf(m, __shfl_xor_sync(0xffffffffu, m, o));
    float s = 0.f;
#pragma unroll
    for (int k = 0; k < 4; k++) {
        x[k].x = __expf(x[k].x - m); x[k].y = __expf(x[k].y - m);
        x[k].z = __expf(x[k].z - m); x[k].w = __expf(x[k].w - m);
        s += x[k].x + x[k].y + x[k].z + x[k].w;
    }
#pragma unroll
    for (int o = 16; o > 0; o >>= 1) s += __shfl_xor_sync(0xffffffffu, s, o);
    float inv = 1.f / s;
    uint2* ph4 = (uint2*)(g_ph + row * S);
    uint2* pl4 = (uint2*)(g_pl + row * S);
#pragma unroll
    for (int k = 0; k < 4; k++) {
        x[k].x *= inv; x[k].y *= inv; x[k].z *= inv; x[k].w *= inv;
        uint2 hv, lv; split4(x[k], hv, lv);
        ph4[lane + 32 * k] = hv;
        pl4[lane + 32 * k] = lv;
    }
}

// ---------------- launch ----------------
extern "C" void kernel_launch(void* const* d_in, const int* in_sizes, int n_in,
                              void* d_out, int out_size)
{
    const float* xs    = (const float*)d_in[0];
    const float* n1emb = (const float*)d_in[1];
    const float* n2emb = (const float*)d_in[2];
    const float* dist1 = (const float*)d_in[3];
    const float* dist2 = (const float*)d_in[4];
    const float* Wq    = (const float*)d_in[5];
    const float* bq    = (const float*)d_in[6];
    const float* Wk    = (const float*)d_in[7];
    const float* bk    = (const float*)d_in[8];
    const float* Wv    = (const float*)d_in[9];
    const float* bv    = (const float*)d_in[10];
    const float* Wa    = (const float*)d_in[11];
    const float* ba    = (const float*)d_in[12];
    const float* Wattn = (const float*)d_in[13];
    const float* battn = (const float*)d_in[14];
    const float* wb    = (const float*)d_in[15];
    const float* bb    = (const float*)d_in[16];
    float* out = (float*)d_out;

    float *pp, *pm1, *pm2, *pqeP, *pzP, *pbias;
    __nv_bfloat16 *pwh, *pwl, *pwknh, *pwknl, *pqeh, *pqel, *pxh, *pxl,
                  *pqkh, *pqkl, *pvh, *pvl, *pph, *ppl, *pah, *pal;
    cudaGetSymbolAddress((void**)&pp,    g_probs);
    cudaGetSymbolAddress((void**)&pm1,   g_msg1);
    cudaGetSymbolAddress((void**)&pm2,   g_msg2);
    cudaGetSymbolAddress((void**)&pqeP,  g_qeP);
    cudaGetSymbolAddress((void**)&pzP,   g_zP);
    cudaGetSymbolAddress((void**)&pbias, g_bias);
    cudaGetSymbolAddress((void**)&pwh,   g_Wh);
    cudaGetSymbolAddress((void**)&pwl,   g_Wl);
    cudaGetSymbolAddress((void**)&pwknh, g_WkNh);
    cudaGetSymbolAddress((void**)&pwknl, g_WkNl);
    cudaGetSymbolAddress((void**)&pqeh,  g_qeh);
    cudaGetSymbolAddress((void**)&pqel,  g_qel);
    cudaGetSymbolAddress((void**)&pxh,   g_xh);
    cudaGetSymbolAddress((void**)&pxl,   g_xl);
    cudaGetSymbolAddress((void**)&pqkh,  g_qkh);
    cudaGetSymbolAddress((void**)&pqkl,  g_qkl);
    cudaGetSymbolAddress((void**)&pvh,   g_vTh);
    cudaGetSymbolAddress((void**)&pvl,   g_vTl);
    cudaGetSymbolAddress((void**)&pph,   g_ph);
    cudaGetSymbolAddress((void**)&ppl,   g_pl);
    cudaGetSymbolAddress((void**)&pah,   g_qAh);
    cudaGetSymbolAddress((void**)&pal,   g_qAl);

    cudaFuncSetAttribute(bgemm<0, false>, cudaFuncAttributeMaxDynamicSharedMemorySize, BG_SMEM);
    cudaFuncSetAttribute(bgemm<0, true>,  cudaFuncAttributeMaxDynamicSharedMemorySize, BG_SMEM);
    cudaFuncSetAttribute(bgemm<3, false>, cudaFuncAttributeMaxDynamicSharedMemorySize, BG_SMEM);

    // prep
    tsplit_all<<<(1280 * H + H * NE + 1280 + 255) / 256, 256>>>(Wq, Wk, Wv, bq, bk, bv);
    u_kernel<<<49, 256>>>(Wa, Wattn, ba, battn);
    sgat_kernel<<<512 * (H / 4) / 256, 256>>>(xs);

    // qe slabs: split-K 6 x 128 over K=768  (grid 2x4x6 = 48 CTAs)
    bgemm<0, true><<<dim3(2, 4, 6), 256, BG_SMEM>>>(
        pah, pal, pwh, pwl, nullptr, pqeP, nullptr, nullptr, nullptr, nullptr,
        H, H, NE, 128, 1.f, 0, 0, (long long)512 * NE);
    qe_finish<<<128, 256>>>();

    // z slabs: split-K 2 x 128 over K=256 (grid 6x4x2 = 48 CTAs)
    bgemm<0, true><<<dim3(6, 4, 2), 256, BG_SMEM>>>(
        pqeh, pqel, pwknh, pwknl, nullptr, pzP, nullptr, nullptr, nullptr, nullptr,
        NE, NE, H, 128, 1.f, 0, 0, (long long)512 * H);
    z_finish<<<384, 256>>>();
    c_kernel<<<64, 256>>>();

    // neighbor attention via emb·z + messages (both branches)
    neigh_kernel<<<2 * Bn * NN, 256>>>(n1emb, n2emb);

    // gate attention + x pairs
    rscore_kernel<<<2 * Bn * 33, 128>>>(xs, pm1, pm2);
    rsoftmax_kernel<<<2 * Bn, 32>>>(dist1, dist2, wb, bb);
    build_x_kernel<<<(Bn * S * H / 4) / 256, 256>>>(xs);

    // fused q/k/v projections: M = 16384 -> 128 M-tiles, N = 1280 -> 10 N-tiles
    bgemm<3, false><<<dim3(10, 128, 1), 256, BG_SMEM>>>(
        pxh, pxl, pwh, pwl, pbias, nullptr, pqkh, pqkl, pvh, pvl,
        H, H, 512, H, 1.f, 0, 0, 0);

    // scores = SCALE * q @ k^T (batched, grid 4x4x32 = 512)
    bgemm<0, false><<<dim3(4, 4, 32), 256, BG_SMEM>>>(
        pqkh, pqkl, pqkh + 256, pqkl + 256, nullptr, pp,
        nullptr, nullptr, nullptr, nullptr,
        512, 512, S, NE, SCALE,
        (long long)S * 512, (long long)S * 512, (long long)S * S);

    softmax_rows_kernel<<<Bn * S / 8, 256>>>();

    // out = probs @ v (batched, grid 6x4x32 = 768)
    bgemm<0, false><<<dim3(6, 4, 32), 256, BG_SMEM>>>(
        pph, ppl, pvh, pvl, nullptr, out, nullptr, nullptr, nullptr, nullptr,
        512, 512, H, S, 1.f,
        (long long)S * S, (long long)H * S, (long long)S * H);
}

// round 12
// speedup vs baseline: 3.5411x; 1.0824x over previous
#include <cuda_runtime.h>
#include <cuda_bf16.h>
#include <cstdint>

// ---------------- problem constants ----------------
namespace {
constexpr int Bn = 32;
constexpr int S  = 512;
constexpr int H  = 768;
constexpr int NN = 32;
constexpr int T  = 32;
constexpr int NE = 256;
constexpr int AE = 128;
constexpr int RL = 8;
constexpr float SCALE = 0.0625f;
constexpr float NEG   = 0.01f;
}

// ---------------- scratch ----------------
__device__ float g_probs[Bn * S * S];
__device__ float g_msg1 [Bn * NN * RL * H];
__device__ float g_msg2 [Bn * NN * RL * H];
__device__ float g_qe   [2 * Bn * RL * NE];
__device__ float g_qeP  [6 * 512 * NE];         // split-K partial slabs
__device__ float g_z    [2 * Bn * RL * H];
__device__ float g_zP   [2 * 512 * H];
__device__ float g_c    [2 * Bn * RL];
__device__ float g_att1 [Bn * NN];
__device__ float g_att2 [Bn * NN];
__device__ float g_u    [2 * H + 1];
__device__ float g_md   [2 * Bn * NN];
__device__ float g_feas [2 * Bn];
__device__ float g_bias [1280];

__device__ __nv_bfloat16 g_Wh  [1280 * H], g_Wl  [1280 * H];  // stacked WqT|WkT|WvT
__device__ __nv_bfloat16 g_WkNh[H * NE],   g_WkNl[H * NE];    // Wk original layout
__device__ __nv_bfloat16 g_qeh [512 * NE], g_qel [512 * NE];
__device__ __nv_bfloat16 g_xh  [Bn * S * H], g_xl [Bn * S * H];
__device__ __nv_bfloat16 g_qkh [Bn * S * 512], g_qkl[Bn * S * 512];
__device__ __nv_bfloat16 g_vTh [Bn * H * S], g_vTl[Bn * H * S];
__device__ __nv_bfloat16 g_ph  [Bn * S * S], g_pl [Bn * S * S];
__device__ __nv_bfloat16 g_qAh [512 * H],   g_qAl [512 * H];

// ---------------- helpers ----------------
__device__ __forceinline__ uint32_t smem_u32(const void* p) {
    uint32_t a;
    asm("{ .reg .u64 t; cvta.to.shared.u64 t, %1; cvt.u32.u64 %0, t; }" : "=r"(a) : "l"(p));
    return a;
}
__device__ __forceinline__ uint32_t bpack(__nv_bfloat16 a, __nv_bfloat16 b) {
    __nv_bfloat162 t = __halves2bfloat162(a, b);
    return *reinterpret_cast<uint32_t*>(&t);
}
__device__ __forceinline__ uint32_t fpack(float a, float b) {
    __nv_bfloat162 t = __floats2bfloat162_rn(a, b);
    return *reinterpret_cast<uint32_t*>(&t);
}
__device__ __forceinline__ void split4(float4 v, uint2& hv, uint2& lv) {
    __nv_bfloat16 h0 = __float2bfloat16(v.x), h1 = __float2bfloat16(v.y);
    __nv_bfloat16 h2 = __float2bfloat16(v.z), h3 = __float2bfloat16(v.w);
    hv.x = bpack(h0, h1); hv.y = bpack(h2, h3);
    lv.x = fpack(v.x - __bfloat162float(h0), v.y - __bfloat162float(h1));
    lv.y = fpack(v.z - __bfloat162float(h2), v.w - __bfloat162float(h3));
}
__device__ __forceinline__ void ldsm4(uint32_t& r0, uint32_t& r1, uint32_t& r2,
                                      uint32_t& r3, uint32_t a) {
    asm volatile("ldmatrix.sync.aligned.m8n8.x4.shared.b16 {%0,%1,%2,%3}, [%4];"
                 : "=r"(r0), "=r"(r1), "=r"(r2), "=r"(r3) : "r"(a));
}
__device__ __forceinline__ void mma16816(float* d, const uint32_t* a, const uint32_t* b) {
    asm volatile(
        "mma.sync.aligned.m16n8k16.row.col.f32.bf16.bf16.f32 "
        "{%0,%1,%2,%3}, {%4,%5,%6,%7}, {%8,%9}, {%0,%1,%2,%3};"
        : "+f"(d[0]), "+f"(d[1]), "+f"(d[2]), "+f"(d[3])
        : "r"(a[0]), "r"(a[1]), "r"(a[2]), "r"(a[3]), "r"(b[0]), "r"(b[1]));
}

// ================= all-bf16 cp.async bf16x3 GEMM, CTA 128x128 =================
// 8 warps (2x4), warp tile 64x32, BK=64, 2-stage pipeline (wait_group 1).
// ROWB=144: row stride 9 octets (odd) -> ldmatrix conflict-free.
// EPI 0: fp32 out (alpha*acc + bias?).  EPI 3: qkv routing — qk tiles (n0<512)
// store bf16 pairs directly; v tiles (n0>=512) transpose via SMEM then store
// coalesced bf16 pairs.
// SK: blockIdx.z = K-slice (length K); output slab at Cf + bz*sC.
constexpr int ROWB  = 144;
constexpr int MTILE = 128 * ROWB;     // 18432
constexpr int STG   = 4 * MTILE;      // 73728
constexpr int BG_SMEM = 2 * STG;      // 147456

template<int EPI, bool SK>
__global__ __launch_bounds__(256, 1) void bgemm(
    const __nv_bfloat16* __restrict__ Ahp, const __nv_bfloat16* __restrict__ Alp,
    const __nv_bfloat16* __restrict__ Bhp, const __nv_bfloat16* __restrict__ Blp,
    const float* __restrict__ bias, float* __restrict__ Cf,
    __nv_bfloat16* __restrict__ Ch, __nv_bfloat16* __restrict__ Cl,
    __nv_bfloat16* __restrict__ Dh, __nv_bfloat16* __restrict__ Dl,
    int lda, int ldb, int ldc, int K, float alpha,
    long long sA, long long sB, long long sC)
{
    extern __shared__ char smem[];
    const uint32_t sb = smem_u32(smem);
    const int tid = threadIdx.x, w = tid >> 5, lane = tid & 31;
    const int m0 = blockIdx.y * 128, n0 = blockIdx.x * 128, bz = blockIdx.z;
    int koff = 0;
    if (SK) {
        koff = bz * K;
        Cf += bz * sC;
    } else {
        Ahp += bz * sA; Alp += bz * sA;
        Bhp += bz * sB; Blp += bz * sB;
        if (EPI == 0) Cf += bz * sC;
    }

    const int wm = (w >> 2) * 64, wn = (w & 3) * 32;
    float acc[4][4][4];
#pragma unroll
    for (int a = 0; a < 4; a++)
#pragma unroll
        for (int b = 0; b < 4; b++)
#pragma unroll
            for (int c = 0; c < 4; c++) acc[a][b][c] = 0.f;

    const int nch = K >> 6;   // BK = 64

    auto issue = [&](int c) {
        if (c < nch) {
            const int k0 = (c << 6) + koff;
            const uint32_t dstb = sb + (c & 1) * STG;
#pragma unroll
            for (int mat = 0; mat < 4; mat++) {
                const __nv_bfloat16* g = (mat == 0) ? Ahp : (mat == 1) ? Alp
                                       : (mat == 2) ? Bhp : Blp;
                const int rb = (mat < 2) ? m0 : n0;
                const int ld = (mat < 2) ? lda : ldb;
#pragma unroll
                for (int it = 0; it < 4; ++it) {
                    int i = (it << 8) + tid, row = i >> 3, c8 = i & 7;
                    const __nv_bfloat16* src = g + (long long)(rb + row) * ld + k0 + (c8 << 3);
                    asm volatile("cp.async.cg.shared.global [%0], [%1], 16;"
                                 :: "r"(dstb + mat * MTILE + row * ROWB + (c8 << 4)), "l"(src));
                }
            }
        }
        asm volatile("cp.async.commit_group;");
    };

    const int q = lane >> 3, r = lane & 7;
    const int aRow = ((q & 1) << 3) + r;
    const int aCol = (q >> 1) << 4;
    const int bRow = ((q >> 1) << 3) + r;
    const int bCol = (q & 1) << 4;

    auto compute = [&](int c) {
        const uint32_t Ah = sb + (c & 1) * STG;
        const uint32_t Al = Ah + MTILE, Bh = Ah + 2 * MTILE, Bl = Ah + 3 * MTILE;
#pragma unroll
        for (int s = 0; s < 4; s++) {
            const int kOff = s * 32;
            uint32_t ah[4][4], al[4][4];
#pragma unroll
            for (int mt = 0; mt < 4; mt++) {
                uint32_t off = (uint32_t)(wm + mt * 16 + aRow) * ROWB + kOff + aCol;
                ldsm4(ah[mt][0], ah[mt][1], ah[mt][2], ah[mt][3], Ah + off);
                ldsm4(al[mt][0], al[mt][1], al[mt][2], al[mt][3], Al + off);
            }
            uint32_t bh[4][2], bl[4][2];
#pragma unroll
            for (int np = 0; np < 2; np++) {
                uint32_t off = (uint32_t)(wn + np * 16 + bRow) * ROWB + kOff + bCol;
                ldsm4(bh[2 * np][0], bh[2 * np][1],
                      bh[2 * np + 1][0], bh[2 * np + 1][1], Bh + off);
                ldsm4(bl[2 * np][0], bl[2 * np][1],
                      bl[2 * np + 1][0], bl[2 * np + 1][1], Bl + off);
            }
#pragma unroll
            for (int mt = 0; mt < 4; mt++)
#pragma unroll
                for (int nt = 0; nt < 4; nt++) {
                    mma16816(acc[mt][nt], ah[mt], bh[nt]);
                    mma16816(acc[mt][nt], ah[mt], bl[nt]);
                    mma16816(acc[mt][nt], al[mt], bh[nt]);
                }
        }
    };

    issue(0); issue(1);
    for (int c = 0; c < nch; c++) {
        asm volatile("cp.async.wait_group 1;");
        __syncthreads();
        compute(c);
        __syncthreads();
        issue(c + 2);
    }

    const int gid = lane >> 2, tig = lane & 3;

    if (EPI == 3 && n0 >= 512) {
        // v tile: transpose through SMEM (pipeline buffers are dead), then
        // write coalesced bf16 hi/lo pairs to the [b, nv, t] layout.
        float* st = (float*)smem;   // [n][m], stride 132 (conflict-free octets)
        __syncthreads();
#pragma unroll
        for (int mt = 0; mt < 4; mt++)
#pragma unroll
            for (int half = 0; half < 2; half++) {
                const int m = wm + mt * 16 + gid + half * 8;
#pragma unroll
                for (int nt = 0; nt < 4; nt++) {
                    const int n = wn + nt * 8 + tig * 2;
                    st[n * 132 + m]       = acc[mt][nt][half * 2 + 0] + bias[n0 + n];
                    st[(n + 1) * 132 + m] = acc[mt][nt][half * 2 + 1] + bias[n0 + n + 1];
                }
            }
        __syncthreads();
        const long long bb2 = m0 >> 9;
        const int t0 = m0 & 511, nvb = n0 - 512;
#pragma unroll
        for (int it = 0; it < 32; it++) {
            int i = it * 256 + tid;                 // 128 n-rows x 64 uint32
            int n = i >> 6, mc = (i & 63) << 1;
            float v0 = st[n * 132 + mc], v1 = st[n * 132 + mc + 1];
            __nv_bfloat16 h0 = __float2bfloat16(v0), h1 = __float2bfloat16(v1);
            long long gi = (bb2 * 768 + nvb + n) * 512 + t0 + mc;
            *(uint32_t*)&Dh[gi] = bpack(h0, h1);
            *(uint32_t*)&Dl[gi] =
                fpack(v0 - __bfloat162float(h0), v1 - __bfloat162float(h1));
        }
    } else {
#pragma unroll
        for (int mt = 0; mt < 4; mt++)
#pragma unroll
            for (int half = 0; half < 2; half++) {
                const long long m = m0 + wm + mt * 16 + gid + half * 8;
#pragma unroll
                for (int nt = 0; nt < 4; nt++) {
                    float v0 = acc[mt][nt][half * 2 + 0];
                    float v1 = acc[mt][nt][half * 2 + 1];
                    const int n = n0 + wn + nt * 8 + tig * 2;
                    if (EPI == 0) {
                        v0 *= alpha; v1 *= alpha;
                        if (bias) { v0 += bias[n]; v1 += bias[n + 1]; }
                        *(float2*)&Cf[m * ldc + n] = make_float2(v0, v1);
                    } else {  // EPI == 3, qk half
                        v0 += bias[n]; v1 += bias[n + 1];
                        __nv_bfloat16 h0 = __float2bfloat16(v0), h1 = __float2bfloat16(v1);
                        *(uint32_t*)&Ch[m * 512 + n] = bpack(h0, h1);
                        *(uint32_t*)&Cl[m * 512 + n] =
                            fpack(v0 - __bfloat162float(h0), v1 - __bfloat162float(h1));
                    }
                }
            }
    }
}

// ---------------- split-K finish: qe = sum(slabs) + bq; emit fp32 + pairs ----
__global__ void qe_finish()
{
    int idx = blockIdx.x * 256 + threadIdx.x;   // 32768 float4s
    int n4 = (idx % (NE / 4)) * 4;
    float4 s = ((const float4*)g_qeP)[idx];
#pragma unroll
    for (int k = 1; k < 6; k++) {
        float4 p = ((const float4*)g_qeP)[k * (512 * NE / 4) + idx];
        s.x += p.x; s.y += p.y; s.z += p.z; s.w += p.w;
    }
    s.x += g_bias[n4]; s.y += g_bias[n4 + 1];
    s.z += g_bias[n4 + 2]; s.w += g_bias[n4 + 3];
    ((float4*)g_qe)[idx] = s;
    uint2 hv, lv; split4(s, hv, lv);
    ((uint2*)g_qeh)[idx] = hv;
    ((uint2*)g_qel)[idx] = lv;
}

// ---------------- split-K finish: z = slab0 + slab1 --------------------------
__global__ void z_finish()
{
    int idx = blockIdx.x * 256 + threadIdx.x;   // 98304 float4s
    float4 a = ((const float4*)g_zP)[idx];
    float4 b = ((const float4*)g_zP)[512 * H / 4 + idx];
    a.x += b.x; a.y += b.y; a.z += b.z; a.w += b.w;
    ((float4*)g_z)[idx] = a;
}

// ---------------- weights: stacked WT pairs + WkN pairs + bias ---------------
__global__ void tsplit_all(const float* __restrict__ Wq, const float* __restrict__ Wk,
                           const float* __restrict__ Wv, const float* __restrict__ bq,
                           const float* __restrict__ bk, const float* __restrict__ bv)
{
    int idx = blockIdx.x * 256 + threadIdx.x;
    if (idx < 1280 * H) {
        int n = idx / H, k = idx - n * H;
        float x = (n < 256) ? Wq[(long long)k * NE + n]
                : (n < 512) ? Wk[(long long)k * NE + (n - 256)]
                            : Wv[(long long)k * H + (n - 512)];
        __nv_bfloat16 h = __float2bfloat16(x);
        g_Wh[idx] = h;
        g_Wl[idx] = __float2bfloat16(x - __bfloat162float(h));
    } else if (idx < 1280 * H + H * NE) {
        int local = idx - 1280 * H;
        float x = Wk[local];
        __nv_bfloat16 h = __float2bfloat16(x);
        g_WkNh[local] = h;
        g_WkNl[local] = __float2bfloat16(x - __bfloat162float(h));
    } else if (idx < 1280 * H + H * NE + 1280) {
        int j = idx - 1280 * H - H * NE;
        g_bias[j] = (j < 256) ? bq[j] : (j < 512) ? bk[j - 256] : bv[j - 512];
    }
}

// ---------------- gather + split region rows for qe GEMM ---------------------
__global__ void sgat_kernel(const float* __restrict__ xs)
{
    int idx = blockIdx.x * 256 + threadIdx.x;
    int m = idx / (H / 4), r4 = idx - m * (H / 4);
    int br = m >> 8, b = (m >> 3) & 31, l = m & 7;
    float4 v = ((const float4*)(xs + ((long long)b * S + (br ? 20 : 1) + l) * H))[r4];
    uint2 hv, lv; split4(v, hv, lv);
    ((uint2*)g_qAh)[idx] = hv;
    ((uint2*)g_qAl)[idx] = lv;
}

// ---------------- c[row] = qe[row]·bk ----------------------------------------
__global__ void c_kernel()
{
    int row = blockIdx.x * 8 + (threadIdx.x >> 5);
    int lane = threadIdx.x & 31;
    float p = 0.f;
#pragma unroll
    for (int i = 0; i < 8; i++) {
        int e = lane + i * 32;
        p += g_qe[row * NE + e] * g_bias[256 + e];
    }
#pragma unroll
    for (int o = 16; o > 0; o >>= 1) p += __shfl_xor_sync(0xffffffffu, p, o);
    if (lane == 0) g_c[row] = p;
}

// ---------------- u = Wa @ Wattn halves; cbase -------------------------------
__global__ void u_kernel(const float* __restrict__ Wa, const float* __restrict__ Wattn,
                         const float* __restrict__ ba, const float* __restrict__ battn)
{
    if (blockIdx.x < 48) {
        int gt = blockIdx.x * 256 + threadIdx.x;
        int g = gt >> 3, sub = gt & 7;
        int j = g / H, h = g - j * H;
        float acc = 0.f;
#pragma unroll 4
        for (int a = sub; a < AE; a += 8) acc += Wa[h * AE + a] * Wattn[j * AE + a];
        acc += __shfl_down_sync(0xffffffffu, acc, 4, 8);
        acc += __shfl_down_sync(0xffffffffu, acc, 2, 8);
        acc += __shfl_down_sync(0xffffffffu, acc, 1, 8);
        if (sub == 0) g_u[g] = acc;
    } else {
        __shared__ float red[256];
        int tid = threadIdx.x;
        float v = 0.f;
        if (tid < AE) v = ba[tid] * (Wattn[tid] + Wattn[AE + tid]);
        red[tid] = v; __syncthreads();
        for (int s2 = 128; s2 > 0; s2 >>= 1) {
            if (tid < s2) red[tid] += red[tid + s2];
            __syncthreads();
        }
        if (tid == 0) g_u[2 * H] = red[0] + battn[0];
    }
}

// ---------------- per-(br,b,n): scores from z -> softmax -> message ----------
// es rows stride 196 floats (16B-aligned, conflict-free LDS.128 across lanes)
__global__ __launch_bounds__(256) void neigh_kernel(
    const float* __restrict__ e1, const float* __restrict__ e2)
{
    __shared__ float zs[RL * H];        // 24 KB
    __shared__ float es[T * 196];       // 25 KB (chunk Hc=192, stride 196)
    __shared__ float aw[RL * T];
    __shared__ float cs[RL];
    int br = blockIdx.x >> 10;
    int b = (blockIdx.x >> 5) & 31, n = blockIdx.x & 31;
    int tid = threadIdx.x;
    const float* emb = (br ? e2 : e1) + (long long)(b * NN + n) * T * H;
    const float4* eb4 = (const float4*)emb;

    const float4* z4 = (const float4*)(g_z + (long long)(br * 256 + b * 8) * H);
#pragma unroll
    for (int it = 0; it < 6; it++) {
        int i = it * 256 + tid;
        *(float4*)&zs[i * 4] = z4[i];
    }
    if (tid < 8) cs[tid] = g_c[br * 256 + b * 8 + tid];
    __syncthreads();

    int l = tid >> 5, tt = tid & 31;
    float sacc = 0.f;
#pragma unroll
    for (int ch = 0; ch < 4; ch++) {
        for (int i = tid; i < T * 48; i += 256) {
            int t2 = i / 48, h4 = i - t2 * 48;
            *(float4*)&es[t2 * 196 + h4 * 4] = eb4[t2 * (H / 4) + ch * 48 + h4];
        }
        __syncthreads();
        const float4* er = (const float4*)&es[tt * 196];
        const float4* zr = (const float4*)&zs[l * H + ch * 192];
#pragma unroll 8
        for (int j = 0; j < 48; j++) {
            float4 e = er[j], zv = zr[j];
            sacc += e.x * zv.x + e.y * zv.y + e.z * zv.z + e.w * zv.w;
        }
        __syncthreads();
    }
    float s = (sacc + cs[l]) * SCALE;
    float m = s;
#pragma unroll
    for (int o = 16; o > 0; o >>= 1) m = fmaxf(m, __shfl_xor_sync(0xffffffffu, m, o));
    float ex = __expf(s - m), sum = ex;
#pragma unroll
    for (int o = 16; o > 0; o >>= 1) sum += __shfl_xor_sync(0xffffffffu, sum, o);
    aw[l * T + tt] = ex / sum;
    __syncthreads();

    float* msg = (br ? g_msg2 : g_msg1) + (long long)(b * NN + n) * RL * H;
    float4* mb4 = (float4*)msg;
#pragma unroll
    for (int it = 0; it < RL * H / 4 / 256; it++) {
        int idx = it * 256 + tid;
        int l2 = idx / (H / 4), h4 = idx - l2 * (H / 4);
        float4 acc = make_float4(0.f, 0.f, 0.f, 0.f);
        const float* awr = aw + l2 * T;
#pragma unroll 8
        for (int t2 = 0; t2 < T; t2++) {
            float wgt = awr[t2];
            float4 e = eb4[t2 * (H / 4) + h4];
            acc.x += wgt * e.x; acc.y += wgt * e.y;
            acc.z += wgt * e.z; acc.w += wgt * e.w;
        }
        mb4[idx] = acc;
    }
}

// ---------------- region gate dots -------------------------------------------
__global__ __launch_bounds__(128) void rscore_kernel(
    const float* __restrict__ xs, const float* __restrict__ msg1,
    const float* __restrict__ msg2)
{
    __shared__ float wred[4];
    int id = blockIdx.x;
    int br = id / (Bn * 33);
    int rem = id - br * (Bn * 33);
    int b = rem / 33, j = rem - b * 33;
    int tid = threadIdx.x;

    const float* src;
    const float* uvec;
    if (j < NN) {
        src = (br ? msg2 : msg1) + (long long)(b * NN + j) * RL * H;
        uvec = g_u + H;
    } else {
        src = xs + ((long long)b * S + (br ? 20 : 1)) * H;
        uvec = g_u;
    }
    const float4* s4 = (const float4*)src;
    float p = 0.f;
#pragma unroll
    for (int it = 0; it < RL * H / 4 / 128; it++) {
        int i = it * 128 + tid;
        float4 v = s4[i];
        const float* up = uvec + (i % (H / 4)) * 4;
        p += v.x * up[0] + v.y * up[1] + v.z * up[2] + v.w * up[3];
    }
#pragma unroll
    for (int o = 16; o > 0; o >>= 1) p += __shfl_xor_sync(0xffffffffu, p, o);
    if ((tid & 31) == 0) wred[tid >> 5] = p;
    __syncthreads();
    if (tid == 0) {
        float tot = (wred[0] + wred[1] + wred[2] + wred[3]) * (1.f / RL);
        if (j < NN) g_md[(br * Bn + b) * NN + j] = tot;
        else        g_feas[br * Bn + b] = tot;
    }
}

__global__ void rsoftmax_kernel(const float* __restrict__ dist1,
                                const float* __restrict__ dist2,
                                const float* __restrict__ wb,
                                const float* __restrict__ bb)
{
    int br = blockIdx.x >> 5, b = blockIdx.x & 31;
    int lane = threadIdx.x;
    float pre = g_feas[br * Bn + b] + g_md[(br * Bn + b) * NN + lane] + g_u[2 * H];
    float z = pre >= 0.f ? pre : NEG * pre;
    const float* dist = br ? dist2 : dist1;
    float v = z + dist[b * NN + lane] * wb[0] + bb[0];
    float m = v;
#pragma unroll
    for (int o = 16; o > 0; o >>= 1) m = fmaxf(m, __shfl_xor_sync(0xffffffffu, m, o));
    float e = __expf(v - m), s = e;
#pragma unroll
    for (int o = 16; o > 0; o >>= 1) s += __shfl_xor_sync(0xffffffffu, s, o);
    (br ? g_att2 : g_att1)[b * NN + lane] = e / s;
}

// ---------------- x = xs (+ gated messages) -> bf16 pairs --------------------
__global__ void build_x_kernel(const float* __restrict__ xs)
{
    int idx = blockIdx.x * 256 + threadIdx.x;
    float4 v = ((const float4*)xs)[idx];
    int h4 = idx % (H / 4);
    int s = (idx / (H / 4)) % S;
    int b = idx / (S * H / 4);
    if (s >= 1 && s < 9) {
        int l = s - 1;
        const float4* m4 = (const float4*)g_msg1;
#pragma unroll 4
        for (int n = 0; n < NN; n++) {
            float a = g_att1[b * NN + n];
            float4 m = m4[((b * NN + n) * RL + l) * (H / 4) + h4];
            v.x += a * m.x; v.y += a * m.y; v.z += a * m.z; v.w += a * m.w;
        }
    } else if (s >= 20 && s < 28) {
        int l = s - 20;
        const float4* m4 = (const float4*)g_msg2;
#pragma unroll 4
        for (int n = 0; n < NN; n++) {
            float a = g_att2[b * NN + n];
            float4 m = m4[((b * NN + n) * RL + l) * (H / 4) + h4];
            v.x += a * m.x; v.y += a * m.y; v.z += a * m.z; v.w += a * m.w;
        }
    }
    uint2 hv, lv; split4(v, hv, lv);
    ((uint2*)g_xh)[idx] = hv;
    ((uint2*)g_xl)[idx] = lv;
}

// ---------------- row softmax (warp/row) -> bf16 pairs -----------------------
__global__ __launch_bounds__(256) void softmax_rows_kernel()
{
    int warp = threadIdx.x >> 5, lane = threadIdx.x & 31;
    long long row = (long long)blockIdx.x * 8 + warp;
    const float4* r4 = (const float4*)(g_probs + row * S);
    float4 x[4];
    float m = -3.4e38f;
#pragma unroll
    for (int k = 0; k < 4; k++) {
        x[k] = r4[lane + 32 * k];
        m = fmaxf(m, fmaxf(fmaxf(x[k].x, x[k].y), fmaxf(x[k].z, x[k].w)));
    }
#pragma unroll
    for (int o = 16; o > 0; o >>= 1) m = fmaxf(m, __shfl_xor_sync(0xffffffffu, m, o));
    float s = 0.f;
#pragma unroll
    for (int k = 0; k < 4; k++) {
        x[k].x = __expf(x[k].x - m); x[k].y = __expf(x[k].y - m);
        x[k].z = __expf(x[k].z - m); x[k].w = __expf(x[k].w - m);
        s += x[k].x + x[k].y + x[k].z + x[k].w;
    }
#pragma unroll
    for (int o = 16; o > 0; o >>= 1) s += __shfl_xor_sync(0xffffffffu, s, o);
    float inv = 1.f / s;
    uint2* ph4 = (uint2*)(g_ph + row * S);
    uint2* pl4 = (uint2*)(g_pl + row * S);
#pragma unroll
    for (int k = 0; k < 4; k++) {
        x[k].x *= inv; x[k].y *= inv; x[k].z *= inv; x[k].w *= inv;
        uint2 hv, lv; split4(x[k], hv, lv);
        ph4[lane + 32 * k] = hv;
        pl4[lane + 32 * k] = lv;
    }
}

// ---------------- launch ----------------
extern "C" void kernel_launch(void* const* d_in, const int* in_sizes, int n_in,
                              void* d_out, int out_size)
{
    const float* xs    = (const float*)d_in[0];
    const float* n1emb = (const float*)d_in[1];
    const float* n2emb = (const float*)d_in[2];
    const float* dist1 = (const float*)d_in[3];
    const float* dist2 = (const float*)d_in[4];
    const float* Wq    = (const float*)d_in[5];
    const float* bq    = (const float*)d_in[6];
    const float* Wk    = (const float*)d_in[7];
    const float* bk    = (const float*)d_in[8];
    const float* Wv    = (const float*)d_in[9];
    const float* bv    = (const float*)d_in[10];
    const float* Wa    = (const float*)d_in[11];
    const float* ba    = (const float*)d_in[12];
    const float* Wattn = (const float*)d_in[13];
    const float* battn = (const float*)d_in[14];
    const float* wb    = (const float*)d_in[15];
    const float* bb    = (const float*)d_in[16];
    float* out = (float*)d_out;

    float *pp, *pm1, *pm2, *pqeP, *pzP, *pbias;
    __nv_bfloat16 *pwh, *pwl, *pwknh, *pwknl, *pqeh, *pqel, *pxh, *pxl,
                  *pqkh, *pqkl, *pvh, *pvl, *pph, *ppl, *pah, *pal;
    cudaGetSymbolAddress((void**)&pp,    g_probs);
    cudaGetSymbolAddress((void**)&pm1,   g_msg1);
    cudaGetSymbolAddress((void**)&pm2,   g_msg2);
    cudaGetSymbolAddress((void**)&pqeP,  g_qeP);
    cudaGetSymbolAddress((void**)&pzP,   g_zP);
    cudaGetSymbolAddress((void**)&pbias, g_bias);
    cudaGetSymbolAddress((void**)&pwh,   g_Wh);
    cudaGetSymbolAddress((void**)&pwl,   g_Wl);
    cudaGetSymbolAddress((void**)&pwknh, g_WkNh);
    cudaGetSymbolAddress((void**)&pwknl, g_WkNl);
    cudaGetSymbolAddress((void**)&pqeh,  g_qeh);
    cudaGetSymbolAddress((void**)&pqel,  g_qel);
    cudaGetSymbolAddress((void**)&pxh,   g_xh);
    cudaGetSymbolAddress((void**)&pxl,   g_xl);
    cudaGetSymbolAddress((void**)&pqkh,  g_qkh);
    cudaGetSymbolAddress((void**)&pqkl,  g_qkl);
    cudaGetSymbolAddress((void**)&pvh,   g_vTh);
    cudaGetSymbolAddress((void**)&pvl,   g_vTl);
    cudaGetSymbolAddress((void**)&pph,   g_ph);
    cudaGetSymbolAddress((void**)&ppl,   g_pl);
    cudaGetSymbolAddress((void**)&pah,   g_qAh);
    cudaGetSymbolAddress((void**)&pal,   g_qAl);

    cudaFuncSetAttribute(bgemm<0, false>, cudaFuncAttributeMaxDynamicSharedMemorySize, BG_SMEM);
    cudaFuncSetAttribute(bgemm<0, true>,  cudaFuncAttributeMaxDynamicSharedMemorySize, BG_SMEM);
    cudaFuncSetAttribute(bgemm<3, false>, cudaFuncAttributeMaxDynamicSharedMemorySize, BG_SMEM);

    // prep
    tsplit_all<<<(1280 * H + H * NE + 1280 + 255) / 256, 256>>>(Wq, Wk, Wv, bq, bk, bv);
    u_kernel<<<49, 256>>>(Wa, Wattn, ba, battn);
    sgat_kernel<<<512 * (H / 4) / 256, 256>>>(xs);

    // qe slabs: split-K 6 x 128 over K=768  (grid 2x4x6 = 48 CTAs)
    bgemm<0, true><<<dim3(2, 4, 6), 256, BG_SMEM>>>(
        pah, pal, pwh, pwl, nullptr, pqeP, nullptr, nullptr, nullptr, nullptr,
        H, H, NE, 128, 1.f, 0, 0, (long long)512 * NE);
    qe_finish<<<128, 256>>>();

    // z slabs: split-K 2 x 128 over K=256 (grid 6x4x2 = 48 CTAs)
    bgemm<0, true><<<dim3(6, 4, 2), 256, BG_SMEM>>>(
        pqeh, pqel, pwknh, pwknl, nullptr, pzP, nullptr, nullptr, nullptr, nullptr,
        NE, NE, H, 128, 1.f, 0, 0, (long long)512 * H);
    z_finish<<<384, 256>>>();
    c_kernel<<<64, 256>>>();

    // neighbor attention via emb·z + messages (both branches)
    neigh_kernel<<<2 * Bn * NN, 256>>>(n1emb, n2emb);

    // gate attention + x pairs
    rscore_kernel<<<2 * Bn * 33, 128>>>(xs, pm1, pm2);
    rsoftmax_kernel<<<2 * Bn, 32>>>(dist1, dist2, wb, bb);
    build_x_kernel<<<(Bn * S * H / 4) / 256, 256>>>(xs);

    // fused q/k/v projections: M = 16384 -> 128 M-tiles, N = 1280 -> 10 N-tiles
    bgemm<3, false><<<dim3(10, 128, 1), 256, BG_SMEM>>>(
        pxh, pxl, pwh, pwl, pbias, nullptr, pqkh, pqkl, pvh, pvl,
        H, H, 512, H, 1.f, 0, 0, 0);

    // scores = SCALE * q @ k^T (batched, grid 4x4x32 = 512)
    bgemm<0, false><<<dim3(4, 4, 32), 256, BG_SMEM>>>(
        pqkh, pqkl, pqkh + 256, pqkl + 256, nullptr, pp,
        nullptr, nullptr, nullptr, nullptr,
        512, 512, S, NE, SCALE,
        (long long)S * 512, (long long)S * 512, (long long)S * S);

    softmax_rows_kernel<<<Bn * S / 8, 256>>>();

    // out = probs @ v (batched, grid 6x4x32 = 768)
    bgemm<0, false><<<dim3(6, 4, 32), 256, BG_SMEM>>>(
        pph, ppl, pvh, pvl, nullptr, out, nullptr, nullptr, nullptr, nullptr,
        512, 512, H, S, 1.f,
        (long long)S * S, (long long)H * S, (long long)S * H);
}